// round 4
// baseline (speedup 1.0000x reference)
#include <cuda_runtime.h>
#include <cuda_fp16.h>
#include <cstdint>
#include <math.h>

// ---------------- problem constants ----------------
#define DHID   512
#define NHEAD  8
#define LAYERS 6
#define BB     16
#define TT     32
#define NTOK   64
#define KCONV  576
#define BT     512
#define MCONV  32768

// ---------------- device scratch ----------------
__device__ __half g_wT_h[KCONV * DHID];
__device__ __half g_patch_h[(size_t)MCONV * KCONV];
__device__ __half g_kqvw_h[LAYERS * DHID * 3 * DHID];
__device__ __half g_projw_h[LAYERS * DHID * DHID];
__device__ __half g_w1_h[LAYERS * DHID * 4 * DHID];
__device__ __half g_w2_h[LAYERS * 4 * DHID * DHID];
__device__ __half g_attn_h[BT * DHID];
__device__ __half g_mlp_h[BT * 4 * DHID];
__device__ float  g_tok[(size_t)MCONV * DHID];
__device__ float  g_film[BT * 2 * DHID];
__device__ float  g_h[BT * DHID];
__device__ float  g_kqv[BT * 3 * DHID];

// ---------------- helpers ----------------
__device__ __forceinline__ float warp_sum(float v) {
#pragma unroll
    for (int o = 16; o; o >>= 1) v += __shfl_xor_sync(0xffffffffu, v, o);
    return v;
}
__device__ __forceinline__ float warp_max(float v) {
#pragma unroll
    for (int o = 16; o; o >>= 1) v = fmaxf(v, __shfl_xor_sync(0xffffffffu, v, o));
    return v;
}
__device__ __forceinline__ float block_sum_256(float v, float* sbuf) {
    int lane = threadIdx.x & 31, wid = threadIdx.x >> 5;
    v = warp_sum(v);
    if (lane == 0) sbuf[wid] = v;
    __syncthreads();
    float r = sbuf[0];
#pragma unroll
    for (int w = 1; w < 8; w++) r += sbuf[w];
    __syncthreads();
    return r;
}
__device__ __forceinline__ unsigned smem_u32(const void* p) {
    return (unsigned)__cvta_generic_to_shared(p);
}

// ---------------- merged weight conversion (4 segments, 1 launch) ----------------
__global__ void f2h4_kernel(const float4* __restrict__ s0, const float4* __restrict__ s1,
                            const float4* __restrict__ s2, const float4* __restrict__ s3,
                            __half* __restrict__ d0, __half* __restrict__ d1,
                            __half* __restrict__ d2, __half* __restrict__ d3,
                            int n0, int n1, int n2, int n3) {
    int i = blockIdx.x * 256 + threadIdx.x;
    const float4* s; __half* d; int j = i;
    if (j < n0) { s = s0; d = d0; }
    else { j -= n0;
        if (j < n1) { s = s1; d = d1; }
        else { j -= n1;
            if (j < n2) { s = s2; d = d2; }
            else { j -= n2; if (j >= n3) return; s = s3; d = d3; }
        }
    }
    float4 v = s[j];
    __half2* o = (__half2*)(d + (size_t)j * 4);
    o[0] = __floats2half2_rn(v.x, v.y);
    o[1] = __floats2half2_rn(v.z, v.w);
}
__global__ void transpose_wh_kernel(const float* __restrict__ w, __half* __restrict__ wT) {
    int idx = blockIdx.x * 256 + threadIdx.x;
    if (idx >= DHID * KCONV) return;
    int d = idx / KCONV, k = idx % KCONV;
    wT[k * DHID + d] = __float2half_rn(w[idx]);
}

// ---------------- im2col (causal time pad 2) -> fp16 ----------------
__global__ void im2col_kernel(const float* __restrict__ x, __half* __restrict__ p) {
    long idx = (long)blockIdx.x * 256 + threadIdx.x;
    if (idx >= (long)MCONV * KCONV) return;
    int kcol = (int)(idx % KCONV);
    long row = idx / KCONV;
    int n  = (int)(row & 63);
    int bt = (int)(row >> 6);
    int t  = bt & 31;
    int b  = bt >> 5;
    int hn = n >> 3, wn = n & 7;
    int pw = kcol & 7;
    int ph = (kcol >> 3) & 7;
    int kt = (kcol >> 6) % 3;
    int c  = kcol / 192;
    int tt = t + kt - 2;
    float v = 0.f;
    if (tt >= 0)
        v = x[((((long)(b * 32 + tt) * 3 + c) * 64) + hn * 8 + ph) * 64 + wn * 8 + pw];
    p[idx] = __float2half_rn(v);
}

// ---------------- tensor-core GEMM (generic) ----------------
// epi 0: Cf = acc+bias   1: Ch = half(gelu)   2: Cf = res + scale[0]*(acc+bias)
#define APAD 8
#define BPAD 8

template<int BM, int BN, int WM, int WN>
__global__ void hgemm_kernel(const __half* __restrict__ A, const __half* __restrict__ B,
                             const float* __restrict__ bias,
                             float* __restrict__ Cf, __half* __restrict__ Ch,
                             int M, int N, int K, int epi,
                             const float* __restrict__ res, const float* __restrict__ scale) {
    constexpr int NT = WM * WN * 32;
    constexpr int A_IT = BM * 4 / NT;
    constexpr int B_IT = 4 * BN / NT;
    constexpr int WTN = BN / WN;      // cols per warp
    constexpr int NJ = WTN / 8;       // n8 tiles per warp
    constexpr int NJ2 = WTN / 16;     // ldmatrix.x4 groups
    __shared__ __half As[2][BM][32 + APAD];
    __shared__ __half Bs[2][32][BN + BPAD];

    int tid = threadIdx.x;
    int lane = tid & 31;
    int warp = tid >> 5;
    int wm = warp / WN, wn = warp % WN;
    int bm = blockIdx.y * BM, bn = blockIdx.x * BN;
    int KT = K >> 5;

    float c[2][NJ][4];
#pragma unroll
    for (int i = 0; i < 2; i++)
#pragma unroll
        for (int j = 0; j < NJ; j++)
#pragma unroll
            for (int e = 0; e < 4; e++) c[i][j][e] = 0.f;

#pragma unroll
    for (int i = 0; i < A_IT; i++) {
        int u = tid + i * NT; int r = u >> 2, q = u & 3;
        *(uint4*)&As[0][r][q * 8] = *(const uint4*)(A + (long)(bm + r) * K + q * 8);
    }
#pragma unroll
    for (int i = 0; i < B_IT; i++) {
        int v = tid + i * NT; int r = v / (BN / 8), q = v % (BN / 8);
        *(uint4*)&Bs[0][r][q * 8] = *(const uint4*)(B + (long)r * N + bn + q * 8);
    }
    __syncthreads();

    for (int kt = 0; kt < KT; kt++) {
        uint4 pa[A_IT]; uint4 pb[B_IT];
        bool more = (kt + 1 < KT);
        if (more) {
            int k0 = (kt + 1) * 32;
#pragma unroll
            for (int i = 0; i < A_IT; i++) {
                int u = tid + i * NT; int r = u >> 2, q = u & 3;
                pa[i] = *(const uint4*)(A + (long)(bm + r) * K + k0 + q * 8);
            }
#pragma unroll
            for (int i = 0; i < B_IT; i++) {
                int v = tid + i * NT; int r = v / (BN / 8), q = v % (BN / 8);
                pb[i] = *(const uint4*)(B + (long)(k0 + r) * N + bn + q * 8);
            }
        }
        int buf = kt & 1;
#pragma unroll
        for (int ks = 0; ks < 32; ks += 16) {
            unsigned a[2][4], bf[NJ2][4];
#pragma unroll
            for (int i = 0; i < 2; i++) {
                unsigned addr = smem_u32(&As[buf][wm * 32 + i * 16 + (lane & 15)][ks + (lane >> 4) * 8]);
                asm volatile("ldmatrix.sync.aligned.m8n8.x4.shared.b16 {%0,%1,%2,%3}, [%4];"
                             : "=r"(a[i][0]), "=r"(a[i][1]), "=r"(a[i][2]), "=r"(a[i][3]) : "r"(addr));
            }
#pragma unroll
            for (int j2 = 0; j2 < NJ2; j2++) {
                unsigned addr = smem_u32(&Bs[buf][ks + (lane & 7) + ((lane >> 3) & 1) * 8]
                                             [wn * WTN + j2 * 16 + (lane >> 4) * 8]);
                asm volatile("ldmatrix.sync.aligned.m8n8.x4.trans.shared.b16 {%0,%1,%2,%3}, [%4];"
                             : "=r"(bf[j2][0]), "=r"(bf[j2][1]), "=r"(bf[j2][2]), "=r"(bf[j2][3]) : "r"(addr));
            }
#pragma unroll
            for (int i = 0; i < 2; i++)
#pragma unroll
                for (int j = 0; j < NJ; j++) {
                    unsigned b0 = bf[j >> 1][(j & 1) * 2], b1 = bf[j >> 1][(j & 1) * 2 + 1];
                    asm volatile(
                        "mma.sync.aligned.m16n8k16.row.col.f32.f16.f16.f32 "
                        "{%0,%1,%2,%3}, {%4,%5,%6,%7}, {%8,%9}, {%0,%1,%2,%3};"
                        : "+f"(c[i][j][0]), "+f"(c[i][j][1]), "+f"(c[i][j][2]), "+f"(c[i][j][3])
                        : "r"(a[i][0]), "r"(a[i][1]), "r"(a[i][2]), "r"(a[i][3]), "r"(b0), "r"(b1));
                }
        }
        if (more) {
            int nb = buf ^ 1;
#pragma unroll
            for (int i = 0; i < A_IT; i++) {
                int u = tid + i * NT; int r = u >> 2, q = u & 3;
                *(uint4*)&As[nb][r][q * 8] = pa[i];
            }
#pragma unroll
            for (int i = 0; i < B_IT; i++) {
                int v = tid + i * NT; int r = v / (BN / 8), q = v % (BN / 8);
                *(uint4*)&Bs[nb][r][q * 8] = pb[i];
            }
        }
        __syncthreads();
    }

    float sc = (epi == 2) ? scale[0] : 0.f;
#pragma unroll
    for (int i = 0; i < 2; i++)
#pragma unroll
        for (int j = 0; j < NJ; j++) {
            int r0 = bm + wm * 32 + i * 16 + (lane >> 2);
            int c0 = bn + wn * WTN + j * 8 + (lane & 3) * 2;
#pragma unroll
            for (int half_ = 0; half_ < 2; half_++) {
                int rr = r0 + half_ * 8;
                float v0 = c[i][j][half_ * 2 + 0] + bias[c0];
                float v1 = c[i][j][half_ * 2 + 1] + bias[c0 + 1];
                long off = (long)rr * N + c0;
                if (epi == 0) {
                    *(float2*)&Cf[off] = make_float2(v0, v1);
                } else if (epi == 1) {
                    float g0 = 0.5f * v0 * (1.f + erff(v0 * 0.70710678118654752f));
                    float g1 = 0.5f * v1 * (1.f + erff(v1 * 0.70710678118654752f));
                    *(__half2*)&Ch[off] = __floats2half2_rn(g0, g1);
                } else {
                    float2 rv = *(const float2*)&res[off];
                    *(float2*)&Cf[off] = make_float2(rv.x + sc * v0, rv.y + sc * v1);
                }
            }
        }
}

// ---------------- fused LayerNorm + GEMM (K=512, BM=64, 128 threads) ----------------
// A = LN(h rows) computed in-block, resident full-K in smem. B fp16 [512,N].
// EPI 0: Cf = acc+bias   EPI 1: Ch = half(gelu(acc+bias))
#define ASTR 520   // 512 + 8 halfs
template<int BN, int EPI>
__global__ void gemm_ln_kernel(const float* __restrict__ H, const float* __restrict__ g,
                               const float* __restrict__ bvec, const __half* __restrict__ B,
                               const float* __restrict__ bias,
                               float* __restrict__ Cf, __half* __restrict__ Ch, int N) {
    extern __shared__ __half dsm[];
    __half* As = dsm;                          // [64][ASTR]
    __half* Bs = dsm + 64 * ASTR;              // [2][32][BN+8]
    constexpr int BSTR = BN + 8;
    constexpr int WTN = BN / 2;                // 2 warps in n
    constexpr int NJ = WTN / 8;
    constexpr int NJ2 = WTN / 16;
    int tid = threadIdx.x, lane = tid & 31, warp = tid >> 5;
    int wm = warp >> 1, wn = warp & 1;
    int bm = blockIdx.y * 64, bn = blockIdx.x * BN;

    // ---- LN phase: warp w handles rows [w*16, w*16+16) ----
    float gv[16], bv[16];
#pragma unroll
    for (int i = 0; i < 16; i++) { gv[i] = g[lane + 32 * i]; bv[i] = bvec[lane + 32 * i]; }
    for (int r = warp * 16; r < warp * 16 + 16; r++) {
        const float* row = H + (long)(bm + r) * 512;
        float v[16]; float s = 0.f;
#pragma unroll
        for (int i = 0; i < 16; i++) { v[i] = row[lane + 32 * i]; s += v[i]; }
        s = warp_sum(s);
        float mu = s * (1.f / 512.f);
        float vs = 0.f;
#pragma unroll
        for (int i = 0; i < 16; i++) { float d = v[i] - mu; vs += d * d; }
        vs = warp_sum(vs);
        float rstd = rsqrtf(vs * (1.f / 512.f) + 1e-5f);
#pragma unroll
        for (int i = 0; i < 16; i++)
            As[r * ASTR + lane + 32 * i] = __float2half_rn((v[i] - mu) * rstd * gv[i] + bv[i]);
    }
    // ---- B tile 0 ----
#pragma unroll
    for (int i = 0; i < 2; i++) {
        int v2 = tid + i * 128; int r = v2 / (BN / 8), q = v2 % (BN / 8);
        *(uint4*)&Bs[r * BSTR + q * 8] = *(const uint4*)(B + (long)r * N + bn + q * 8);
    }
    __syncthreads();

    float c[2][NJ][4];
#pragma unroll
    for (int i = 0; i < 2; i++)
#pragma unroll
        for (int j = 0; j < NJ; j++)
#pragma unroll
            for (int e = 0; e < 4; e++) c[i][j][e] = 0.f;

    for (int kt = 0; kt < 16; kt++) {
        uint4 pb[2];
        bool more = (kt + 1 < 16);
        if (more) {
            int k0 = (kt + 1) * 32;
#pragma unroll
            for (int i = 0; i < 2; i++) {
                int v2 = tid + i * 128; int r = v2 / (BN / 8), q = v2 % (BN / 8);
                pb[i] = *(const uint4*)(B + (long)(k0 + r) * N + bn + q * 8);
            }
        }
        int buf = kt & 1;
#pragma unroll
        for (int ks = 0; ks < 32; ks += 16) {
            unsigned a[2][4], bf[NJ2][4];
#pragma unroll
            for (int i = 0; i < 2; i++) {
                unsigned addr = smem_u32(&As[(wm * 32 + i * 16 + (lane & 15)) * ASTR
                                             + kt * 32 + ks + (lane >> 4) * 8]);
                asm volatile("ldmatrix.sync.aligned.m8n8.x4.shared.b16 {%0,%1,%2,%3}, [%4];"
                             : "=r"(a[i][0]), "=r"(a[i][1]), "=r"(a[i][2]), "=r"(a[i][3]) : "r"(addr));
            }
#pragma unroll
            for (int j2 = 0; j2 < NJ2; j2++) {
                unsigned addr = smem_u32(&Bs[(buf * 32 + ks + (lane & 7) + ((lane >> 3) & 1) * 8) * BSTR
                                             + wn * WTN + j2 * 16 + (lane >> 4) * 8]);
                asm volatile("ldmatrix.sync.aligned.m8n8.x4.trans.shared.b16 {%0,%1,%2,%3}, [%4];"
                             : "=r"(bf[j2][0]), "=r"(bf[j2][1]), "=r"(bf[j2][2]), "=r"(bf[j2][3]) : "r"(addr));
            }
#pragma unroll
            for (int i = 0; i < 2; i++)
#pragma unroll
                for (int j = 0; j < NJ; j++) {
                    unsigned b0 = bf[j >> 1][(j & 1) * 2], b1 = bf[j >> 1][(j & 1) * 2 + 1];
                    asm volatile(
                        "mma.sync.aligned.m16n8k16.row.col.f32.f16.f16.f32 "
                        "{%0,%1,%2,%3}, {%4,%5,%6,%7}, {%8,%9}, {%0,%1,%2,%3};"
                        : "+f"(c[i][j][0]), "+f"(c[i][j][1]), "+f"(c[i][j][2]), "+f"(c[i][j][3])
                        : "r"(a[i][0]), "r"(a[i][1]), "r"(a[i][2]), "r"(a[i][3]), "r"(b0), "r"(b1));
                }
        }
        if (more) {
            int nb = buf ^ 1;
#pragma unroll
            for (int i = 0; i < 2; i++) {
                int v2 = tid + i * 128; int r = v2 / (BN / 8), q = v2 % (BN / 8);
                *(uint4*)&Bs[(nb * 32 + r) * BSTR + q * 8] = pb[i];
            }
        }
        __syncthreads();
    }

#pragma unroll
    for (int i = 0; i < 2; i++)
#pragma unroll
        for (int j = 0; j < NJ; j++) {
            int r0 = bm + wm * 32 + i * 16 + (lane >> 2);
            int c0 = bn + wn * WTN + j * 8 + (lane & 3) * 2;
#pragma unroll
            for (int half_ = 0; half_ < 2; half_++) {
                int rr = r0 + half_ * 8;
                float v0 = c[i][j][half_ * 2 + 0] + bias[c0];
                float v1 = c[i][j][half_ * 2 + 1] + bias[c0 + 1];
                long off = (long)rr * N + c0;
                if (EPI == 0) {
                    *(float2*)&Cf[off] = make_float2(v0, v1);
                } else {
                    float g0 = 0.5f * v0 * (1.f + erff(v0 * 0.70710678118654752f));
                    float g1 = 0.5f * v1 * (1.f + erff(v1 * 0.70710678118654752f));
                    *(__half2*)&Ch[off] = __floats2half2_rn(g0, g1);
                }
            }
        }
}

// ---------------- small fp32 GEMM (film only) ----------------
__global__ void gemm_kernel(const float* __restrict__ A, const float* __restrict__ Bm,
                            const float* __restrict__ bias, float* C,
                            int M, int N, int K) {
    __shared__ float As[16][65];
    __shared__ float Bs[16][64];
    int bm = blockIdx.y * 64, bn = blockIdx.x * 64;
    int tid = threadIdx.x;
    int tx = tid & 15, ty = tid >> 4;
    float acc[4][4];
#pragma unroll
    for (int i = 0; i < 4; i++)
#pragma unroll
        for (int j = 0; j < 4; j++) acc[i][j] = 0.f;
    const float* Ab = A + (long)bm * K;
    for (int k0 = 0; k0 < K; k0 += 16) {
        {
            int col = tid & 15, row = tid >> 4;
#pragma unroll
            for (int r = 0; r < 4; r++)
                As[col][row + r * 16] = Ab[(long)(row + r * 16) * K + k0 + col];
        }
        {
            int col = tid & 63, row = tid >> 6;
#pragma unroll
            for (int r = 0; r < 4; r++)
                Bs[row + r * 4][col] = Bm[(long)(k0 + row + r * 4) * N + bn + col];
        }
        __syncthreads();
#pragma unroll
        for (int kk = 0; kk < 16; kk++) {
            float a0 = As[kk][ty * 4 + 0], a1 = As[kk][ty * 4 + 1];
            float a2 = As[kk][ty * 4 + 2], a3 = As[kk][ty * 4 + 3];
            float4 b4 = *(const float4*)&Bs[kk][tx * 4];
            acc[0][0] += a0 * b4.x; acc[0][1] += a0 * b4.y; acc[0][2] += a0 * b4.z; acc[0][3] += a0 * b4.w;
            acc[1][0] += a1 * b4.x; acc[1][1] += a1 * b4.y; acc[1][2] += a1 * b4.z; acc[1][3] += a1 * b4.w;
            acc[2][0] += a2 * b4.x; acc[2][1] += a2 * b4.y; acc[2][2] += a2 * b4.z; acc[2][3] += a2 * b4.w;
            acc[3][0] += a3 * b4.x; acc[3][1] += a3 * b4.y; acc[3][2] += a3 * b4.z; acc[3][3] += a3 * b4.w;
        }
        __syncthreads();
    }
#pragma unroll
    for (int i = 0; i < 4; i++) {
        int row = bm + ty * 4 + i;
#pragma unroll
        for (int j = 0; j < 4; j++) {
            int col = bn + tx * 4 + j;
            C[(long)row * N + col] = acc[i][j] + bias[col];
        }
    }
}

// ---------------- fused token LN + FiLM + spatial mean ----------------
__global__ void tok_reduce_kernel(const float* __restrict__ tok, const float* __restrict__ tg,
                                  const float* __restrict__ tb, const float* __restrict__ film,
                                  float* __restrict__ h) {
    __shared__ float accs[8][DHID];
    int bt = blockIdx.x;
    int wid = threadIdx.x >> 5, lane = threadIdx.x & 31;
    float acc[16];
#pragma unroll
    for (int i = 0; i < 16; i++) acc[i] = 0.f;
    const float* gb = film + bt * (2 * DHID);
    for (int n = wid; n < NTOK; n += 8) {
        const float* row = tok + (long)(bt * NTOK + n) * DHID;
        float v[16]; float s = 0.f;
#pragma unroll
        for (int i = 0; i < 16; i++) { v[i] = row[i * 32 + lane]; s += v[i]; }
        s = warp_sum(s);
        float mu = s * (1.f / 512.f);
        float vs = 0.f;
#pragma unroll
        for (int i = 0; i < 16; i++) { float d = v[i] - mu; vs += d * d; }
        vs = warp_sum(vs);
        float rstd = rsqrtf(vs * (1.f / 512.f) + 1e-5f);
#pragma unroll
        for (int i = 0; i < 16; i++) {
            int d = i * 32 + lane;
            float ln = (v[i] - mu) * rstd * tg[d] + tb[d];
            acc[i] += (1.f + 0.5f * gb[d]) * ln + 0.5f * gb[DHID + d];
        }
    }
#pragma unroll
    for (int i = 0; i < 16; i++) accs[wid][i * 32 + lane] = acc[i];
    __syncthreads();
    for (int d = threadIdx.x; d < DHID; d += 256) {
        float s = 0.f;
#pragma unroll
        for (int w = 0; w < 8; w++) s += accs[w][d];
        h[bt * DHID + d] = s * (1.f / 64.f);
    }
}

// ---------------- attention per (b, head) ----------------
__global__ void attn_kernel(const float* __restrict__ kqv, __half* __restrict__ out) {
    __shared__ float q[32][64];
    __shared__ float k[32][65];
    __shared__ float v[32][64];
    __shared__ float s[32][33];
    int bh = blockIdx.x;
    int b = bh >> 3, h = bh & 7;
    int tid = threadIdx.x;
#pragma unroll
    for (int i = 0; i < 8; i++) {
        int e = tid + i * 256;
        int t = e >> 6, d = e & 63;
        const float* base = kqv + (long)(b * 32 + t) * 1536 + h * 64;
        float kk = base[d];
        float qq = base[512 + d];
        v[t][d] = base[1024 + d];
        int j = d & 31;
        float ang = (float)t * powf(10000.f, -(float)j * (1.f / 32.f));
        float sn, cs;
        sincosf(ang, &sn, &cs);
        if (d < 32) {
            float kp = base[d + 32], qp = base[512 + d + 32];
            k[t][d] = kk * cs - kp * sn;
            q[t][d] = qq * cs - qp * sn;
        } else {
            float kp = base[d - 32], qp = base[512 + d - 32];
            k[t][d] = kk * cs + kp * sn;
            q[t][d] = qq * cs + qp * sn;
        }
    }
    __syncthreads();
#pragma unroll
    for (int i = 0; i < 4; i++) {
        int e = tid + i * 256;
        int tq = e >> 5, tk = e & 31;
        if (tk <= tq) {
            float acc = 0.f;
#pragma unroll
            for (int dd = 0; dd < 64; dd++) acc += q[tq][dd] * k[tk][dd];
            s[tq][tk] = acc * 0.125f;
        }
    }
    __syncthreads();
    int wid = tid >> 5, lane = tid & 31;
    for (int r = wid; r < 32; r += 8) {
        float val = (lane <= r) ? s[r][lane] : -3.4e38f;
        float m = warp_max(val);
        float e = (lane <= r) ? expf(val - m) : 0.f;
        float sum = warp_sum(e);
        s[r][lane] = e / sum;
    }
    __syncthreads();
#pragma unroll
    for (int i = 0; i < 8; i++) {
        int e = tid + i * 256;
        int t = e >> 6, d = e & 63;
        float acc = 0.f;
#pragma unroll
        for (int kk2 = 0; kk2 < 32; kk2++) acc += s[t][kk2] * v[kk2][d];
        out[(long)(b * 32 + t) * DHID + h * 64 + d] = __float2half_rn(acc);
    }
}

// ---------------- head ----------------
__global__ void head_kernel(const float* __restrict__ hin, const float* __restrict__ g,
                            const float* __restrict__ b, const float* __restrict__ w,
                            const float* __restrict__ bias0, float* __restrict__ out) {
    __shared__ float sbuf[8];
    int tok = blockIdx.x, tid = threadIdx.x;
    const float* row = hin + tok * DHID;
    float v0 = row[tid], v1 = row[tid + 256];
    float sum = block_sum_256(v0 + v1, sbuf);
    float mu = sum * (1.f / 512.f);
    float d0 = v0 - mu, d1 = v1 - mu;
    float vs = block_sum_256(d0 * d0 + d1 * d1, sbuf);
    float rstd = rsqrtf(vs * (1.f / 512.f) + 1e-5f);
    float c = (d0 * rstd * g[tid] + b[tid]) * w[tid] +
              (d1 * rstd * g[tid + 256] + b[tid + 256]) * w[tid + 256];
    float tot = block_sum_256(c, sbuf);
    if (tid == 0) out[tok] = tot + bias0[0];
}

// ---------------- launch ----------------
#define SMEM_GLN ((64 * ASTR + 2 * 32 * (64 + 8)) * 2)

extern "C" void kernel_launch(void* const* d_in, const int* in_sizes, int n_in,
                              void* d_out, int out_size) {
    const float* x       = (const float*)d_in[0];
    const float* z       = (const float*)d_in[1];
    const float* conv_w  = (const float*)d_in[2];
    const float* conv_b  = (const float*)d_in[3];
    const float* tok_g   = (const float*)d_in[4];
    const float* tok_b   = (const float*)d_in[5];
    const float* film_w  = (const float*)d_in[6];
    const float* film_b  = (const float*)d_in[7];
    const float* ln1_g   = (const float*)d_in[8];
    const float* ln1_b   = (const float*)d_in[9];
    const float* kqv_w   = (const float*)d_in[10];
    const float* kqv_b   = (const float*)d_in[11];
    const float* proj_w  = (const float*)d_in[12];
    const float* proj_b  = (const float*)d_in[13];
    const float* ln2_g   = (const float*)d_in[14];
    const float* ln2_b   = (const float*)d_in[15];
    const float* mlp_w1  = (const float*)d_in[16];
    const float* mlp_b1  = (const float*)d_in[17];
    const float* mlp_w2  = (const float*)d_in[18];
    const float* mlp_b2  = (const float*)d_in[19];
    const float* rs_attn = (const float*)d_in[20];
    const float* rs_mlp  = (const float*)d_in[21];
    const float* head_g  = (const float*)d_in[22];
    const float* head_b  = (const float*)d_in[23];
    const float* head_w  = (const float*)d_in[24];
    const float* head_bi = (const float*)d_in[25];
    float* out = (float*)d_out;

    __half *wT_h, *patch_h, *kqvw_h, *projw_h, *w1_h, *w2_h, *attn_h, *mlp_h;
    float *tok, *film, *h, *kqv;
    cudaGetSymbolAddress((void**)&wT_h, g_wT_h);
    cudaGetSymbolAddress((void**)&patch_h, g_patch_h);
    cudaGetSymbolAddress((void**)&kqvw_h, g_kqvw_h);
    cudaGetSymbolAddress((void**)&projw_h, g_projw_h);
    cudaGetSymbolAddress((void**)&w1_h, g_w1_h);
    cudaGetSymbolAddress((void**)&w2_h, g_w2_h);
    cudaGetSymbolAddress((void**)&attn_h, g_attn_h);
    cudaGetSymbolAddress((void**)&mlp_h, g_mlp_h);
    cudaGetSymbolAddress((void**)&tok, g_tok);
    cudaGetSymbolAddress((void**)&film, g_film);
    cudaGetSymbolAddress((void**)&h, g_h);
    cudaGetSymbolAddress((void**)&kqv, g_kqv);

    cudaFuncSetAttribute(gemm_ln_kernel<64, 0>, cudaFuncAttributeMaxDynamicSharedMemorySize, SMEM_GLN);
    cudaFuncSetAttribute(gemm_ln_kernel<64, 1>, cudaFuncAttributeMaxDynamicSharedMemorySize, SMEM_GLN);

    // weight conversions (merged)
    transpose_wh_kernel<<<(DHID * KCONV + 255) / 256, 256>>>(conv_w, wT_h);
    {
        int n0 = LAYERS * DHID * 3 * DHID / 4;
        int n1 = LAYERS * DHID * DHID / 4;
        int n2 = LAYERS * DHID * 4 * DHID / 4;
        int n3 = n2;
        int tot = n0 + n1 + n2 + n3;
        f2h4_kernel<<<(tot + 255) / 256, 256>>>(
            (const float4*)kqv_w, (const float4*)proj_w, (const float4*)mlp_w1, (const float4*)mlp_w2,
            kqvw_h, projw_h, w1_h, w2_h, n0, n1, n2, n3);
    }
    // tokenizer
    im2col_kernel<<<(int)(((long)MCONV * KCONV + 255) / 256), 256>>>(x, patch_h);
    hgemm_kernel<128, 128, 4, 2><<<dim3(DHID / 128, MCONV / 128), 256>>>(
        patch_h, wT_h, conv_b, tok, nullptr, MCONV, DHID, KCONV, 0, nullptr, nullptr);
    gemm_kernel<<<dim3(1024 / 64, BT / 64), 256>>>(z, film_w, film_b, film, BT, 1024, 32);
    tok_reduce_kernel<<<BT, 256>>>(tok, tok_g, tok_b, film, h);

    // transformer
    for (int i = 0; i < LAYERS; i++) {
        gemm_ln_kernel<64, 0><<<dim3(1536 / 64, BT / 64), 128, SMEM_GLN>>>(
            h, ln1_g + i * DHID, ln1_b + i * DHID, kqvw_h + (long)i * DHID * 1536,
            kqv_b + i * 1536, kqv, nullptr, 1536);
        attn_kernel<<<BB * NHEAD, 256>>>(kqv, attn_h);
        hgemm_kernel<64, 64, 2, 2><<<dim3(DHID / 64, BT / 64), 128>>>(
            attn_h, projw_h + (long)i * DHID * DHID, proj_b + i * DHID, h, nullptr,
            BT, DHID, DHID, 2, h, rs_attn + i);
        gemm_ln_kernel<64, 1><<<dim3(2048 / 64, BT / 64), 128, SMEM_GLN>>>(
            h, ln2_g + i * DHID, ln2_b + i * DHID, w1_h + (long)i * DHID * 2048,
            mlp_b1 + i * 2048, nullptr, mlp_h, 2048);
        hgemm_kernel<64, 64, 2, 2><<<dim3(DHID / 64, BT / 64), 128>>>(
            mlp_h, w2_h + (long)i * 2048 * DHID, mlp_b2 + i * DHID, h, nullptr,
            BT, DHID, 2048, 2, h, rs_mlp + i);
    }
    head_kernel<<<BT, 256>>>(h, head_g, head_b, head_w, head_bi, out);
}

// round 5
// speedup vs baseline: 1.1021x; 1.1021x over previous
#include <cuda_runtime.h>
#include <cuda_fp16.h>
#include <cstdint>
#include <math.h>

// ---------------- problem constants ----------------
#define DHID   512
#define NHEAD  8
#define LAYERS 6
#define BB     16
#define TT     32
#define NTOK   64
#define KCONV  576
#define BT     512
#define MCONV  32768

// ---------------- device scratch ----------------
__device__ __half g_wT_h[KCONV * DHID];
__device__ __half g_patch_h[(size_t)MCONV * KCONV];
__device__ __half g_kqvw_h[LAYERS * DHID * 3 * DHID];
__device__ __half g_projw_h[LAYERS * DHID * DHID];
__device__ __half g_w1_h[LAYERS * DHID * 4 * DHID];
__device__ __half g_w2_h[LAYERS * 4 * DHID * DHID];
__device__ __half g_xln_h[BT * DHID];
__device__ __half g_attn_h[BT * DHID];
__device__ __half g_mlp_h[BT * 4 * DHID];
__device__ float  g_tok[(size_t)MCONV * DHID];
__device__ float  g_film[BT * 2 * DHID];
__device__ float  g_h[BT * DHID];
__device__ float  g_kqv[BT * 3 * DHID];

// ---------------- helpers ----------------
__device__ __forceinline__ float warp_sum(float v) {
#pragma unroll
    for (int o = 16; o; o >>= 1) v += __shfl_xor_sync(0xffffffffu, v, o);
    return v;
}
__device__ __forceinline__ float warp_max(float v) {
#pragma unroll
    for (int o = 16; o; o >>= 1) v = fmaxf(v, __shfl_xor_sync(0xffffffffu, v, o));
    return v;
}
__device__ __forceinline__ float block_sum_256(float v, float* sbuf) {
    int lane = threadIdx.x & 31, wid = threadIdx.x >> 5;
    v = warp_sum(v);
    if (lane == 0) sbuf[wid] = v;
    __syncthreads();
    float r = sbuf[0];
#pragma unroll
    for (int w = 1; w < 8; w++) r += sbuf[w];
    __syncthreads();
    return r;
}
__device__ __forceinline__ unsigned smem_u32(const void* p) {
    return (unsigned)__cvta_generic_to_shared(p);
}

// ---------------- merged weight conversion (4 segments, 1 launch) ----------------
__global__ void f2h4_kernel(const float4* __restrict__ s0, const float4* __restrict__ s1,
                            const float4* __restrict__ s2, const float4* __restrict__ s3,
                            __half* __restrict__ d0, __half* __restrict__ d1,
                            __half* __restrict__ d2, __half* __restrict__ d3,
                            int n0, int n1, int n2, int n3) {
    int i = blockIdx.x * 256 + threadIdx.x;
    const float4* s; __half* d; int j = i;
    if (j < n0) { s = s0; d = d0; }
    else { j -= n0;
        if (j < n1) { s = s1; d = d1; }
        else { j -= n1;
            if (j < n2) { s = s2; d = d2; }
            else { j -= n2; if (j >= n3) return; s = s3; d = d3; }
        }
    }
    float4 v = s[j];
    __half2* o = (__half2*)(d + (size_t)j * 4);
    o[0] = __floats2half2_rn(v.x, v.y);
    o[1] = __floats2half2_rn(v.z, v.w);
}
__global__ void transpose_wh_kernel(const float* __restrict__ w, __half* __restrict__ wT) {
    int idx = blockIdx.x * 256 + threadIdx.x;
    if (idx >= DHID * KCONV) return;
    int d = idx / KCONV, k = idx % KCONV;
    wT[k * DHID + d] = __float2half_rn(w[idx]);
}

// ---------------- im2col (causal time pad 2) -> fp16 ----------------
__global__ void im2col_kernel(const float* __restrict__ x, __half* __restrict__ p) {
    long idx = (long)blockIdx.x * 256 + threadIdx.x;
    if (idx >= (long)MCONV * KCONV) return;
    int kcol = (int)(idx % KCONV);
    long row = idx / KCONV;
    int n  = (int)(row & 63);
    int bt = (int)(row >> 6);
    int t  = bt & 31;
    int b  = bt >> 5;
    int hn = n >> 3, wn = n & 7;
    int pw = kcol & 7;
    int ph = (kcol >> 3) & 7;
    int kt = (kcol >> 6) % 3;
    int c  = kcol / 192;
    int tt = t + kt - 2;
    float v = 0.f;
    if (tt >= 0)
        v = x[((((long)(b * 32 + tt) * 3 + c) * 64) + hn * 8 + ph) * 64 + wn * 8 + pw];
    p[idx] = __float2half_rn(v);
}

// ---------------- tensor-core GEMM ----------------
// BM = WM*MI*16.  epi 0: Cf=acc+bias  1: Ch=half(gelu)  2: Cf=res+scale[0]*(acc+bias)
#define APAD 8
#define BPAD 8

template<int BM, int BN, int WM, int WN, int MI>
__global__ void hgemm_kernel(const __half* __restrict__ A, const __half* __restrict__ B,
                             const float* __restrict__ bias,
                             float* __restrict__ Cf, __half* __restrict__ Ch,
                             int M, int N, int K, int epi,
                             const float* __restrict__ res, const float* __restrict__ scale) {
    constexpr int NT = WM * WN * 32;
    constexpr int A_IT = BM * 4 / NT;
    constexpr int B_IT = 4 * BN / NT;
    constexpr int WTN = BN / WN;
    constexpr int NJ = WTN / 8;
    constexpr int NJ2 = WTN / 16;
    __shared__ __half As[2][BM][32 + APAD];
    __shared__ __half Bs[2][32][BN + BPAD];

    int tid = threadIdx.x;
    int lane = tid & 31;
    int warp = tid >> 5;
    int wm = warp / WN, wn = warp % WN;
    int bm = blockIdx.y * BM, bn = blockIdx.x * BN;
    int KT = K >> 5;

    float c[MI][NJ][4];
#pragma unroll
    for (int i = 0; i < MI; i++)
#pragma unroll
        for (int j = 0; j < NJ; j++)
#pragma unroll
            for (int e = 0; e < 4; e++) c[i][j][e] = 0.f;

#pragma unroll
    for (int i = 0; i < A_IT; i++) {
        int u = tid + i * NT; int r = u >> 2, q = u & 3;
        *(uint4*)&As[0][r][q * 8] = *(const uint4*)(A + (long)(bm + r) * K + q * 8);
    }
#pragma unroll
    for (int i = 0; i < B_IT; i++) {
        int v = tid + i * NT; int r = v / (BN / 8), q = v % (BN / 8);
        *(uint4*)&Bs[0][r][q * 8] = *(const uint4*)(B + (long)r * N + bn + q * 8);
    }
    __syncthreads();

    for (int kt = 0; kt < KT; kt++) {
        uint4 pa[A_IT]; uint4 pb[B_IT];
        bool more = (kt + 1 < KT);
        if (more) {
            int k0 = (kt + 1) * 32;
#pragma unroll
            for (int i = 0; i < A_IT; i++) {
                int u = tid + i * NT; int r = u >> 2, q = u & 3;
                pa[i] = *(const uint4*)(A + (long)(bm + r) * K + k0 + q * 8);
            }
#pragma unroll
            for (int i = 0; i < B_IT; i++) {
                int v = tid + i * NT; int r = v / (BN / 8), q = v % (BN / 8);
                pb[i] = *(const uint4*)(B + (long)(k0 + r) * N + bn + q * 8);
            }
        }
        int buf = kt & 1;
#pragma unroll
        for (int ks = 0; ks < 32; ks += 16) {
            unsigned a[MI][4], bf[NJ2][4];
#pragma unroll
            for (int i = 0; i < MI; i++) {
                unsigned addr = smem_u32(&As[buf][wm * MI * 16 + i * 16 + (lane & 15)][ks + (lane >> 4) * 8]);
                asm volatile("ldmatrix.sync.aligned.m8n8.x4.shared.b16 {%0,%1,%2,%3}, [%4];"
                             : "=r"(a[i][0]), "=r"(a[i][1]), "=r"(a[i][2]), "=r"(a[i][3]) : "r"(addr));
            }
#pragma unroll
            for (int j2 = 0; j2 < NJ2; j2++) {
                unsigned addr = smem_u32(&Bs[buf][ks + (lane & 7) + ((lane >> 3) & 1) * 8]
                                             [wn * WTN + j2 * 16 + (lane >> 4) * 8]);
                asm volatile("ldmatrix.sync.aligned.m8n8.x4.trans.shared.b16 {%0,%1,%2,%3}, [%4];"
                             : "=r"(bf[j2][0]), "=r"(bf[j2][1]), "=r"(bf[j2][2]), "=r"(bf[j2][3]) : "r"(addr));
            }
#pragma unroll
            for (int i = 0; i < MI; i++)
#pragma unroll
                for (int j = 0; j < NJ; j++) {
                    unsigned b0 = bf[j >> 1][(j & 1) * 2], b1 = bf[j >> 1][(j & 1) * 2 + 1];
                    asm volatile(
                        "mma.sync.aligned.m16n8k16.row.col.f32.f16.f16.f32 "
                        "{%0,%1,%2,%3}, {%4,%5,%6,%7}, {%8,%9}, {%0,%1,%2,%3};"
                        : "+f"(c[i][j][0]), "+f"(c[i][j][1]), "+f"(c[i][j][2]), "+f"(c[i][j][3])
                        : "r"(a[i][0]), "r"(a[i][1]), "r"(a[i][2]), "r"(a[i][3]), "r"(b0), "r"(b1));
                }
        }
        if (more) {
            int nb = buf ^ 1;
#pragma unroll
            for (int i = 0; i < A_IT; i++) {
                int u = tid + i * NT; int r = u >> 2, q = u & 3;
                *(uint4*)&As[nb][r][q * 8] = pa[i];
            }
#pragma unroll
            for (int i = 0; i < B_IT; i++) {
                int v = tid + i * NT; int r = v / (BN / 8), q = v % (BN / 8);
                *(uint4*)&Bs[nb][r][q * 8] = pb[i];
            }
        }
        __syncthreads();
    }

    float sc = (epi == 2) ? scale[0] : 0.f;
#pragma unroll
    for (int i = 0; i < MI; i++)
#pragma unroll
        for (int j = 0; j < NJ; j++) {
            int r0 = bm + wm * MI * 16 + i * 16 + (lane >> 2);
            int c0 = bn + wn * WTN + j * 8 + (lane & 3) * 2;
#pragma unroll
            for (int half_ = 0; half_ < 2; half_++) {
                int rr = r0 + half_ * 8;
                float v0 = c[i][j][half_ * 2 + 0] + bias[c0];
                float v1 = c[i][j][half_ * 2 + 1] + bias[c0 + 1];
                long off = (long)rr * N + c0;
                if (epi == 0) {
                    *(float2*)&Cf[off] = make_float2(v0, v1);
                } else if (epi == 1) {
                    float g0 = 0.5f * v0 * (1.f + erff(v0 * 0.70710678118654752f));
                    float g1 = 0.5f * v1 * (1.f + erff(v1 * 0.70710678118654752f));
                    *(__half2*)&Ch[off] = __floats2half2_rn(g0, g1);
                } else {
                    float2 rv = *(const float2*)&res[off];
                    *(float2*)&Cf[off] = make_float2(rv.x + sc * v0, rv.y + sc * v1);
                }
            }
        }
}

// ---------------- small fp32 GEMM (film only) ----------------
__global__ void gemm_kernel(const float* __restrict__ A, const float* __restrict__ Bm,
                            const float* __restrict__ bias, float* C,
                            int M, int N, int K) {
    __shared__ float As[16][65];
    __shared__ float Bs[16][64];
    int bm = blockIdx.y * 64, bn = blockIdx.x * 64;
    int tid = threadIdx.x;
    int tx = tid & 15, ty = tid >> 4;
    float acc[4][4];
#pragma unroll
    for (int i = 0; i < 4; i++)
#pragma unroll
        for (int j = 0; j < 4; j++) acc[i][j] = 0.f;
    const float* Ab = A + (long)bm * K;
    for (int k0 = 0; k0 < K; k0 += 16) {
        {
            int col = tid & 15, row = tid >> 4;
#pragma unroll
            for (int r = 0; r < 4; r++)
                As[col][row + r * 16] = Ab[(long)(row + r * 16) * K + k0 + col];
        }
        {
            int col = tid & 63, row = tid >> 6;
#pragma unroll
            for (int r = 0; r < 4; r++)
                Bs[row + r * 4][col] = Bm[(long)(k0 + row + r * 4) * N + bn + col];
        }
        __syncthreads();
#pragma unroll
        for (int kk = 0; kk < 16; kk++) {
            float a0 = As[kk][ty * 4 + 0], a1 = As[kk][ty * 4 + 1];
            float a2 = As[kk][ty * 4 + 2], a3 = As[kk][ty * 4 + 3];
            float4 b4 = *(const float4*)&Bs[kk][tx * 4];
            acc[0][0] += a0 * b4.x; acc[0][1] += a0 * b4.y; acc[0][2] += a0 * b4.z; acc[0][3] += a0 * b4.w;
            acc[1][0] += a1 * b4.x; acc[1][1] += a1 * b4.y; acc[1][2] += a1 * b4.z; acc[1][3] += a1 * b4.w;
            acc[2][0] += a2 * b4.x; acc[2][1] += a2 * b4.y; acc[2][2] += a2 * b4.z; acc[2][3] += a2 * b4.w;
            acc[3][0] += a3 * b4.x; acc[3][1] += a3 * b4.y; acc[3][2] += a3 * b4.z; acc[3][3] += a3 * b4.w;
        }
        __syncthreads();
    }
#pragma unroll
    for (int i = 0; i < 4; i++) {
        int row = bm + ty * 4 + i;
#pragma unroll
        for (int j = 0; j < 4; j++) {
            int col = bn + tx * 4 + j;
            C[(long)row * N + col] = acc[i][j] + bias[col];
        }
    }
}

// ---------------- fused token LN + FiLM + spatial mean ----------------
__global__ void tok_reduce_kernel(const float* __restrict__ tok, const float* __restrict__ tg,
                                  const float* __restrict__ tb, const float* __restrict__ film,
                                  float* __restrict__ h) {
    __shared__ float accs[8][DHID];
    int bt = blockIdx.x;
    int wid = threadIdx.x >> 5, lane = threadIdx.x & 31;
    float acc[16];
#pragma unroll
    for (int i = 0; i < 16; i++) acc[i] = 0.f;
    const float* gb = film + bt * (2 * DHID);
    for (int n = wid; n < NTOK; n += 8) {
        const float* row = tok + (long)(bt * NTOK + n) * DHID;
        float v[16]; float s = 0.f;
#pragma unroll
        for (int i = 0; i < 16; i++) { v[i] = row[i * 32 + lane]; s += v[i]; }
        s = warp_sum(s);
        float mu = s * (1.f / 512.f);
        float vs = 0.f;
#pragma unroll
        for (int i = 0; i < 16; i++) { float d = v[i] - mu; vs += d * d; }
        vs = warp_sum(vs);
        float rstd = rsqrtf(vs * (1.f / 512.f) + 1e-5f);
#pragma unroll
        for (int i = 0; i < 16; i++) {
            int d = i * 32 + lane;
            float ln = (v[i] - mu) * rstd * tg[d] + tb[d];
            acc[i] += (1.f + 0.5f * gb[d]) * ln + 0.5f * gb[DHID + d];
        }
    }
#pragma unroll
    for (int i = 0; i < 16; i++) accs[wid][i * 32 + lane] = acc[i];
    __syncthreads();
    for (int d = threadIdx.x; d < DHID; d += 256) {
        float s = 0.f;
#pragma unroll
        for (int w = 0; w < 8; w++) s += accs[w][d];
        h[bt * DHID + d] = s * (1.f / 64.f);
    }
}

// ---------------- LayerNorm -> fp16 out ----------------
__global__ void ln_h_kernel(const float* __restrict__ in, const float* __restrict__ g,
                            const float* __restrict__ b, __half* __restrict__ out) {
    __shared__ float sbuf[8];
    int tok = blockIdx.x, tid = threadIdx.x;
    const float* row = in + tok * DHID;
    float v0 = row[tid], v1 = row[tid + 256];
    float sum = block_sum_256(v0 + v1, sbuf);
    float mu = sum * (1.f / 512.f);
    float d0 = v0 - mu, d1 = v1 - mu;
    float vs = block_sum_256(d0 * d0 + d1 * d1, sbuf);
    float rstd = rsqrtf(vs * (1.f / 512.f) + 1e-5f);
    out[tok * DHID + tid]       = __float2half_rn(d0 * rstd * g[tid] + b[tid]);
    out[tok * DHID + tid + 256] = __float2half_rn(d1 * rstd * g[tid + 256] + b[tid + 256]);
}

// ---------------- attention per (b, head) ----------------
__global__ void attn_kernel(const float* __restrict__ kqv, __half* __restrict__ out) {
    __shared__ float q[32][64];
    __shared__ float k[32][65];
    __shared__ float v[32][64];
    __shared__ float s[32][33];
    int bh = blockIdx.x;
    int b = bh >> 3, h = bh & 7;
    int tid = threadIdx.x;
#pragma unroll
    for (int i = 0; i < 8; i++) {
        int e = tid + i * 256;
        int t = e >> 6, d = e & 63;
        const float* base = kqv + (long)(b * 32 + t) * 1536 + h * 64;
        float kk = base[d];
        float qq = base[512 + d];
        v[t][d] = base[1024 + d];
        int j = d & 31;
        float ang = (float)t * powf(10000.f, -(float)j * (1.f / 32.f));
        float sn, cs;
        sincosf(ang, &sn, &cs);
        if (d < 32) {
            float kp = base[d + 32], qp = base[512 + d + 32];
            k[t][d] = kk * cs - kp * sn;
            q[t][d] = qq * cs - qp * sn;
        } else {
            float kp = base[d - 32], qp = base[512 + d - 32];
            k[t][d] = kk * cs + kp * sn;
            q[t][d] = qq * cs + qp * sn;
        }
    }
    __syncthreads();
#pragma unroll
    for (int i = 0; i < 4; i++) {
        int e = tid + i * 256;
        int tq = e >> 5, tk = e & 31;
        if (tk <= tq) {
            float acc = 0.f;
#pragma unroll
            for (int dd = 0; dd < 64; dd++) acc += q[tq][dd] * k[tk][dd];
            s[tq][tk] = acc * 0.125f;
        }
    }
    __syncthreads();
    int wid = tid >> 5, lane = tid & 31;
    for (int r = wid; r < 32; r += 8) {
        float val = (lane <= r) ? s[r][lane] : -3.4e38f;
        float m = warp_max(val);
        float e = (lane <= r) ? expf(val - m) : 0.f;
        float sum = warp_sum(e);
        s[r][lane] = e / sum;
    }
    __syncthreads();
#pragma unroll
    for (int i = 0; i < 8; i++) {
        int e = tid + i * 256;
        int t = e >> 6, d = e & 63;
        float acc = 0.f;
#pragma unroll
        for (int kk2 = 0; kk2 < 32; kk2++) acc += s[t][kk2] * v[kk2][d];
        out[(long)(b * 32 + t) * DHID + h * 64 + d] = __float2half_rn(acc);
    }
}

// ---------------- head ----------------
__global__ void head_kernel(const float* __restrict__ hin, const float* __restrict__ g,
                            const float* __restrict__ b, const float* __restrict__ w,
                            const float* __restrict__ bias0, float* __restrict__ out) {
    __shared__ float sbuf[8];
    int tok = blockIdx.x, tid = threadIdx.x;
    const float* row = hin + tok * DHID;
    float v0 = row[tid], v1 = row[tid + 256];
    float sum = block_sum_256(v0 + v1, sbuf);
    float mu = sum * (1.f / 512.f);
    float d0 = v0 - mu, d1 = v1 - mu;
    float vs = block_sum_256(d0 * d0 + d1 * d1, sbuf);
    float rstd = rsqrtf(vs * (1.f / 512.f) + 1e-5f);
    float c = (d0 * rstd * g[tid] + b[tid]) * w[tid] +
              (d1 * rstd * g[tid + 256] + b[tid + 256]) * w[tid + 256];
    float tot = block_sum_256(c, sbuf);
    if (tid == 0) out[tok] = tot + bias0[0];
}

// ---------------- launch ----------------
extern "C" void kernel_launch(void* const* d_in, const int* in_sizes, int n_in,
                              void* d_out, int out_size) {
    const float* x       = (const float*)d_in[0];
    const float* z       = (const float*)d_in[1];
    const float* conv_w  = (const float*)d_in[2];
    const float* conv_b  = (const float*)d_in[3];
    const float* tok_g   = (const float*)d_in[4];
    const float* tok_b   = (const float*)d_in[5];
    const float* film_w  = (const float*)d_in[6];
    const float* film_b  = (const float*)d_in[7];
    const float* ln1_g   = (const float*)d_in[8];
    const float* ln1_b   = (const float*)d_in[9];
    const float* kqv_w   = (const float*)d_in[10];
    const float* kqv_b   = (const float*)d_in[11];
    const float* proj_w  = (const float*)d_in[12];
    const float* proj_b  = (const float*)d_in[13];
    const float* ln2_g   = (const float*)d_in[14];
    const float* ln2_b   = (const float*)d_in[15];
    const float* mlp_w1  = (const float*)d_in[16];
    const float* mlp_b1  = (const float*)d_in[17];
    const float* mlp_w2  = (const float*)d_in[18];
    const float* mlp_b2  = (const float*)d_in[19];
    const float* rs_attn = (const float*)d_in[20];
    const float* rs_mlp  = (const float*)d_in[21];
    const float* head_g  = (const float*)d_in[22];
    const float* head_b  = (const float*)d_in[23];
    const float* head_w  = (const float*)d_in[24];
    const float* head_bi = (const float*)d_in[25];
    float* out = (float*)d_out;

    __half *wT_h, *patch_h, *kqvw_h, *projw_h, *w1_h, *w2_h, *xln_h, *attn_h, *mlp_h;
    float *tok, *film, *h, *kqv;
    cudaGetSymbolAddress((void**)&wT_h, g_wT_h);
    cudaGetSymbolAddress((void**)&patch_h, g_patch_h);
    cudaGetSymbolAddress((void**)&kqvw_h, g_kqvw_h);
    cudaGetSymbolAddress((void**)&projw_h, g_projw_h);
    cudaGetSymbolAddress((void**)&w1_h, g_w1_h);
    cudaGetSymbolAddress((void**)&w2_h, g_w2_h);
    cudaGetSymbolAddress((void**)&xln_h, g_xln_h);
    cudaGetSymbolAddress((void**)&attn_h, g_attn_h);
    cudaGetSymbolAddress((void**)&mlp_h, g_mlp_h);
    cudaGetSymbolAddress((void**)&tok, g_tok);
    cudaGetSymbolAddress((void**)&film, g_film);
    cudaGetSymbolAddress((void**)&h, g_h);
    cudaGetSymbolAddress((void**)&kqv, g_kqv);

    // weight conversions
    transpose_wh_kernel<<<(DHID * KCONV + 255) / 256, 256>>>(conv_w, wT_h);
    {
        int n0 = LAYERS * DHID * 3 * DHID / 4;
        int n1 = LAYERS * DHID * DHID / 4;
        int n2 = LAYERS * DHID * 4 * DHID / 4;
        int n3 = n2;
        int tot = n0 + n1 + n2 + n3;
        f2h4_kernel<<<(tot + 255) / 256, 256>>>(
            (const float4*)kqv_w, (const float4*)proj_w, (const float4*)mlp_w1, (const float4*)mlp_w2,
            kqvw_h, projw_h, w1_h, w2_h, n0, n1, n2, n3);
    }
    // tokenizer
    im2col_kernel<<<(int)(((long)MCONV * KCONV + 255) / 256), 256>>>(x, patch_h);
    hgemm_kernel<128, 64, 4, 2, 2><<<dim3(DHID / 64, MCONV / 128), 256>>>(
        patch_h, wT_h, conv_b, tok, nullptr, MCONV, DHID, KCONV, 0, nullptr, nullptr);
    gemm_kernel<<<dim3(1024 / 64, BT / 64), 256>>>(z, film_w, film_b, film, BT, 1024, 32);
    tok_reduce_kernel<<<BT, 256>>>(tok, tok_g, tok_b, film, h);

    // transformer (BM=32 tiles: 2x block count vs BM=64)
    for (int i = 0; i < LAYERS; i++) {
        ln_h_kernel<<<BT, 256>>>(h, ln1_g + i * DHID, ln1_b + i * DHID, xln_h);
        hgemm_kernel<32, 64, 2, 2, 1><<<dim3(1536 / 64, BT / 32), 128>>>(
            xln_h, kqvw_h + (long)i * DHID * 1536, kqv_b + i * 1536, kqv, nullptr,
            BT, 1536, DHID, 0, nullptr, nullptr);
        attn_kernel<<<BB * NHEAD, 256>>>(kqv, attn_h);
        hgemm_kernel<32, 64, 2, 2, 1><<<dim3(DHID / 64, BT / 32), 128>>>(
            attn_h, projw_h + (long)i * DHID * DHID, proj_b + i * DHID, h, nullptr,
            BT, DHID, DHID, 2, h, rs_attn + i);
        ln_h_kernel<<<BT, 256>>>(h, ln2_g + i * DHID, ln2_b + i * DHID, xln_h);
        hgemm_kernel<32, 64, 2, 2, 1><<<dim3(2048 / 64, BT / 32), 128>>>(
            xln_h, w1_h + (long)i * DHID * 2048, mlp_b1 + i * 2048, nullptr, mlp_h,
            BT, 2048, DHID, 1, nullptr, nullptr);
        hgemm_kernel<32, 64, 2, 2, 1><<<dim3(DHID / 64, BT / 32), 128>>>(
            mlp_h, w2_h + (long)i * 2048 * DHID, mlp_b2 + i * DHID, h, nullptr,
            BT, DHID, 2048, 2, h, rs_mlp + i);
    }
    head_kernel<<<BT, 256>>>(h, head_g, head_b, head_w, head_bi, out);
}

// round 6
// speedup vs baseline: 1.4826x; 1.3453x over previous
#include <cuda_runtime.h>
#include <cuda_fp16.h>
#include <cstdint>
#include <math.h>

// ---------------- problem constants ----------------
#define DHID   512
#define NHEAD  8
#define LAYERS 6
#define BB     16
#define TT     32
#define NTOK   64
#define KCONV  576
#define BT     512
#define MCONV  32768

// ---------------- device scratch ----------------
__device__ __half g_wT_h[KCONV * DHID];
__device__ __half g_patch_h[(size_t)MCONV * KCONV];
__device__ __half g_kqvw_h[LAYERS * DHID * 3 * DHID];
__device__ __half g_projw_h[LAYERS * DHID * DHID];
__device__ __half g_w1_h[LAYERS * DHID * 4 * DHID];
__device__ __half g_w2_h[LAYERS * 4 * DHID * DHID];
__device__ __half g_xln_h[BT * DHID];
__device__ __half g_attn_h[BT * DHID];
__device__ __half g_mlp_h[BT * 4 * DHID];
__device__ float  g_tok[(size_t)MCONV * DHID];
__device__ float  g_film[BT * 2 * DHID];
__device__ float  g_h[BT * DHID];
__device__ float  g_kqv[BT * 3 * DHID];

// ---------------- helpers ----------------
__device__ __forceinline__ float warp_sum(float v) {
#pragma unroll
    for (int o = 16; o; o >>= 1) v += __shfl_xor_sync(0xffffffffu, v, o);
    return v;
}
__device__ __forceinline__ float warp_max(float v) {
#pragma unroll
    for (int o = 16; o; o >>= 1) v = fmaxf(v, __shfl_xor_sync(0xffffffffu, v, o));
    return v;
}
__device__ __forceinline__ float block_sum_256(float v, float* sbuf) {
    int lane = threadIdx.x & 31, wid = threadIdx.x >> 5;
    v = warp_sum(v);
    if (lane == 0) sbuf[wid] = v;
    __syncthreads();
    float r = sbuf[0];
#pragma unroll
    for (int w = 1; w < 8; w++) r += sbuf[w];
    __syncthreads();
    return r;
}
__device__ __forceinline__ unsigned smem_u32(const void* p) {
    return (unsigned)__cvta_generic_to_shared(p);
}
__device__ __forceinline__ void cp_async16(unsigned dst, const void* src) {
    asm volatile("cp.async.cg.shared.global [%0], [%1], 16;" :: "r"(dst), "l"(src));
}
__device__ __forceinline__ void cp_commit() {
    asm volatile("cp.async.commit_group;");
}
template<int N>
__device__ __forceinline__ void cp_wait() {
    asm volatile("cp.async.wait_group %0;" :: "n"(N));
}

// ---------------- merged weight conversion (4 segments, 1 launch) ----------------
__global__ void f2h4_kernel(const float4* __restrict__ s0, const float4* __restrict__ s1,
                            const float4* __restrict__ s2, const float4* __restrict__ s3,
                            __half* __restrict__ d0, __half* __restrict__ d1,
                            __half* __restrict__ d2, __half* __restrict__ d3,
                            int n0, int n1, int n2, int n3) {
    int i = blockIdx.x * 256 + threadIdx.x;
    const float4* s; __half* d; int j = i;
    if (j < n0) { s = s0; d = d0; }
    else { j -= n0;
        if (j < n1) { s = s1; d = d1; }
        else { j -= n1;
            if (j < n2) { s = s2; d = d2; }
            else { j -= n2; if (j >= n3) return; s = s3; d = d3; }
        }
    }
    float4 v = s[j];
    __half2* o = (__half2*)(d + (size_t)j * 4);
    o[0] = __floats2half2_rn(v.x, v.y);
    o[1] = __floats2half2_rn(v.z, v.w);
}
__global__ void transpose_wh_kernel(const float* __restrict__ w, __half* __restrict__ wT) {
    int idx = blockIdx.x * 256 + threadIdx.x;
    if (idx >= DHID * KCONV) return;
    int d = idx / KCONV, k = idx % KCONV;
    wT[k * DHID + d] = __float2half_rn(w[idx]);
}

// ---------------- im2col (causal time pad 2) -> fp16 ----------------
__global__ void im2col_kernel(const float* __restrict__ x, __half* __restrict__ p) {
    long idx = (long)blockIdx.x * 256 + threadIdx.x;
    if (idx >= (long)MCONV * KCONV) return;
    int kcol = (int)(idx % KCONV);
    long row = idx / KCONV;
    int n  = (int)(row & 63);
    int bt = (int)(row >> 6);
    int t  = bt & 31;
    int b  = bt >> 5;
    int hn = n >> 3, wn = n & 7;
    int pw = kcol & 7;
    int ph = (kcol >> 3) & 7;
    int kt = (kcol >> 6) % 3;
    int c  = kcol / 192;
    int tt = t + kt - 2;
    float v = 0.f;
    if (tt >= 0)
        v = x[((((long)(b * 32 + tt) * 3 + c) * 64) + hn * 8 + ph) * 64 + wn * 8 + pw];
    p[idx] = __float2half_rn(v);
}

// ---------------- tensor-core GEMM, 3-stage cp.async pipeline ----------------
// BM = WM*MI*16.  epi 0: Cf=acc+bias  1: Ch=half(gelu)  2: Cf=res+scale[0]*(acc+bias)
#define APAD 8
#define BPAD 8
#define STG  3

template<int BM, int BN, int WM, int WN, int MI>
__global__ void hgemm_kernel(const __half* __restrict__ A, const __half* __restrict__ B,
                             const float* __restrict__ bias,
                             float* __restrict__ Cf, __half* __restrict__ Ch,
                             int M, int N, int K, int epi,
                             const float* __restrict__ res, const float* __restrict__ scale) {
    constexpr int NT = WM * WN * 32;
    constexpr int A_IT = BM * 4 / NT;      // uint4 per thread, A stage
    constexpr int B_IT = 4 * BN / NT;      // uint4 per thread, B stage
    constexpr int WTN = BN / WN;
    constexpr int NJ = WTN / 8;
    constexpr int NJ2 = WTN / 16;
    __shared__ __half As[STG][BM][32 + APAD];
    __shared__ __half Bs[STG][32][BN + BPAD];

    int tid = threadIdx.x;
    int lane = tid & 31;
    int warp = tid >> 5;
    int wm = warp / WN, wn = warp % WN;
    int bm = blockIdx.y * BM, bn = blockIdx.x * BN;
    int KT = K >> 5;

    // per-thread load coords
    int ar[A_IT], aq[A_IT], br[B_IT], bq[B_IT];
#pragma unroll
    for (int i = 0; i < A_IT; i++) { int u = tid + i * NT; ar[i] = u >> 2; aq[i] = u & 3; }
#pragma unroll
    for (int i = 0; i < B_IT; i++) { int v = tid + i * NT; br[i] = v / (BN / 8); bq[i] = v % (BN / 8); }

    // prologue: fill stages 0..STG-2
#pragma unroll
    for (int s = 0; s < STG - 1; s++) {
        int k0 = s * 32;
        if (s < KT) {
#pragma unroll
            for (int i = 0; i < A_IT; i++)
                cp_async16(smem_u32(&As[s][ar[i]][aq[i] * 8]),
                           A + (long)(bm + ar[i]) * K + k0 + aq[i] * 8);
#pragma unroll
            for (int i = 0; i < B_IT; i++)
                cp_async16(smem_u32(&Bs[s][br[i]][bq[i] * 8]),
                           B + (long)(k0 + br[i]) * N + bn + bq[i] * 8);
        }
        cp_commit();
    }

    float c[MI][NJ][4];
#pragma unroll
    for (int i = 0; i < MI; i++)
#pragma unroll
        for (int j = 0; j < NJ; j++)
#pragma unroll
            for (int e = 0; e < 4; e++) c[i][j][e] = 0.f;

    for (int kt = 0; kt < KT; kt++) {
        cp_wait<STG - 2>();
        __syncthreads();
        int buf = kt % STG;
#pragma unroll
        for (int ks = 0; ks < 32; ks += 16) {
            unsigned a[MI][4], bf[NJ2][4];
#pragma unroll
            for (int i = 0; i < MI; i++) {
                unsigned addr = smem_u32(&As[buf][wm * MI * 16 + i * 16 + (lane & 15)][ks + (lane >> 4) * 8]);
                asm volatile("ldmatrix.sync.aligned.m8n8.x4.shared.b16 {%0,%1,%2,%3}, [%4];"
                             : "=r"(a[i][0]), "=r"(a[i][1]), "=r"(a[i][2]), "=r"(a[i][3]) : "r"(addr));
            }
#pragma unroll
            for (int j2 = 0; j2 < NJ2; j2++) {
                unsigned addr = smem_u32(&Bs[buf][ks + (lane & 7) + ((lane >> 3) & 1) * 8]
                                             [wn * WTN + j2 * 16 + (lane >> 4) * 8]);
                asm volatile("ldmatrix.sync.aligned.m8n8.x4.trans.shared.b16 {%0,%1,%2,%3}, [%4];"
                             : "=r"(bf[j2][0]), "=r"(bf[j2][1]), "=r"(bf[j2][2]), "=r"(bf[j2][3]) : "r"(addr));
            }
#pragma unroll
            for (int i = 0; i < MI; i++)
#pragma unroll
                for (int j = 0; j < NJ; j++) {
                    unsigned b0 = bf[j >> 1][(j & 1) * 2], b1 = bf[j >> 1][(j & 1) * 2 + 1];
                    asm volatile(
                        "mma.sync.aligned.m16n8k16.row.col.f32.f16.f16.f32 "
                        "{%0,%1,%2,%3}, {%4,%5,%6,%7}, {%8,%9}, {%0,%1,%2,%3};"
                        : "+f"(c[i][j][0]), "+f"(c[i][j][1]), "+f"(c[i][j][2]), "+f"(c[i][j][3])
                        : "r"(a[i][0]), "r"(a[i][1]), "r"(a[i][2]), "r"(a[i][3]), "r"(b0), "r"(b1));
                }
        }
        // issue loads for stage kt+STG-1
        int kn = kt + STG - 1;
        if (kn < KT) {
            int nb = kn % STG;
            int k0 = kn * 32;
#pragma unroll
            for (int i = 0; i < A_IT; i++)
                cp_async16(smem_u32(&As[nb][ar[i]][aq[i] * 8]),
                           A + (long)(bm + ar[i]) * K + k0 + aq[i] * 8);
#pragma unroll
            for (int i = 0; i < B_IT; i++)
                cp_async16(smem_u32(&Bs[nb][br[i]][bq[i] * 8]),
                           B + (long)(k0 + br[i]) * N + bn + bq[i] * 8);
        }
        cp_commit();
    }

    float sc = (epi == 2) ? scale[0] : 0.f;
#pragma unroll
    for (int i = 0; i < MI; i++)
#pragma unroll
        for (int j = 0; j < NJ; j++) {
            int r0 = bm + wm * MI * 16 + i * 16 + (lane >> 2);
            int c0 = bn + wn * WTN + j * 8 + (lane & 3) * 2;
#pragma unroll
            for (int half_ = 0; half_ < 2; half_++) {
                int rr = r0 + half_ * 8;
                float v0 = c[i][j][half_ * 2 + 0] + bias[c0];
                float v1 = c[i][j][half_ * 2 + 1] + bias[c0 + 1];
                long off = (long)rr * N + c0;
                if (epi == 0) {
                    *(float2*)&Cf[off] = make_float2(v0, v1);
                } else if (epi == 1) {
                    float g0 = 0.5f * v0 * (1.f + erff(v0 * 0.70710678118654752f));
                    float g1 = 0.5f * v1 * (1.f + erff(v1 * 0.70710678118654752f));
                    *(__half2*)&Ch[off] = __floats2half2_rn(g0, g1);
                } else {
                    float2 rv = *(const float2*)&res[off];
                    *(float2*)&Cf[off] = make_float2(rv.x + sc * v0, rv.y + sc * v1);
                }
            }
        }
}

// ---------------- small fp32 GEMM (film only) ----------------
__global__ void gemm_kernel(const float* __restrict__ A, const float* __restrict__ Bm,
                            const float* __restrict__ bias, float* C,
                            int M, int N, int K) {
    __shared__ float As[16][65];
    __shared__ float Bs[16][64];
    int bm = blockIdx.y * 64, bn = blockIdx.x * 64;
    int tid = threadIdx.x;
    int tx = tid & 15, ty = tid >> 4;
    float acc[4][4];
#pragma unroll
    for (int i = 0; i < 4; i++)
#pragma unroll
        for (int j = 0; j < 4; j++) acc[i][j] = 0.f;
    const float* Ab = A + (long)bm * K;
    for (int k0 = 0; k0 < K; k0 += 16) {
        {
            int col = tid & 15, row = tid >> 4;
#pragma unroll
            for (int r = 0; r < 4; r++)
                As[col][row + r * 16] = Ab[(long)(row + r * 16) * K + k0 + col];
        }
        {
            int col = tid & 63, row = tid >> 6;
#pragma unroll
            for (int r = 0; r < 4; r++)
                Bs[row + r * 4][col] = Bm[(long)(k0 + row + r * 4) * N + bn + col];
        }
        __syncthreads();
#pragma unroll
        for (int kk = 0; kk < 16; kk++) {
            float a0 = As[kk][ty * 4 + 0], a1 = As[kk][ty * 4 + 1];
            float a2 = As[kk][ty * 4 + 2], a3 = As[kk][ty * 4 + 3];
            float4 b4 = *(const float4*)&Bs[kk][tx * 4];
            acc[0][0] += a0 * b4.x; acc[0][1] += a0 * b4.y; acc[0][2] += a0 * b4.z; acc[0][3] += a0 * b4.w;
            acc[1][0] += a1 * b4.x; acc[1][1] += a1 * b4.y; acc[1][2] += a1 * b4.z; acc[1][3] += a1 * b4.w;
            acc[2][0] += a2 * b4.x; acc[2][1] += a2 * b4.y; acc[2][2] += a2 * b4.z; acc[2][3] += a2 * b4.w;
            acc[3][0] += a3 * b4.x; acc[3][1] += a3 * b4.y; acc[3][2] += a3 * b4.z; acc[3][3] += a3 * b4.w;
        }
        __syncthreads();
    }
#pragma unroll
    for (int i = 0; i < 4; i++) {
        int row = bm + ty * 4 + i;
#pragma unroll
        for (int j = 0; j < 4; j++) {
            int col = bn + tx * 4 + j;
            C[(long)row * N + col] = acc[i][j] + bias[col];
        }
    }
}

// ---------------- fused token LN + FiLM + spatial mean ----------------
__global__ void tok_reduce_kernel(const float* __restrict__ tok, const float* __restrict__ tg,
                                  const float* __restrict__ tb, const float* __restrict__ film,
                                  float* __restrict__ h) {
    __shared__ float accs[8][DHID];
    int bt = blockIdx.x;
    int wid = threadIdx.x >> 5, lane = threadIdx.x & 31;
    float acc[16];
#pragma unroll
    for (int i = 0; i < 16; i++) acc[i] = 0.f;
    const float* gb = film + bt * (2 * DHID);
    for (int n = wid; n < NTOK; n += 8) {
        const float* row = tok + (long)(bt * NTOK + n) * DHID;
        float v[16]; float s = 0.f;
#pragma unroll
        for (int i = 0; i < 16; i++) { v[i] = row[i * 32 + lane]; s += v[i]; }
        s = warp_sum(s);
        float mu = s * (1.f / 512.f);
        float vs = 0.f;
#pragma unroll
        for (int i = 0; i < 16; i++) { float d = v[i] - mu; vs += d * d; }
        vs = warp_sum(vs);
        float rstd = rsqrtf(vs * (1.f / 512.f) + 1e-5f);
#pragma unroll
        for (int i = 0; i < 16; i++) {
            int d = i * 32 + lane;
            float ln = (v[i] - mu) * rstd * tg[d] + tb[d];
            acc[i] += (1.f + 0.5f * gb[d]) * ln + 0.5f * gb[DHID + d];
        }
    }
#pragma unroll
    for (int i = 0; i < 16; i++) accs[wid][i * 32 + lane] = acc[i];
    __syncthreads();
    for (int d = threadIdx.x; d < DHID; d += 256) {
        float s = 0.f;
#pragma unroll
        for (int w = 0; w < 8; w++) s += accs[w][d];
        h[bt * DHID + d] = s * (1.f / 64.f);
    }
}

// ---------------- LayerNorm -> fp16 out ----------------
__global__ void ln_h_kernel(const float* __restrict__ in, const float* __restrict__ g,
                            const float* __restrict__ b, __half* __restrict__ out) {
    __shared__ float sbuf[8];
    int tok = blockIdx.x, tid = threadIdx.x;
    const float* row = in + tok * DHID;
    float v0 = row[tid], v1 = row[tid + 256];
    float sum = block_sum_256(v0 + v1, sbuf);
    float mu = sum * (1.f / 512.f);
    float d0 = v0 - mu, d1 = v1 - mu;
    float vs = block_sum_256(d0 * d0 + d1 * d1, sbuf);
    float rstd = rsqrtf(vs * (1.f / 512.f) + 1e-5f);
    out[tok * DHID + tid]       = __float2half_rn(d0 * rstd * g[tid] + b[tid]);
    out[tok * DHID + tid + 256] = __float2half_rn(d1 * rstd * g[tid + 256] + b[tid + 256]);
}

// ---------------- attention per (b, head) ----------------
__global__ void attn_kernel(const float* __restrict__ kqv, __half* __restrict__ out) {
    __shared__ float q[32][64];
    __shared__ float k[32][65];
    __shared__ float v[32][64];
    __shared__ float s[32][33];
    int bh = blockIdx.x;
    int b = bh >> 3, h = bh & 7;
    int tid = threadIdx.x;
#pragma unroll
    for (int i = 0; i < 8; i++) {
        int e = tid + i * 256;
        int t = e >> 6, d = e & 63;
        const float* base = kqv + (long)(b * 32 + t) * 1536 + h * 64;
        float kk = base[d];
        float qq = base[512 + d];
        v[t][d] = base[1024 + d];
        int j = d & 31;
        float ang = (float)t * powf(10000.f, -(float)j * (1.f / 32.f));
        float sn, cs;
        sincosf(ang, &sn, &cs);
        if (d < 32) {
            float kp = base[d + 32], qp = base[512 + d + 32];
            k[t][d] = kk * cs - kp * sn;
            q[t][d] = qq * cs - qp * sn;
        } else {
            float kp = base[d - 32], qp = base[512 + d - 32];
            k[t][d] = kk * cs + kp * sn;
            q[t][d] = qq * cs + qp * sn;
        }
    }
    __syncthreads();
#pragma unroll
    for (int i = 0; i < 4; i++) {
        int e = tid + i * 256;
        int tq = e >> 5, tk = e & 31;
        if (tk <= tq) {
            float acc = 0.f;
#pragma unroll
            for (int dd = 0; dd < 64; dd++) acc += q[tq][dd] * k[tk][dd];
            s[tq][tk] = acc * 0.125f;
        }
    }
    __syncthreads();
    int wid = tid >> 5, lane = tid & 31;
    for (int r = wid; r < 32; r += 8) {
        float val = (lane <= r) ? s[r][lane] : -3.4e38f;
        float m = warp_max(val);
        float e = (lane <= r) ? expf(val - m) : 0.f;
        float sum = warp_sum(e);
        s[r][lane] = e / sum;
    }
    __syncthreads();
#pragma unroll
    for (int i = 0; i < 8; i++) {
        int e = tid + i * 256;
        int t = e >> 6, d = e & 63;
        float acc = 0.f;
#pragma unroll
        for (int kk2 = 0; kk2 < 32; kk2++) acc += s[t][kk2] * v[kk2][d];
        out[(long)(b * 32 + t) * DHID + h * 64 + d] = __float2half_rn(acc);
    }
}

// ---------------- head ----------------
__global__ void head_kernel(const float* __restrict__ hin, const float* __restrict__ g,
                            const float* __restrict__ b, const float* __restrict__ w,
                            const float* __restrict__ bias0, float* __restrict__ out) {
    __shared__ float sbuf[8];
    int tok = blockIdx.x, tid = threadIdx.x;
    const float* row = hin + tok * DHID;
    float v0 = row[tid], v1 = row[tid + 256];
    float sum = block_sum_256(v0 + v1, sbuf);
    float mu = sum * (1.f / 512.f);
    float d0 = v0 - mu, d1 = v1 - mu;
    float vs = block_sum_256(d0 * d0 + d1 * d1, sbuf);
    float rstd = rsqrtf(vs * (1.f / 512.f) + 1e-5f);
    float c = (d0 * rstd * g[tid] + b[tid]) * w[tid] +
              (d1 * rstd * g[tid + 256] + b[tid + 256]) * w[tid + 256];
    float tot = block_sum_256(c, sbuf);
    if (tid == 0) out[tok] = tot + bias0[0];
}

// ---------------- launch ----------------
extern "C" void kernel_launch(void* const* d_in, const int* in_sizes, int n_in,
                              void* d_out, int out_size) {
    const float* x       = (const float*)d_in[0];
    const float* z       = (const float*)d_in[1];
    const float* conv_w  = (const float*)d_in[2];
    const float* conv_b  = (const float*)d_in[3];
    const float* tok_g   = (const float*)d_in[4];
    const float* tok_b   = (const float*)d_in[5];
    const float* film_w  = (const float*)d_in[6];
    const float* film_b  = (const float*)d_in[7];
    const float* ln1_g   = (const float*)d_in[8];
    const float* ln1_b   = (const float*)d_in[9];
    const float* kqv_w   = (const float*)d_in[10];
    const float* kqv_b   = (const float*)d_in[11];
    const float* proj_w  = (const float*)d_in[12];
    const float* proj_b  = (const float*)d_in[13];
    const float* ln2_g   = (const float*)d_in[14];
    const float* ln2_b   = (const float*)d_in[15];
    const float* mlp_w1  = (const float*)d_in[16];
    const float* mlp_b1  = (const float*)d_in[17];
    const float* mlp_w2  = (const float*)d_in[18];
    const float* mlp_b2  = (const float*)d_in[19];
    const float* rs_attn = (const float*)d_in[20];
    const float* rs_mlp  = (const float*)d_in[21];
    const float* head_g  = (const float*)d_in[22];
    const float* head_b  = (const float*)d_in[23];
    const float* head_w  = (const float*)d_in[24];
    const float* head_bi = (const float*)d_in[25];
    float* out = (float*)d_out;

    __half *wT_h, *patch_h, *kqvw_h, *projw_h, *w1_h, *w2_h, *xln_h, *attn_h, *mlp_h;
    float *tok, *film, *h, *kqv;
    cudaGetSymbolAddress((void**)&wT_h, g_wT_h);
    cudaGetSymbolAddress((void**)&patch_h, g_patch_h);
    cudaGetSymbolAddress((void**)&kqvw_h, g_kqvw_h);
    cudaGetSymbolAddress((void**)&projw_h, g_projw_h);
    cudaGetSymbolAddress((void**)&w1_h, g_w1_h);
    cudaGetSymbolAddress((void**)&w2_h, g_w2_h);
    cudaGetSymbolAddress((void**)&xln_h, g_xln_h);
    cudaGetSymbolAddress((void**)&attn_h, g_attn_h);
    cudaGetSymbolAddress((void**)&mlp_h, g_mlp_h);
    cudaGetSymbolAddress((void**)&tok, g_tok);
    cudaGetSymbolAddress((void**)&film, g_film);
    cudaGetSymbolAddress((void**)&h, g_h);
    cudaGetSymbolAddress((void**)&kqv, g_kqv);

    // weight conversions
    transpose_wh_kernel<<<(DHID * KCONV + 255) / 256, 256>>>(conv_w, wT_h);
    {
        int n0 = LAYERS * DHID * 3 * DHID / 4;
        int n1 = LAYERS * DHID * DHID / 4;
        int n2 = LAYERS * DHID * 4 * DHID / 4;
        int n3 = n2;
        int tot = n0 + n1 + n2 + n3;
        f2h4_kernel<<<(tot + 255) / 256, 256>>>(
            (const float4*)kqv_w, (const float4*)proj_w, (const float4*)mlp_w1, (const float4*)mlp_w2,
            kqvw_h, projw_h, w1_h, w2_h, n0, n1, n2, n3);
    }
    // tokenizer
    im2col_kernel<<<(int)(((long)MCONV * KCONV + 255) / 256), 256>>>(x, patch_h);
    hgemm_kernel<128, 128, 4, 2, 2><<<dim3(DHID / 128, MCONV / 128), 256>>>(
        patch_h, wT_h, conv_b, tok, nullptr, MCONV, DHID, KCONV, 0, nullptr, nullptr);
    gemm_kernel<<<dim3(1024 / 64, BT / 64), 256>>>(z, film_w, film_b, film, BT, 1024, 32);
    tok_reduce_kernel<<<BT, 256>>>(tok, tok_g, tok_b, film, h);

    // transformer (BM=32 tiles, cp.async pipeline)
    for (int i = 0; i < LAYERS; i++) {
        ln_h_kernel<<<BT, 256>>>(h, ln1_g + i * DHID, ln1_b + i * DHID, xln_h);
        hgemm_kernel<32, 64, 2, 2, 1><<<dim3(1536 / 64, BT / 32), 128>>>(
            xln_h, kqvw_h + (long)i * DHID * 1536, kqv_b + i * 1536, kqv, nullptr,
            BT, 1536, DHID, 0, nullptr, nullptr);
        attn_kernel<<<BB * NHEAD, 256>>>(kqv, attn_h);
        hgemm_kernel<32, 64, 2, 2, 1><<<dim3(DHID / 64, BT / 32), 128>>>(
            attn_h, projw_h + (long)i * DHID * DHID, proj_b + i * DHID, h, nullptr,
            BT, DHID, DHID, 2, h, rs_attn + i);
        ln_h_kernel<<<BT, 256>>>(h, ln2_g + i * DHID, ln2_b + i * DHID, xln_h);
        hgemm_kernel<32, 64, 2, 2, 1><<<dim3(2048 / 64, BT / 32), 128>>>(
            xln_h, w1_h + (long)i * DHID * 2048, mlp_b1 + i * 2048, nullptr, mlp_h,
            BT, 2048, DHID, 1, nullptr, nullptr);
        hgemm_kernel<32, 64, 2, 2, 1><<<dim3(DHID / 64, BT / 32), 128>>>(
            mlp_h, w2_h + (long)i * 2048 * DHID, mlp_b2 + i * DHID, h, nullptr,
            BT, DHID, 2048, 2, h, rs_mlp + i);
    }
    head_kernel<<<BT, 256>>>(h, head_g, head_b, head_w, head_bi, out);
}

// round 8
// speedup vs baseline: 1.5122x; 1.0199x over previous
#include <cuda_runtime.h>
#include <cuda_fp16.h>
#include <cstdint>
#include <math.h>

// ---------------- problem constants ----------------
#define DHID   512
#define NHEAD  8
#define LAYERS 6
#define BB     16
#define TT     32
#define NTOK   64
#define KCONV  576
#define BT     512
#define MCONV  32768

// ---------------- device scratch ----------------
__device__ __half g_wT_h[KCONV * DHID];
__device__ __half g_patch_h[(size_t)MCONV * KCONV];
__device__ __half g_kqvw_h[LAYERS * DHID * 3 * DHID];
__device__ __half g_projw_h[LAYERS * DHID * DHID];
__device__ __half g_w1_h[LAYERS * DHID * 4 * DHID];
__device__ __half g_w2_h[LAYERS * 4 * DHID * DHID];
__device__ __half g_xln_h[BT * DHID];
__device__ __half g_attn_h[BT * DHID];
__device__ __half g_mlp_h[BT * 4 * DHID];
__device__ float  g_tok[(size_t)MCONV * DHID];
__device__ float  g_film[BT * 2 * DHID];
__device__ float  g_h[BT * DHID];
__device__ float  g_ropeS[TT * 32];
__device__ float  g_ropeC[TT * 32];

// ---------------- helpers ----------------
__device__ __forceinline__ float warp_sum(float v) {
#pragma unroll
    for (int o = 16; o; o >>= 1) v += __shfl_xor_sync(0xffffffffu, v, o);
    return v;
}
__device__ __forceinline__ float warp_max(float v) {
#pragma unroll
    for (int o = 16; o; o >>= 1) v = fmaxf(v, __shfl_xor_sync(0xffffffffu, v, o));
    return v;
}
__device__ __forceinline__ float block_sum_256(float v, float* sbuf) {
    int lane = threadIdx.x & 31, wid = threadIdx.x >> 5;
    v = warp_sum(v);
    if (lane == 0) sbuf[wid] = v;
    __syncthreads();
    float r = sbuf[0];
#pragma unroll
    for (int w = 1; w < 8; w++) r += sbuf[w];
    __syncthreads();
    return r;
}
__device__ __forceinline__ unsigned smem_u32(const void* p) {
    return (unsigned)__cvta_generic_to_shared(p);
}
__device__ __forceinline__ void cp_async16(unsigned dst, const void* src) {
    asm volatile("cp.async.cg.shared.global [%0], [%1], 16;" :: "r"(dst), "l"(src));
}
__device__ __forceinline__ void cp_commit() {
    asm volatile("cp.async.commit_group;");
}
template<int N>
__device__ __forceinline__ void cp_wait() {
    asm volatile("cp.async.wait_group %0;" :: "n"(N));
}

// ---------------- rope table ----------------
__global__ void rope_kernel(float* rs, float* rc) {
    int i = threadIdx.x;      // 1024
    int t = i >> 5, j = i & 31;
    float ang = (float)t * powf(10000.f, -(float)j * (1.f / 32.f));
    float sn, cs; sincosf(ang, &sn, &cs);
    rs[i] = sn; rc[i] = cs;
}

// ---------------- merged weight conversion ----------------
__global__ void f2h4_kernel(const float4* __restrict__ s0, const float4* __restrict__ s1,
                            const float4* __restrict__ s2, const float4* __restrict__ s3,
                            __half* __restrict__ d0, __half* __restrict__ d1,
                            __half* __restrict__ d2, __half* __restrict__ d3,
                            int n0, int n1, int n2, int n3) {
    int i = blockIdx.x * 256 + threadIdx.x;
    const float4* s; __half* d; int j = i;
    if (j < n0) { s = s0; d = d0; }
    else { j -= n0;
        if (j < n1) { s = s1; d = d1; }
        else { j -= n1;
            if (j < n2) { s = s2; d = d2; }
            else { j -= n2; if (j >= n3) return; s = s3; d = d3; }
        }
    }
    float4 v = s[j];
    __half2* o = (__half2*)(d + (size_t)j * 4);
    o[0] = __floats2half2_rn(v.x, v.y);
    o[1] = __floats2half2_rn(v.z, v.w);
}
__global__ void transpose_wh_kernel(const float* __restrict__ w, __half* __restrict__ wT) {
    int idx = blockIdx.x * 256 + threadIdx.x;
    if (idx >= DHID * KCONV) return;
    int d = idx / KCONV, k = idx % KCONV;
    wT[k * DHID + d] = __float2half_rn(w[idx]);
}

// ---------------- im2col (causal time pad 2) -> fp16 ----------------
__global__ void im2col_kernel(const float* __restrict__ x, __half* __restrict__ p) {
    long idx = (long)blockIdx.x * 256 + threadIdx.x;
    if (idx >= (long)MCONV * KCONV) return;
    int kcol = (int)(idx % KCONV);
    long row = idx / KCONV;
    int n  = (int)(row & 63);
    int bt = (int)(row >> 6);
    int t  = bt & 31;
    int b  = bt >> 5;
    int hn = n >> 3, wn = n & 7;
    int pw = kcol & 7;
    int ph = (kcol >> 3) & 7;
    int kt = (kcol >> 6) % 3;
    int c  = kcol / 192;
    int tt = t + kt - 2;
    float v = 0.f;
    if (tt >= 0)
        v = x[((((long)(b * 32 + tt) * 3 + c) * 64) + hn * 8 + ph) * 64 + wn * 8 + pw];
    p[idx] = __float2half_rn(v);
}

// ---------------- tensor-core GEMM, 3-stage cp.async pipeline ----------------
#define APAD 8
#define BPAD 8
#define STG  3

template<int BM, int BN, int WM, int WN, int MI>
__global__ void hgemm_kernel(const __half* __restrict__ A, const __half* __restrict__ B,
                             const float* __restrict__ bias,
                             float* __restrict__ Cf, __half* __restrict__ Ch,
                             int M, int N, int K, int epi,
                             const float* __restrict__ res, const float* __restrict__ scale) {
    constexpr int NT = WM * WN * 32;
    constexpr int A_IT = BM * 4 / NT;
    constexpr int B_IT = 4 * BN / NT;
    constexpr int WTN = BN / WN;
    constexpr int NJ = WTN / 8;
    constexpr int NJ2 = WTN / 16;
    __shared__ __half As[STG][BM][32 + APAD];
    __shared__ __half Bs[STG][32][BN + BPAD];

    int tid = threadIdx.x;
    int lane = tid & 31;
    int warp = tid >> 5;
    int wm = warp / WN, wn = warp % WN;
    int bm = blockIdx.y * BM, bn = blockIdx.x * BN;
    int KT = K >> 5;

    int ar[A_IT], aq[A_IT], br[B_IT], bq[B_IT];
#pragma unroll
    for (int i = 0; i < A_IT; i++) { int u = tid + i * NT; ar[i] = u >> 2; aq[i] = u & 3; }
#pragma unroll
    for (int i = 0; i < B_IT; i++) { int v = tid + i * NT; br[i] = v / (BN / 8); bq[i] = v % (BN / 8); }

#pragma unroll
    for (int s = 0; s < STG - 1; s++) {
        int k0 = s * 32;
        if (s < KT) {
#pragma unroll
            for (int i = 0; i < A_IT; i++)
                cp_async16(smem_u32(&As[s][ar[i]][aq[i] * 8]),
                           A + (long)(bm + ar[i]) * K + k0 + aq[i] * 8);
#pragma unroll
            for (int i = 0; i < B_IT; i++)
                cp_async16(smem_u32(&Bs[s][br[i]][bq[i] * 8]),
                           B + (long)(k0 + br[i]) * N + bn + bq[i] * 8);
        }
        cp_commit();
    }

    float c[MI][NJ][4];
#pragma unroll
    for (int i = 0; i < MI; i++)
#pragma unroll
        for (int j = 0; j < NJ; j++)
#pragma unroll
            for (int e = 0; e < 4; e++) c[i][j][e] = 0.f;

    for (int kt = 0; kt < KT; kt++) {
        cp_wait<STG - 2>();
        __syncthreads();
        int buf = kt % STG;
#pragma unroll
        for (int ks = 0; ks < 32; ks += 16) {
            unsigned a[MI][4], bf[NJ2][4];
#pragma unroll
            for (int i = 0; i < MI; i++) {
                unsigned addr = smem_u32(&As[buf][wm * MI * 16 + i * 16 + (lane & 15)][ks + (lane >> 4) * 8]);
                asm volatile("ldmatrix.sync.aligned.m8n8.x4.shared.b16 {%0,%1,%2,%3}, [%4];"
                             : "=r"(a[i][0]), "=r"(a[i][1]), "=r"(a[i][2]), "=r"(a[i][3]) : "r"(addr));
            }
#pragma unroll
            for (int j2 = 0; j2 < NJ2; j2++) {
                unsigned addr = smem_u32(&Bs[buf][ks + (lane & 7) + ((lane >> 3) & 1) * 8]
                                             [wn * WTN + j2 * 16 + (lane >> 4) * 8]);
                asm volatile("ldmatrix.sync.aligned.m8n8.x4.trans.shared.b16 {%0,%1,%2,%3}, [%4];"
                             : "=r"(bf[j2][0]), "=r"(bf[j2][1]), "=r"(bf[j2][2]), "=r"(bf[j2][3]) : "r"(addr));
            }
#pragma unroll
            for (int i = 0; i < MI; i++)
#pragma unroll
                for (int j = 0; j < NJ; j++) {
                    unsigned b0 = bf[j >> 1][(j & 1) * 2], b1 = bf[j >> 1][(j & 1) * 2 + 1];
                    asm volatile(
                        "mma.sync.aligned.m16n8k16.row.col.f32.f16.f16.f32 "
                        "{%0,%1,%2,%3}, {%4,%5,%6,%7}, {%8,%9}, {%0,%1,%2,%3};"
                        : "+f"(c[i][j][0]), "+f"(c[i][j][1]), "+f"(c[i][j][2]), "+f"(c[i][j][3])
                        : "r"(a[i][0]), "r"(a[i][1]), "r"(a[i][2]), "r"(a[i][3]), "r"(b0), "r"(b1));
                }
        }
        int kn = kt + STG - 1;
        if (kn < KT) {
            int nb = kn % STG;
            int k0 = kn * 32;
#pragma unroll
            for (int i = 0; i < A_IT; i++)
                cp_async16(smem_u32(&As[nb][ar[i]][aq[i] * 8]),
                           A + (long)(bm + ar[i]) * K + k0 + aq[i] * 8);
#pragma unroll
            for (int i = 0; i < B_IT; i++)
                cp_async16(smem_u32(&Bs[nb][br[i]][bq[i] * 8]),
                           B + (long)(k0 + br[i]) * N + bn + bq[i] * 8);
        }
        cp_commit();
    }

    float sc = (epi == 2) ? scale[0] : 0.f;
#pragma unroll
    for (int i = 0; i < MI; i++)
#pragma unroll
        for (int j = 0; j < NJ; j++) {
            int r0 = bm + wm * MI * 16 + i * 16 + (lane >> 2);
            int c0 = bn + wn * WTN + j * 8 + (lane & 3) * 2;
#pragma unroll
            for (int half_ = 0; half_ < 2; half_++) {
                int rr = r0 + half_ * 8;
                float v0 = c[i][j][half_ * 2 + 0] + bias[c0];
                float v1 = c[i][j][half_ * 2 + 1] + bias[c0 + 1];
                long off = (long)rr * N + c0;
                if (epi == 0) {
                    *(float2*)&Cf[off] = make_float2(v0, v1);
                } else if (epi == 1) {
                    float g0 = 0.5f * v0 * (1.f + erff(v0 * 0.70710678118654752f));
                    float g1 = 0.5f * v1 * (1.f + erff(v1 * 0.70710678118654752f));
                    *(__half2*)&Ch[off] = __floats2half2_rn(g0, g1);
                } else {
                    float2 rv = *(const float2*)&res[off];
                    *(float2*)&Cf[off] = make_float2(rv.x + sc * v0, rv.y + sc * v1);
                }
            }
        }
}

// ---------------- fused LN1 + kqv GEMM + RoPE + attention ----------------
// One block per (batch, head). 256 threads = 8 warps (wm 0..1, wn 0..3).
#define XSTR 520
#define BSTRF 200
#define SMEMF 79872

__global__ void kqvattn_kernel(const float* __restrict__ H, const float* __restrict__ g,
                               const float* __restrict__ bvec, const __half* __restrict__ W,
                               const float* __restrict__ bias,
                               const float* __restrict__ ropeS, const float* __restrict__ ropeC,
                               __half* __restrict__ out) {
    extern __shared__ char smf[];
    __half* xs = (__half*)smf;
    __half* Bsm = (__half*)(smf + 33280);
    float* kk = (float*)(smf + 33280);
    float* qq = kk + 32 * 65;
    float* vv = qq + 32 * 64;
    float* ss = vv + 32 * 64;
    float* rs = (float*)(smf + 71680);
    float* rc = rs + 32 * 32;

    int tid = threadIdx.x, lane = tid & 31, warp = tid >> 5;
    int bh = blockIdx.x, b = bh >> 3, h = bh & 7;
    int wm = warp >> 2, wn = warp & 3;

    for (int i = tid; i < 1024; i += 256) { rs[i] = ropeS[i]; rc[i] = ropeC[i]; }

    int brr[3], bqq[3];
#pragma unroll
    for (int i = 0; i < 3; i++) { int v = tid + i * 256; brr[i] = v / 24; bqq[i] = v % 24; }
    const __half* Wbase = W + h * 64;
#pragma unroll
    for (int s = 0; s < 2; s++) {
        int k0 = s * 32;
#pragma unroll
        for (int i = 0; i < 3; i++) {
            cp_async16(smem_u32(&Bsm[(s * 32 + brr[i]) * BSTRF + bqq[i] * 8]),
                       Wbase + (long)(k0 + brr[i]) * 1536 + (bqq[i] >> 3) * 512 + (bqq[i] & 7) * 8);
        }
        cp_commit();
    }

    for (int ri = 0; ri < 4; ri++) {
        int r = warp * 4 + ri;
        const float* row = H + (long)(b * 32 + r) * DHID;
        float v[16]; float s = 0.f;
#pragma unroll
        for (int i = 0; i < 16; i++) { v[i] = row[lane + 32 * i]; s += v[i]; }
        s = warp_sum(s);
        float mu = s * (1.f / 512.f);
        float vs = 0.f;
#pragma unroll
        for (int i = 0; i < 16; i++) { float d = v[i] - mu; vs += d * d; }
        vs = warp_sum(vs);
        float rstd = rsqrtf(vs * (1.f / 512.f) + 1e-5f);
#pragma unroll
        for (int i = 0; i < 16; i++) {
            int d = lane + 32 * i;
            xs[r * XSTR + d] = __float2half_rn((v[i] - mu) * rstd * g[d] + bvec[d]);
        }
    }

    float c[6][4];
#pragma unroll
    for (int j = 0; j < 6; j++)
#pragma unroll
        for (int e = 0; e < 4; e++) c[j][e] = 0.f;

    for (int kt = 0; kt < 16; kt++) {
        cp_wait<1>();
        __syncthreads();
        int buf = kt % 3;
#pragma unroll
        for (int ks = 0; ks < 32; ks += 16) {
            unsigned a[4], bf[3][4];
            unsigned addr = smem_u32(&xs[(wm * 16 + (lane & 15)) * XSTR + kt * 32 + ks + (lane >> 4) * 8]);
            asm volatile("ldmatrix.sync.aligned.m8n8.x4.shared.b16 {%0,%1,%2,%3}, [%4];"
                         : "=r"(a[0]), "=r"(a[1]), "=r"(a[2]), "=r"(a[3]) : "r"(addr));
#pragma unroll
            for (int j2 = 0; j2 < 3; j2++) {
                unsigned baddr = smem_u32(&Bsm[(buf * 32 + ks + (lane & 7) + ((lane >> 3) & 1) * 8) * BSTRF
                                               + wn * 48 + j2 * 16 + (lane >> 4) * 8]);
                asm volatile("ldmatrix.sync.aligned.m8n8.x4.trans.shared.b16 {%0,%1,%2,%3}, [%4];"
                             : "=r"(bf[j2][0]), "=r"(bf[j2][1]), "=r"(bf[j2][2]), "=r"(bf[j2][3]) : "r"(baddr));
            }
#pragma unroll
            for (int j = 0; j < 6; j++) {
                unsigned b0 = bf[j >> 1][(j & 1) * 2], b1 = bf[j >> 1][(j & 1) * 2 + 1];
                asm volatile(
                    "mma.sync.aligned.m16n8k16.row.col.f32.f16.f16.f32 "
                    "{%0,%1,%2,%3}, {%4,%5,%6,%7}, {%8,%9}, {%0,%1,%2,%3};"
                    : "+f"(c[j][0]), "+f"(c[j][1]), "+f"(c[j][2]), "+f"(c[j][3])
                    : "r"(a[0]), "r"(a[1]), "r"(a[2]), "r"(a[3]), "r"(b0), "r"(b1));
            }
        }
        int kn = kt + 2;
        if (kn < 16) {
            int nb = kn % 3;
            int k0 = kn * 32;
#pragma unroll
            for (int i = 0; i < 3; i++) {
                cp_async16(smem_u32(&Bsm[(nb * 32 + brr[i]) * BSTRF + bqq[i] * 8]),
                           Wbase + (long)(k0 + brr[i]) * 1536 + (bqq[i] >> 3) * 512 + (bqq[i] & 7) * 8);
            }
        }
        cp_commit();
    }
    __syncthreads();

#pragma unroll
    for (int j = 0; j < 6; j++) {
        int c0 = wn * 48 + j * 8 + (lane & 3) * 2;
        int seg = c0 >> 6, d = c0 & 63;
        float b0 = bias[seg * 512 + h * 64 + d];
        float b1 = bias[seg * 512 + h * 64 + d + 1];
#pragma unroll
        for (int half_ = 0; half_ < 2; half_++) {
            int r = wm * 16 + (lane >> 2) + half_ * 8;
            float v0 = c[j][half_ * 2 + 0] + b0;
            float v1 = c[j][half_ * 2 + 1] + b1;
            if (seg == 0)      { kk[r * 65 + d] = v0; kk[r * 65 + d + 1] = v1; }
            else if (seg == 1) { qq[r * 64 + d] = v0; qq[r * 64 + d + 1] = v1; }
            else               { vv[r * 64 + d] = v0; vv[r * 64 + d + 1] = v1; }
        }
    }
    __syncthreads();

#pragma unroll
    for (int i = 0; i < 4; i++) {
        int e = tid + i * 256;
        int t = e >> 5, j = e & 31;
        float sn = rs[t * 32 + j], cs = rc[t * 32 + j];
        float q1 = qq[t * 64 + j], q2 = qq[t * 64 + j + 32];
        qq[t * 64 + j]      = q1 * cs - q2 * sn;
        qq[t * 64 + j + 32] = q2 * cs + q1 * sn;
        float k1 = kk[t * 65 + j], k2 = kk[t * 65 + j + 32];
        kk[t * 65 + j]      = k1 * cs - k2 * sn;
        kk[t * 65 + j + 32] = k2 * cs + k1 * sn;
    }
    __syncthreads();

#pragma unroll
    for (int i = 0; i < 4; i++) {
        int e = tid + i * 256;
        int tq = e >> 5, tk = e & 31;
        if (tk <= tq) {
            float acc = 0.f;
#pragma unroll
            for (int dd = 0; dd < 64; dd++) acc += qq[tq * 64 + dd] * kk[tk * 65 + dd];
            ss[tq * 33 + tk] = acc * 0.125f;
        }
    }
    __syncthreads();
    for (int r = warp; r < 32; r += 8) {
        float val = (lane <= r) ? ss[r * 33 + lane] : -3.4e38f;
        float m = warp_max(val);
        float e = (lane <= r) ? expf(val - m) : 0.f;
        float sum = warp_sum(e);
        ss[r * 33 + lane] = e / sum;
    }
    __syncthreads();
#pragma unroll
    for (int i = 0; i < 8; i++) {
        int e = tid + i * 256;
        int t = e >> 6, d = e & 63;
        float acc = 0.f;
#pragma unroll
        for (int kk2 = 0; kk2 < 32; kk2++) acc += ss[t * 33 + kk2] * vv[kk2 * 64 + d];
        out[(long)(b * 32 + t) * DHID + h * 64 + d] = __float2half_rn(acc);
    }
}

// ---------------- small fp32 GEMM (film only) ----------------
__global__ void gemm_kernel(const float* __restrict__ A, const float* __restrict__ Bm,
                            const float* __restrict__ bias, float* C,
                            int M, int N, int K) {
    __shared__ float As[16][65];
    __shared__ float Bs[16][64];
    int bm = blockIdx.y * 64, bn = blockIdx.x * 64;
    int tid = threadIdx.x;
    int tx = tid & 15, ty = tid >> 4;
    float acc[4][4];
#pragma unroll
    for (int i = 0; i < 4; i++)
#pragma unroll
        for (int j = 0; j < 4; j++) acc[i][j] = 0.f;
    const float* Ab = A + (long)bm * K;
    for (int k0 = 0; k0 < K; k0 += 16) {
        {
            int col = tid & 15, row = tid >> 4;
#pragma unroll
            for (int r = 0; r < 4; r++)
                As[col][row + r * 16] = Ab[(long)(row + r * 16) * K + k0 + col];
        }
        {
            int col = tid & 63, row = tid >> 6;
#pragma unroll
            for (int r = 0; r < 4; r++)
                Bs[row + r * 4][col] = Bm[(long)(k0 + row + r * 4) * N + bn + col];
        }
        __syncthreads();
#pragma unroll
        for (int kk = 0; kk < 16; kk++) {
            float a0 = As[kk][ty * 4 + 0], a1 = As[kk][ty * 4 + 1];
            float a2 = As[kk][ty * 4 + 2], a3 = As[kk][ty * 4 + 3];
            float4 b4 = *(const float4*)&Bs[kk][tx * 4];
            acc[0][0] += a0 * b4.x; acc[0][1] += a0 * b4.y; acc[0][2] += a0 * b4.z; acc[0][3] += a0 * b4.w;
            acc[1][0] += a1 * b4.x; acc[1][1] += a1 * b4.y; acc[1][2] += a1 * b4.z; acc[1][3] += a1 * b4.w;
            acc[2][0] += a2 * b4.x; acc[2][1] += a2 * b4.y; acc[2][2] += a2 * b4.z; acc[2][3] += a2 * b4.w;
            acc[3][0] += a3 * b4.x; acc[3][1] += a3 * b4.y; acc[3][2] += a3 * b4.z; acc[3][3] += a3 * b4.w;
        }
        __syncthreads();
    }
#pragma unroll
    for (int i = 0; i < 4; i++) {
        int row = bm + ty * 4 + i;
#pragma unroll
        for (int j = 0; j < 4; j++) {
            int col = bn + tx * 4 + j;
            C[(long)row * N + col] = acc[i][j] + bias[col];
        }
    }
}

// ---------------- fused token LN + FiLM + spatial mean ----------------
__global__ void tok_reduce_kernel(const float* __restrict__ tok, const float* __restrict__ tg,
                                  const float* __restrict__ tb, const float* __restrict__ film,
                                  float* __restrict__ h) {
    __shared__ float accs[8][DHID];
    int bt = blockIdx.x;
    int wid = threadIdx.x >> 5, lane = threadIdx.x & 31;
    float acc[16];
#pragma unroll
    for (int i = 0; i < 16; i++) acc[i] = 0.f;
    const float* gb = film + bt * (2 * DHID);
    for (int n = wid; n < NTOK; n += 8) {
        const float* row = tok + (long)(bt * NTOK + n) * DHID;
        float v[16]; float s = 0.f;
#pragma unroll
        for (int i = 0; i < 16; i++) { v[i] = row[i * 32 + lane]; s += v[i]; }
        s = warp_sum(s);
        float mu = s * (1.f / 512.f);
        float vs = 0.f;
#pragma unroll
        for (int i = 0; i < 16; i++) { float d = v[i] - mu; vs += d * d; }
        vs = warp_sum(vs);
        float rstd = rsqrtf(vs * (1.f / 512.f) + 1e-5f);
#pragma unroll
        for (int i = 0; i < 16; i++) {
            int d = i * 32 + lane;
            float ln = (v[i] - mu) * rstd * tg[d] + tb[d];
            acc[i] += (1.f + 0.5f * gb[d]) * ln + 0.5f * gb[DHID + d];
        }
    }
#pragma unroll
    for (int i = 0; i < 16; i++) accs[wid][i * 32 + lane] = acc[i];
    __syncthreads();
    for (int d = threadIdx.x; d < DHID; d += 256) {
        float s = 0.f;
#pragma unroll
        for (int w = 0; w < 8; w++) s += accs[w][d];
        h[bt * DHID + d] = s * (1.f / 64.f);
    }
}

// ---------------- LayerNorm -> fp16 out ----------------
__global__ void ln_h_kernel(const float* __restrict__ in, const float* __restrict__ g,
                            const float* __restrict__ b, __half* __restrict__ out) {
    __shared__ float sbuf[8];
    int tok = blockIdx.x, tid = threadIdx.x;
    const float* row = in + tok * DHID;
    float v0 = row[tid], v1 = row[tid + 256];
    float sum = block_sum_256(v0 + v1, sbuf);
    float mu = sum * (1.f / 512.f);
    float d0 = v0 - mu, d1 = v1 - mu;
    float vs = block_sum_256(d0 * d0 + d1 * d1, sbuf);
    float rstd = rsqrtf(vs * (1.f / 512.f) + 1e-5f);
    out[tok * DHID + tid]       = __float2half_rn(d0 * rstd * g[tid] + b[tid]);
    out[tok * DHID + tid + 256] = __float2half_rn(d1 * rstd * g[tid + 256] + b[tid + 256]);
}

// ---------------- head ----------------
__global__ void head_kernel(const float* __restrict__ hin, const float* __restrict__ g,
                            const float* __restrict__ b, const float* __restrict__ w,
                            const float* __restrict__ bias0, float* __restrict__ out) {
    __shared__ float sbuf[8];
    int tok = blockIdx.x, tid = threadIdx.x;
    const float* row = hin + tok * DHID;
    float v0 = row[tid], v1 = row[tid + 256];
    float sum = block_sum_256(v0 + v1, sbuf);
    float mu = sum * (1.f / 512.f);
    float d0 = v0 - mu, d1 = v1 - mu;
    float vs = block_sum_256(d0 * d0 + d1 * d1, sbuf);
    float rstd = rsqrtf(vs * (1.f / 512.f) + 1e-5f);
    float c = (d0 * rstd * g[tid] + b[tid]) * w[tid] +
              (d1 * rstd * g[tid + 256] + b[tid + 256]) * w[tid + 256];
    float tot = block_sum_256(c, sbuf);
    if (tid == 0) out[tok] = tot + bias0[0];
}

// ---------------- launch ----------------
extern "C" void kernel_launch(void* const* d_in, const int* in_sizes, int n_in,
                              void* d_out, int out_size) {
    const float* x       = (const float*)d_in[0];
    const float* z       = (const float*)d_in[1];
    const float* conv_w  = (const float*)d_in[2];
    const float* conv_b  = (const float*)d_in[3];
    const float* tok_g   = (const float*)d_in[4];
    const float* tok_b   = (const float*)d_in[5];
    const float* film_w  = (const float*)d_in[6];
    const float* film_b  = (const float*)d_in[7];
    const float* ln1_g   = (const float*)d_in[8];
    const float* ln1_b   = (const float*)d_in[9];
    const float* kqv_w   = (const float*)d_in[10];
    const float* kqv_b   = (const float*)d_in[11];
    const float* proj_w  = (const float*)d_in[12];
    const float* proj_b  = (const float*)d_in[13];
    const float* ln2_g   = (const float*)d_in[14];
    const float* ln2_b   = (const float*)d_in[15];
    const float* mlp_w1  = (const float*)d_in[16];
    const float* mlp_b1  = (const float*)d_in[17];
    const float* mlp_w2  = (const float*)d_in[18];
    const float* mlp_b2  = (const float*)d_in[19];
    const float* rs_attn = (const float*)d_in[20];
    const float* rs_mlp  = (const float*)d_in[21];
    const float* head_g  = (const float*)d_in[22];
    const float* head_b  = (const float*)d_in[23];
    const float* head_w  = (const float*)d_in[24];
    const float* head_bi = (const float*)d_in[25];
    float* out = (float*)d_out;

    __half *wT_h, *patch_h, *kqvw_h, *projw_h, *w1_h, *w2_h, *xln_h, *attn_h, *mlp_h;
    float *tok, *film, *h, *ropeS, *ropeC;
    cudaGetSymbolAddress((void**)&wT_h, g_wT_h);
    cudaGetSymbolAddress((void**)&patch_h, g_patch_h);
    cudaGetSymbolAddress((void**)&kqvw_h, g_kqvw_h);
    cudaGetSymbolAddress((void**)&projw_h, g_projw_h);
    cudaGetSymbolAddress((void**)&w1_h, g_w1_h);
    cudaGetSymbolAddress((void**)&w2_h, g_w2_h);
    cudaGetSymbolAddress((void**)&xln_h, g_xln_h);
    cudaGetSymbolAddress((void**)&attn_h, g_attn_h);
    cudaGetSymbolAddress((void**)&mlp_h, g_mlp_h);
    cudaGetSymbolAddress((void**)&tok, g_tok);
    cudaGetSymbolAddress((void**)&film, g_film);
    cudaGetSymbolAddress((void**)&h, g_h);
    cudaGetSymbolAddress((void**)&ropeS, g_ropeS);
    cudaGetSymbolAddress((void**)&ropeC, g_ropeC);

    cudaFuncSetAttribute(kqvattn_kernel, cudaFuncAttributeMaxDynamicSharedMemorySize, SMEMF);

    // setup: weights, rope
    transpose_wh_kernel<<<(DHID * KCONV + 255) / 256, 256>>>(conv_w, wT_h);
    rope_kernel<<<1, 1024>>>(ropeS, ropeC);
    {
        int n0 = LAYERS * DHID * 3 * DHID / 4;
        int n1 = LAYERS * DHID * DHID / 4;
        int n2 = LAYERS * DHID * 4 * DHID / 4;
        int n3 = n2;
        int tot = n0 + n1 + n2 + n3;
        f2h4_kernel<<<(tot + 255) / 256, 256>>>(
            (const float4*)kqv_w, (const float4*)proj_w, (const float4*)mlp_w1, (const float4*)mlp_w2,
            kqvw_h, projw_h, w1_h, w2_h, n0, n1, n2, n3);
    }
    // tokenizer
    im2col_kernel<<<(int)(((long)MCONV * KCONV + 255) / 256), 256>>>(x, patch_h);
    hgemm_kernel<128, 128, 4, 2, 2><<<dim3(DHID / 128, MCONV / 128), 256>>>(
        patch_h, wT_h, conv_b, tok, nullptr, MCONV, DHID, KCONV, 0, nullptr, nullptr);
    gemm_kernel<<<dim3(1024 / 64, BT / 64), 256>>>(z, film_w, film_b, film, BT, 1024, 32);
    tok_reduce_kernel<<<BT, 256>>>(tok, tok_g, tok_b, film, h);

    // transformer
    for (int i = 0; i < LAYERS; i++) {
        kqvattn_kernel<<<BB * NHEAD, 256, SMEMF>>>(
            h, ln1_g + i * DHID, ln1_b + i * DHID, kqvw_h + (long)i * DHID * 1536,
            kqv_b + i * 1536, ropeS, ropeC, attn_h);
        hgemm_kernel<32, 64, 2, 2, 1><<<dim3(DHID / 64, BT / 32), 128>>>(
            attn_h, projw_h + (long)i * DHID * DHID, proj_b + i * DHID, h, nullptr,
            BT, DHID, DHID, 2, h, rs_attn + i);
        ln_h_kernel<<<BT, 256>>>(h, ln2_g + i * DHID, ln2_b + i * DHID, xln_h);
        hgemm_kernel<32, 64, 2, 2, 1><<<dim3(2048 / 64, BT / 32), 128>>>(
            xln_h, w1_h + (long)i * DHID * 2048, mlp_b1 + i * 2048, nullptr, mlp_h,
            BT, 2048, DHID, 1, nullptr, nullptr);
        hgemm_kernel<32, 64, 2, 2, 1><<<dim3(DHID / 64, BT / 32), 128>>>(
            mlp_h, w2_h + (long)i * 2048 * DHID, mlp_b2 + i * DHID, h, nullptr,
            BT, DHID, 2048, 2, h, rs_mlp + i);
    }
    head_kernel<<<BT, 256>>>(h, head_g, head_b, head_w, head_bi, out);
}

// round 9
// speedup vs baseline: 1.5533x; 1.0272x over previous
#include <cuda_runtime.h>
#include <cuda_fp16.h>
#include <cstdint>
#include <math.h>

// ---------------- problem constants ----------------
#define DHID   512
#define NHEAD  8
#define LAYERS 6
#define BB     16
#define TT     32
#define NTOK   64
#define KCONV  576
#define BT     512
#define MCONV  32768

// ---------------- device scratch ----------------
__device__ __half g_wT_h[KCONV * DHID];
__device__ __half g_xh[BB * TT * 3 * 64 * 64];      // x in fp16
__device__ __half g_kqvw_h[LAYERS * DHID * 3 * DHID];
__device__ __half g_projw_h[LAYERS * DHID * DHID];
__device__ __half g_w1_h[LAYERS * DHID * 4 * DHID];
__device__ __half g_w2_h[LAYERS * 4 * DHID * DHID];
__device__ __half g_xln_h[BT * DHID];
__device__ __half g_attn_h[BT * DHID];
__device__ __half g_mlp_h[BT * 4 * DHID];
__device__ float  g_tok[(size_t)MCONV * DHID];
__device__ float  g_film[BT * 2 * DHID];
__device__ float  g_h[BT * DHID];
__device__ float  g_ropeS[TT * 32];
__device__ float  g_ropeC[TT * 32];

// ---------------- helpers ----------------
__device__ __forceinline__ float warp_sum(float v) {
#pragma unroll
    for (int o = 16; o; o >>= 1) v += __shfl_xor_sync(0xffffffffu, v, o);
    return v;
}
__device__ __forceinline__ float warp_max(float v) {
#pragma unroll
    for (int o = 16; o; o >>= 1) v = fmaxf(v, __shfl_xor_sync(0xffffffffu, v, o));
    return v;
}
__device__ __forceinline__ float block_sum_256(float v, float* sbuf) {
    int lane = threadIdx.x & 31, wid = threadIdx.x >> 5;
    v = warp_sum(v);
    if (lane == 0) sbuf[wid] = v;
    __syncthreads();
    float r = sbuf[0];
#pragma unroll
    for (int w = 1; w < 8; w++) r += sbuf[w];
    __syncthreads();
    return r;
}
__device__ __forceinline__ unsigned smem_u32(const void* p) {
    return (unsigned)__cvta_generic_to_shared(p);
}
__device__ __forceinline__ void cp_async16(unsigned dst, const void* src) {
    asm volatile("cp.async.cg.shared.global [%0], [%1], 16;" :: "r"(dst), "l"(src));
}
__device__ __forceinline__ void cp_async16z(unsigned dst, const void* src, int srcsize) {
    asm volatile("cp.async.cg.shared.global [%0], [%1], 16, %2;" :: "r"(dst), "l"(src), "r"(srcsize));
}
__device__ __forceinline__ void cp_commit() {
    asm volatile("cp.async.commit_group;");
}
template<int N>
__device__ __forceinline__ void cp_wait() {
    asm volatile("cp.async.wait_group %0;" :: "n"(N));
}

// ---------------- rope table ----------------
__global__ void rope_kernel(float* rs, float* rc) {
    int i = threadIdx.x;      // 1024
    int t = i >> 5, j = i & 31;
    float ang = (float)t * powf(10000.f, -(float)j * (1.f / 32.f));
    float sn, cs; sincosf(ang, &sn, &cs);
    rs[i] = sn; rc[i] = cs;
}

// ---------------- conversions ----------------
__global__ void f2h_kernel(const float4* __restrict__ s, __half* __restrict__ d, int n4) {
    int i = blockIdx.x * 256 + threadIdx.x;
    if (i >= n4) return;
    float4 v = s[i];
    __half2* o = (__half2*)(d + (size_t)i * 4);
    o[0] = __floats2half2_rn(v.x, v.y);
    o[1] = __floats2half2_rn(v.z, v.w);
}
__global__ void f2h4_kernel(const float4* __restrict__ s0, const float4* __restrict__ s1,
                            const float4* __restrict__ s2, const float4* __restrict__ s3,
                            __half* __restrict__ d0, __half* __restrict__ d1,
                            __half* __restrict__ d2, __half* __restrict__ d3,
                            int n0, int n1, int n2, int n3) {
    int i = blockIdx.x * 256 + threadIdx.x;
    const float4* s; __half* d; int j = i;
    if (j < n0) { s = s0; d = d0; }
    else { j -= n0;
        if (j < n1) { s = s1; d = d1; }
        else { j -= n1;
            if (j < n2) { s = s2; d = d2; }
            else { j -= n2; if (j >= n3) return; s = s3; d = d3; }
        }
    }
    float4 v = s[j];
    __half2* o = (__half2*)(d + (size_t)j * 4);
    o[0] = __floats2half2_rn(v.x, v.y);
    o[1] = __floats2half2_rn(v.z, v.w);
}
__global__ void transpose_wh_kernel(const float* __restrict__ w, __half* __restrict__ wT) {
    int idx = blockIdx.x * 256 + threadIdx.x;
    if (idx >= DHID * KCONV) return;
    int d = idx / KCONV, k = idx % KCONV;
    wT[k * DHID + d] = __float2half_rn(w[idx]);
}

// ---------------- implicit-GEMM conv (im2col fused into A loads) ----------------
// A[M=32768, K=576] virtual; row R -> (b, t, n), kcol -> (c, kt, ph, pw0..7).
// Each 8-half chunk = one contiguous row-of-8 in xh, zfill when tt < 0.
#define APAD 8
#define BPAD 8
#define STG  3

__device__ __forceinline__ const __half* conv_srcaddr(const __half* xh, int R, int kcol, int& sz) {
    int b = R >> 11;
    int t = (R >> 6) & 31;
    int n = R & 63;
    int c = kcol / 192;
    int rem = kcol - c * 192;
    int kt = rem >> 6;
    int ph = (rem & 63) >> 3;
    int tt = t + kt - 2;
    sz = (tt >= 0) ? 16 : 0;
    if (tt < 0) tt = 0;
    return xh + (((long)(b * 32 + tt) * 3 + c) << 12) + ((n >> 3) * 8 + ph) * 64 + (n & 7) * 8;
}

__global__ void conv_gemm_kernel(const __half* __restrict__ xh, const __half* __restrict__ B,
                                 const float* __restrict__ bias, float* __restrict__ Cf) {
    // BM=128, BN=128, 8 warps (WM=4, WN=2), MI=2, N=512, K=576
    constexpr int BM = 128, BN = 128, WN = 2, MI = 2;
    constexpr int NT = 256;
    constexpr int A_IT = 2, B_IT = 2;
    constexpr int WTN = BN / WN;   // 64
    constexpr int NJ = 8, NJ2 = 4;
    constexpr int KT = KCONV / 32; // 18
    __shared__ __half As[STG][BM][32 + APAD];
    __shared__ __half Bs[STG][32][BN + BPAD];

    int tid = threadIdx.x, lane = tid & 31, warp = tid >> 5;
    int wm = warp / WN, wn = warp % WN;
    int bm = blockIdx.y * BM, bn = blockIdx.x * BN;

    int ar[A_IT], aq[A_IT], br[B_IT], bq[B_IT];
#pragma unroll
    for (int i = 0; i < A_IT; i++) { int u = tid + i * NT; ar[i] = u >> 2; aq[i] = u & 3; }
#pragma unroll
    for (int i = 0; i < B_IT; i++) { int v = tid + i * NT; br[i] = v / (BN / 8); bq[i] = v % (BN / 8); }

#pragma unroll
    for (int s = 0; s < STG - 1; s++) {
        int k0 = s * 32;
#pragma unroll
        for (int i = 0; i < A_IT; i++) {
            int sz; const __half* src = conv_srcaddr(xh, bm + ar[i], k0 + aq[i] * 8, sz);
            cp_async16z(smem_u32(&As[s][ar[i]][aq[i] * 8]), src, sz);
        }
#pragma unroll
        for (int i = 0; i < B_IT; i++)
            cp_async16(smem_u32(&Bs[s][br[i]][bq[i] * 8]),
                       B + (long)(k0 + br[i]) * DHID + bn + bq[i] * 8);
        cp_commit();
    }

    float c[MI][NJ][4];
#pragma unroll
    for (int i = 0; i < MI; i++)
#pragma unroll
        for (int j = 0; j < NJ; j++)
#pragma unroll
            for (int e = 0; e < 4; e++) c[i][j][e] = 0.f;

    for (int kt = 0; kt < KT; kt++) {
        cp_wait<STG - 2>();
        __syncthreads();
        int buf = kt % STG;
#pragma unroll
        for (int ks = 0; ks < 32; ks += 16) {
            unsigned a[MI][4], bf[NJ2][4];
#pragma unroll
            for (int i = 0; i < MI; i++) {
                unsigned addr = smem_u32(&As[buf][wm * MI * 16 + i * 16 + (lane & 15)][ks + (lane >> 4) * 8]);
                asm volatile("ldmatrix.sync.aligned.m8n8.x4.shared.b16 {%0,%1,%2,%3}, [%4];"
                             : "=r"(a[i][0]), "=r"(a[i][1]), "=r"(a[i][2]), "=r"(a[i][3]) : "r"(addr));
            }
#pragma unroll
            for (int j2 = 0; j2 < NJ2; j2++) {
                unsigned addr = smem_u32(&Bs[buf][ks + (lane & 7) + ((lane >> 3) & 1) * 8]
                                             [wn * WTN + j2 * 16 + (lane >> 4) * 8]);
                asm volatile("ldmatrix.sync.aligned.m8n8.x4.trans.shared.b16 {%0,%1,%2,%3}, [%4];"
                             : "=r"(bf[j2][0]), "=r"(bf[j2][1]), "=r"(bf[j2][2]), "=r"(bf[j2][3]) : "r"(addr));
            }
#pragma unroll
            for (int i = 0; i < MI; i++)
#pragma unroll
                for (int j = 0; j < NJ; j++) {
                    unsigned b0 = bf[j >> 1][(j & 1) * 2], b1 = bf[j >> 1][(j & 1) * 2 + 1];
                    asm volatile(
                        "mma.sync.aligned.m16n8k16.row.col.f32.f16.f16.f32 "
                        "{%0,%1,%2,%3}, {%4,%5,%6,%7}, {%8,%9}, {%0,%1,%2,%3};"
                        : "+f"(c[i][j][0]), "+f"(c[i][j][1]), "+f"(c[i][j][2]), "+f"(c[i][j][3])
                        : "r"(a[i][0]), "r"(a[i][1]), "r"(a[i][2]), "r"(a[i][3]), "r"(b0), "r"(b1));
                }
        }
        int kn = kt + STG - 1;
        if (kn < KT) {
            int nb = kn % STG;
            int k0 = kn * 32;
#pragma unroll
            for (int i = 0; i < A_IT; i++) {
                int sz; const __half* src = conv_srcaddr(xh, bm + ar[i], k0 + aq[i] * 8, sz);
                cp_async16z(smem_u32(&As[nb][ar[i]][aq[i] * 8]), src, sz);
            }
#pragma unroll
            for (int i = 0; i < B_IT; i++)
                cp_async16(smem_u32(&Bs[nb][br[i]][bq[i] * 8]),
                           B + (long)(k0 + br[i]) * DHID + bn + bq[i] * 8);
        }
        cp_commit();
    }

#pragma unroll
    for (int i = 0; i < MI; i++)
#pragma unroll
        for (int j = 0; j < NJ; j++) {
            int r0 = bm + wm * MI * 16 + i * 16 + (lane >> 2);
            int c0 = bn + wn * WTN + j * 8 + (lane & 3) * 2;
#pragma unroll
            for (int half_ = 0; half_ < 2; half_++) {
                int rr = r0 + half_ * 8;
                float v0 = c[i][j][half_ * 2 + 0] + bias[c0];
                float v1 = c[i][j][half_ * 2 + 1] + bias[c0 + 1];
                *(float2*)&Cf[(long)rr * DHID + c0] = make_float2(v0, v1);
            }
        }
}

// ---------------- tensor-core GEMM, 3-stage cp.async pipeline ----------------
template<int BM, int BN, int WM, int WN, int MI>
__global__ void hgemm_kernel(const __half* __restrict__ A, const __half* __restrict__ B,
                             const float* __restrict__ bias,
                             float* __restrict__ Cf, __half* __restrict__ Ch,
                             int M, int N, int K, int epi,
                             const float* __restrict__ res, const float* __restrict__ scale) {
    constexpr int NT = WM * WN * 32;
    constexpr int A_IT = BM * 4 / NT;
    constexpr int B_IT = 4 * BN / NT;
    constexpr int WTN = BN / WN;
    constexpr int NJ = WTN / 8;
    constexpr int NJ2 = WTN / 16;
    __shared__ __half As[STG][BM][32 + APAD];
    __shared__ __half Bs[STG][32][BN + BPAD];

    int tid = threadIdx.x;
    int lane = tid & 31;
    int warp = tid >> 5;
    int wm = warp / WN, wn = warp % WN;
    int bm = blockIdx.y * BM, bn = blockIdx.x * BN;
    int KT = K >> 5;

    int ar[A_IT], aq[A_IT], br[B_IT], bq[B_IT];
#pragma unroll
    for (int i = 0; i < A_IT; i++) { int u = tid + i * NT; ar[i] = u >> 2; aq[i] = u & 3; }
#pragma unroll
    for (int i = 0; i < B_IT; i++) { int v = tid + i * NT; br[i] = v / (BN / 8); bq[i] = v % (BN / 8); }

#pragma unroll
    for (int s = 0; s < STG - 1; s++) {
        int k0 = s * 32;
        if (s < KT) {
#pragma unroll
            for (int i = 0; i < A_IT; i++)
                cp_async16(smem_u32(&As[s][ar[i]][aq[i] * 8]),
                           A + (long)(bm + ar[i]) * K + k0 + aq[i] * 8);
#pragma unroll
            for (int i = 0; i < B_IT; i++)
                cp_async16(smem_u32(&Bs[s][br[i]][bq[i] * 8]),
                           B + (long)(k0 + br[i]) * N + bn + bq[i] * 8);
        }
        cp_commit();
    }

    float c[MI][NJ][4];
#pragma unroll
    for (int i = 0; i < MI; i++)
#pragma unroll
        for (int j = 0; j < NJ; j++)
#pragma unroll
            for (int e = 0; e < 4; e++) c[i][j][e] = 0.f;

    for (int kt = 0; kt < KT; kt++) {
        cp_wait<STG - 2>();
        __syncthreads();
        int buf = kt % STG;
#pragma unroll
        for (int ks = 0; ks < 32; ks += 16) {
            unsigned a[MI][4], bf[NJ2][4];
#pragma unroll
            for (int i = 0; i < MI; i++) {
                unsigned addr = smem_u32(&As[buf][wm * MI * 16 + i * 16 + (lane & 15)][ks + (lane >> 4) * 8]);
                asm volatile("ldmatrix.sync.aligned.m8n8.x4.shared.b16 {%0,%1,%2,%3}, [%4];"
                             : "=r"(a[i][0]), "=r"(a[i][1]), "=r"(a[i][2]), "=r"(a[i][3]) : "r"(addr));
            }
#pragma unroll
            for (int j2 = 0; j2 < NJ2; j2++) {
                unsigned addr = smem_u32(&Bs[buf][ks + (lane & 7) + ((lane >> 3) & 1) * 8]
                                             [wn * WTN + j2 * 16 + (lane >> 4) * 8]);
                asm volatile("ldmatrix.sync.aligned.m8n8.x4.trans.shared.b16 {%0,%1,%2,%3}, [%4];"
                             : "=r"(bf[j2][0]), "=r"(bf[j2][1]), "=r"(bf[j2][2]), "=r"(bf[j2][3]) : "r"(addr));
            }
#pragma unroll
            for (int i = 0; i < MI; i++)
#pragma unroll
                for (int j = 0; j < NJ; j++) {
                    unsigned b0 = bf[j >> 1][(j & 1) * 2], b1 = bf[j >> 1][(j & 1) * 2 + 1];
                    asm volatile(
                        "mma.sync.aligned.m16n8k16.row.col.f32.f16.f16.f32 "
                        "{%0,%1,%2,%3}, {%4,%5,%6,%7}, {%8,%9}, {%0,%1,%2,%3};"
                        : "+f"(c[i][j][0]), "+f"(c[i][j][1]), "+f"(c[i][j][2]), "+f"(c[i][j][3])
                        : "r"(a[i][0]), "r"(a[i][1]), "r"(a[i][2]), "r"(a[i][3]), "r"(b0), "r"(b1));
                }
        }
        int kn = kt + STG - 1;
        if (kn < KT) {
            int nb = kn % STG;
            int k0 = kn * 32;
#pragma unroll
            for (int i = 0; i < A_IT; i++)
                cp_async16(smem_u32(&As[nb][ar[i]][aq[i] * 8]),
                           A + (long)(bm + ar[i]) * K + k0 + aq[i] * 8);
#pragma unroll
            for (int i = 0; i < B_IT; i++)
                cp_async16(smem_u32(&Bs[nb][br[i]][bq[i] * 8]),
                           B + (long)(k0 + br[i]) * N + bn + bq[i] * 8);
        }
        cp_commit();
    }

    float sc = (epi == 2) ? scale[0] : 0.f;
#pragma unroll
    for (int i = 0; i < MI; i++)
#pragma unroll
        for (int j = 0; j < NJ; j++) {
            int r0 = bm + wm * MI * 16 + i * 16 + (lane >> 2);
            int c0 = bn + wn * WTN + j * 8 + (lane & 3) * 2;
#pragma unroll
            for (int half_ = 0; half_ < 2; half_++) {
                int rr = r0 + half_ * 8;
                float v0 = c[i][j][half_ * 2 + 0] + bias[c0];
                float v1 = c[i][j][half_ * 2 + 1] + bias[c0 + 1];
                long off = (long)rr * N + c0;
                if (epi == 0) {
                    *(float2*)&Cf[off] = make_float2(v0, v1);
                } else if (epi == 1) {
                    float g0 = 0.5f * v0 * (1.f + erff(v0 * 0.70710678118654752f));
                    float g1 = 0.5f * v1 * (1.f + erff(v1 * 0.70710678118654752f));
                    *(__half2*)&Ch[off] = __floats2half2_rn(g0, g1);
                } else {
                    float2 rv = *(const float2*)&res[off];
                    *(float2*)&Cf[off] = make_float2(rv.x + sc * v0, rv.y + sc * v1);
                }
            }
        }
}

// ---------------- fused LN1 + kqv GEMM + RoPE + attention ----------------
#define XSTR 520
#define BSTRF 200
#define SMEMF 79872

__global__ void kqvattn_kernel(const float* __restrict__ H, const float* __restrict__ g,
                               const float* __restrict__ bvec, const __half* __restrict__ W,
                               const float* __restrict__ bias,
                               const float* __restrict__ ropeS, const float* __restrict__ ropeC,
                               __half* __restrict__ out) {
    extern __shared__ char smf[];
    __half* xs = (__half*)smf;
    __half* Bsm = (__half*)(smf + 33280);
    float* kk = (float*)(smf + 33280);
    float* qq = kk + 32 * 65;
    float* vv = qq + 32 * 64;
    float* ss = vv + 32 * 64;
    float* rs = (float*)(smf + 71680);
    float* rc = rs + 32 * 32;

    int tid = threadIdx.x, lane = tid & 31, warp = tid >> 5;
    int bh = blockIdx.x, b = bh >> 3, h = bh & 7;
    int wm = warp >> 2, wn = warp & 3;

    for (int i = tid; i < 1024; i += 256) { rs[i] = ropeS[i]; rc[i] = ropeC[i]; }

    int brr[3], bqq[3];
#pragma unroll
    for (int i = 0; i < 3; i++) { int v = tid + i * 256; brr[i] = v / 24; bqq[i] = v % 24; }
    const __half* Wbase = W + h * 64;
#pragma unroll
    for (int s = 0; s < 2; s++) {
        int k0 = s * 32;
#pragma unroll
        for (int i = 0; i < 3; i++) {
            cp_async16(smem_u32(&Bsm[(s * 32 + brr[i]) * BSTRF + bqq[i] * 8]),
                       Wbase + (long)(k0 + brr[i]) * 1536 + (bqq[i] >> 3) * 512 + (bqq[i] & 7) * 8);
        }
        cp_commit();
    }

    for (int ri = 0; ri < 4; ri++) {
        int r = warp * 4 + ri;
        const float* row = H + (long)(b * 32 + r) * DHID;
        float v[16]; float s = 0.f;
#pragma unroll
        for (int i = 0; i < 16; i++) { v[i] = row[lane + 32 * i]; s += v[i]; }
        s = warp_sum(s);
        float mu = s * (1.f / 512.f);
        float vs = 0.f;
#pragma unroll
        for (int i = 0; i < 16; i++) { float d = v[i] - mu; vs += d * d; }
        vs = warp_sum(vs);
        float rstd = rsqrtf(vs * (1.f / 512.f) + 1e-5f);
#pragma unroll
        for (int i = 0; i < 16; i++) {
            int d = lane + 32 * i;
            xs[r * XSTR + d] = __float2half_rn((v[i] - mu) * rstd * g[d] + bvec[d]);
        }
    }

    float c[6][4];
#pragma unroll
    for (int j = 0; j < 6; j++)
#pragma unroll
        for (int e = 0; e < 4; e++) c[j][e] = 0.f;

    for (int kt = 0; kt < 16; kt++) {
        cp_wait<1>();
        __syncthreads();
        int buf = kt % 3;
#pragma unroll
        for (int ks = 0; ks < 32; ks += 16) {
            unsigned a[4], bf[3][4];
            unsigned addr = smem_u32(&xs[(wm * 16 + (lane & 15)) * XSTR + kt * 32 + ks + (lane >> 4) * 8]);
            asm volatile("ldmatrix.sync.aligned.m8n8.x4.shared.b16 {%0,%1,%2,%3}, [%4];"
                         : "=r"(a[0]), "=r"(a[1]), "=r"(a[2]), "=r"(a[3]) : "r"(addr));
#pragma unroll
            for (int j2 = 0; j2 < 3; j2++) {
                unsigned baddr = smem_u32(&Bsm[(buf * 32 + ks + (lane & 7) + ((lane >> 3) & 1) * 8) * BSTRF
                                               + wn * 48 + j2 * 16 + (lane >> 4) * 8]);
                asm volatile("ldmatrix.sync.aligned.m8n8.x4.trans.shared.b16 {%0,%1,%2,%3}, [%4];"
                             : "=r"(bf[j2][0]), "=r"(bf[j2][1]), "=r"(bf[j2][2]), "=r"(bf[j2][3]) : "r"(baddr));
            }
#pragma unroll
            for (int j = 0; j < 6; j++) {
                unsigned b0 = bf[j >> 1][(j & 1) * 2], b1 = bf[j >> 1][(j & 1) * 2 + 1];
                asm volatile(
                    "mma.sync.aligned.m16n8k16.row.col.f32.f16.f16.f32 "
                    "{%0,%1,%2,%3}, {%4,%5,%6,%7}, {%8,%9}, {%0,%1,%2,%3};"
                    : "+f"(c[j][0]), "+f"(c[j][1]), "+f"(c[j][2]), "+f"(c[j][3])
                    : "r"(a[0]), "r"(a[1]), "r"(a[2]), "r"(a[3]), "r"(b0), "r"(b1));
            }
        }
        int kn = kt + 2;
        if (kn < 16) {
            int nb = kn % 3;
            int k0 = kn * 32;
#pragma unroll
            for (int i = 0; i < 3; i++) {
                cp_async16(smem_u32(&Bsm[(nb * 32 + brr[i]) * BSTRF + bqq[i] * 8]),
                           Wbase + (long)(k0 + brr[i]) * 1536 + (bqq[i] >> 3) * 512 + (bqq[i] & 7) * 8);
            }
        }
        cp_commit();
    }
    __syncthreads();

#pragma unroll
    for (int j = 0; j < 6; j++) {
        int c0 = wn * 48 + j * 8 + (lane & 3) * 2;
        int seg = c0 >> 6, d = c0 & 63;
        float b0 = bias[seg * 512 + h * 64 + d];
        float b1 = bias[seg * 512 + h * 64 + d + 1];
#pragma unroll
        for (int half_ = 0; half_ < 2; half_++) {
            int r = wm * 16 + (lane >> 2) + half_ * 8;
            float v0 = c[j][half_ * 2 + 0] + b0;
            float v1 = c[j][half_ * 2 + 1] + b1;
            if (seg == 0)      { kk[r * 65 + d] = v0; kk[r * 65 + d + 1] = v1; }
            else if (seg == 1) { qq[r * 64 + d] = v0; qq[r * 64 + d + 1] = v1; }
            else               { vv[r * 64 + d] = v0; vv[r * 64 + d + 1] = v1; }
        }
    }
    __syncthreads();

#pragma unroll
    for (int i = 0; i < 4; i++) {
        int e = tid + i * 256;
        int t = e >> 5, j = e & 31;
        float sn = rs[t * 32 + j], cs = rc[t * 32 + j];
        float q1 = qq[t * 64 + j], q2 = qq[t * 64 + j + 32];
        qq[t * 64 + j]      = q1 * cs - q2 * sn;
        qq[t * 64 + j + 32] = q2 * cs + q1 * sn;
        float k1 = kk[t * 65 + j], k2 = kk[t * 65 + j + 32];
        kk[t * 65 + j]      = k1 * cs - k2 * sn;
        kk[t * 65 + j + 32] = k2 * cs + k1 * sn;
    }
    __syncthreads();

#pragma unroll
    for (int i = 0; i < 4; i++) {
        int e = tid + i * 256;
        int tq = e >> 5, tk = e & 31;
        if (tk <= tq) {
            float acc = 0.f;
#pragma unroll
            for (int dd = 0; dd < 64; dd++) acc += qq[tq * 64 + dd] * kk[tk * 65 + dd];
            ss[tq * 33 + tk] = acc * 0.125f;
        }
    }
    __syncthreads();
    for (int r = warp; r < 32; r += 8) {
        float val = (lane <= r) ? ss[r * 33 + lane] : -3.4e38f;
        float m = warp_max(val);
        float e = (lane <= r) ? expf(val - m) : 0.f;
        float sum = warp_sum(e);
        ss[r * 33 + lane] = e / sum;
    }
    __syncthreads();
#pragma unroll
    for (int i = 0; i < 8; i++) {
        int e = tid + i * 256;
        int t = e >> 6, d = e & 63;
        float acc = 0.f;
#pragma unroll
        for (int kk2 = 0; kk2 < 32; kk2++) acc += ss[t * 33 + kk2] * vv[kk2 * 64 + d];
        out[(long)(b * 32 + t) * DHID + h * 64 + d] = __float2half_rn(acc);
    }
}

// ---------------- small fp32 GEMM (film only) ----------------
__global__ void gemm_kernel(const float* __restrict__ A, const float* __restrict__ Bm,
                            const float* __restrict__ bias, float* C,
                            int M, int N, int K) {
    __shared__ float As[16][65];
    __shared__ float Bs[16][64];
    int bm = blockIdx.y * 64, bn = blockIdx.x * 64;
    int tid = threadIdx.x;
    int tx = tid & 15, ty = tid >> 4;
    float acc[4][4];
#pragma unroll
    for (int i = 0; i < 4; i++)
#pragma unroll
        for (int j = 0; j < 4; j++) acc[i][j] = 0.f;
    const float* Ab = A + (long)bm * K;
    for (int k0 = 0; k0 < K; k0 += 16) {
        {
            int col = tid & 15, row = tid >> 4;
#pragma unroll
            for (int r = 0; r < 4; r++)
                As[col][row + r * 16] = Ab[(long)(row + r * 16) * K + k0 + col];
        }
        {
            int col = tid & 63, row = tid >> 6;
#pragma unroll
            for (int r = 0; r < 4; r++)
                Bs[row + r * 4][col] = Bm[(long)(k0 + row + r * 4) * N + bn + col];
        }
        __syncthreads();
#pragma unroll
        for (int kk = 0; kk < 16; kk++) {
            float a0 = As[kk][ty * 4 + 0], a1 = As[kk][ty * 4 + 1];
            float a2 = As[kk][ty * 4 + 2], a3 = As[kk][ty * 4 + 3];
            float4 b4 = *(const float4*)&Bs[kk][tx * 4];
            acc[0][0] += a0 * b4.x; acc[0][1] += a0 * b4.y; acc[0][2] += a0 * b4.z; acc[0][3] += a0 * b4.w;
            acc[1][0] += a1 * b4.x; acc[1][1] += a1 * b4.y; acc[1][2] += a1 * b4.z; acc[1][3] += a1 * b4.w;
            acc[2][0] += a2 * b4.x; acc[2][1] += a2 * b4.y; acc[2][2] += a2 * b4.z; acc[2][3] += a2 * b4.w;
            acc[3][0] += a3 * b4.x; acc[3][1] += a3 * b4.y; acc[3][2] += a3 * b4.z; acc[3][3] += a3 * b4.w;
        }
        __syncthreads();
    }
#pragma unroll
    for (int i = 0; i < 4; i++) {
        int row = bm + ty * 4 + i;
#pragma unroll
        for (int j = 0; j < 4; j++) {
            int col = bn + tx * 4 + j;
            C[(long)row * N + col] = acc[i][j] + bias[col];
        }
    }
}

// ---------------- fused token LN + FiLM + spatial mean ----------------
__global__ void tok_reduce_kernel(const float* __restrict__ tok, const float* __restrict__ tg,
                                  const float* __restrict__ tb, const float* __restrict__ film,
                                  float* __restrict__ h) {
    __shared__ float accs[8][DHID];
    int bt = blockIdx.x;
    int wid = threadIdx.x >> 5, lane = threadIdx.x & 31;
    float acc[16];
#pragma unroll
    for (int i = 0; i < 16; i++) acc[i] = 0.f;
    const float* gb = film + bt * (2 * DHID);
    for (int n = wid; n < NTOK; n += 8) {
        const float* row = tok + (long)(bt * NTOK + n) * DHID;
        float v[16]; float s = 0.f;
#pragma unroll
        for (int i = 0; i < 16; i++) { v[i] = row[i * 32 + lane]; s += v[i]; }
        s = warp_sum(s);
        float mu = s * (1.f / 512.f);
        float vs = 0.f;
#pragma unroll
        for (int i = 0; i < 16; i++) { float d = v[i] - mu; vs += d * d; }
        vs = warp_sum(vs);
        float rstd = rsqrtf(vs * (1.f / 512.f) + 1e-5f);
#pragma unroll
        for (int i = 0; i < 16; i++) {
            int d = i * 32 + lane;
            float ln = (v[i] - mu) * rstd * tg[d] + tb[d];
            acc[i] += (1.f + 0.5f * gb[d]) * ln + 0.5f * gb[DHID + d];
        }
    }
#pragma unroll
    for (int i = 0; i < 16; i++) accs[wid][i * 32 + lane] = acc[i];
    __syncthreads();
    for (int d = threadIdx.x; d < DHID; d += 256) {
        float s = 0.f;
#pragma unroll
        for (int w = 0; w < 8; w++) s += accs[w][d];
        h[bt * DHID + d] = s * (1.f / 64.f);
    }
}

// ---------------- LayerNorm -> fp16 out ----------------
__global__ void ln_h_kernel(const float* __restrict__ in, const float* __restrict__ g,
                            const float* __restrict__ b, __half* __restrict__ out) {
    __shared__ float sbuf[8];
    int tok = blockIdx.x, tid = threadIdx.x;
    const float* row = in + tok * DHID;
    float v0 = row[tid], v1 = row[tid + 256];
    float sum = block_sum_256(v0 + v1, sbuf);
    float mu = sum * (1.f / 512.f);
    float d0 = v0 - mu, d1 = v1 - mu;
    float vs = block_sum_256(d0 * d0 + d1 * d1, sbuf);
    float rstd = rsqrtf(vs * (1.f / 512.f) + 1e-5f);
    out[tok * DHID + tid]       = __float2half_rn(d0 * rstd * g[tid] + b[tid]);
    out[tok * DHID + tid + 256] = __float2half_rn(d1 * rstd * g[tid + 256] + b[tid + 256]);
}

// ---------------- head ----------------
__global__ void head_kernel(const float* __restrict__ hin, const float* __restrict__ g,
                            const float* __restrict__ b, const float* __restrict__ w,
                            const float* __restrict__ bias0, float* __restrict__ out) {
    __shared__ float sbuf[8];
    int tok = blockIdx.x, tid = threadIdx.x;
    const float* row = hin + tok * DHID;
    float v0 = row[tid], v1 = row[tid + 256];
    float sum = block_sum_256(v0 + v1, sbuf);
    float mu = sum * (1.f / 512.f);
    float d0 = v0 - mu, d1 = v1 - mu;
    float vs = block_sum_256(d0 * d0 + d1 * d1, sbuf);
    float rstd = rsqrtf(vs * (1.f / 512.f) + 1e-5f);
    float c = (d0 * rstd * g[tid] + b[tid]) * w[tid] +
              (d1 * rstd * g[tid + 256] + b[tid + 256]) * w[tid + 256];
    float tot = block_sum_256(c, sbuf);
    if (tid == 0) out[tok] = tot + bias0[0];
}

// ---------------- launch ----------------
extern "C" void kernel_launch(void* const* d_in, const int* in_sizes, int n_in,
                              void* d_out, int out_size) {
    const float* x       = (const float*)d_in[0];
    const float* z       = (const float*)d_in[1];
    const float* conv_w  = (const float*)d_in[2];
    const float* conv_b  = (const float*)d_in[3];
    const float* tok_g   = (const float*)d_in[4];
    const float* tok_b   = (const float*)d_in[5];
    const float* film_w  = (const float*)d_in[6];
    const float* film_b  = (const float*)d_in[7];
    const float* ln1_g   = (const float*)d_in[8];
    const float* ln1_b   = (const float*)d_in[9];
    const float* kqv_w   = (const float*)d_in[10];
    const float* kqv_b   = (const float*)d_in[11];
    const float* proj_w  = (const float*)d_in[12];
    const float* proj_b  = (const float*)d_in[13];
    const float* ln2_g   = (const float*)d_in[14];
    const float* ln2_b   = (const float*)d_in[15];
    const float* mlp_w1  = (const float*)d_in[16];
    const float* mlp_b1  = (const float*)d_in[17];
    const float* mlp_w2  = (const float*)d_in[18];
    const float* mlp_b2  = (const float*)d_in[19];
    const float* rs_attn = (const float*)d_in[20];
    const float* rs_mlp  = (const float*)d_in[21];
    const float* head_g  = (const float*)d_in[22];
    const float* head_b  = (const float*)d_in[23];
    const float* head_w  = (const float*)d_in[24];
    const float* head_bi = (const float*)d_in[25];
    float* out = (float*)d_out;

    __half *wT_h, *xh, *kqvw_h, *projw_h, *w1_h, *w2_h, *xln_h, *attn_h, *mlp_h;
    float *tok, *film, *h, *ropeS, *ropeC;
    cudaGetSymbolAddress((void**)&wT_h, g_wT_h);
    cudaGetSymbolAddress((void**)&xh, g_xh);
    cudaGetSymbolAddress((void**)&kqvw_h, g_kqvw_h);
    cudaGetSymbolAddress((void**)&projw_h, g_projw_h);
    cudaGetSymbolAddress((void**)&w1_h, g_w1_h);
    cudaGetSymbolAddress((void**)&w2_h, g_w2_h);
    cudaGetSymbolAddress((void**)&xln_h, g_xln_h);
    cudaGetSymbolAddress((void**)&attn_h, g_attn_h);
    cudaGetSymbolAddress((void**)&mlp_h, g_mlp_h);
    cudaGetSymbolAddress((void**)&tok, g_tok);
    cudaGetSymbolAddress((void**)&film, g_film);
    cudaGetSymbolAddress((void**)&h, g_h);
    cudaGetSymbolAddress((void**)&ropeS, g_ropeS);
    cudaGetSymbolAddress((void**)&ropeC, g_ropeC);

    cudaFuncSetAttribute(kqvattn_kernel, cudaFuncAttributeMaxDynamicSharedMemorySize, SMEMF);

    // setup: weights, rope, x -> fp16
    transpose_wh_kernel<<<(DHID * KCONV + 255) / 256, 256>>>(conv_w, wT_h);
    rope_kernel<<<1, 1024>>>(ropeS, ropeC);
    {
        int n0 = LAYERS * DHID * 3 * DHID / 4;
        int n1 = LAYERS * DHID * DHID / 4;
        int n2 = LAYERS * DHID * 4 * DHID / 4;
        int n3 = n2;
        int tot = n0 + n1 + n2 + n3;
        f2h4_kernel<<<(tot + 255) / 256, 256>>>(
            (const float4*)kqv_w, (const float4*)proj_w, (const float4*)mlp_w1, (const float4*)mlp_w2,
            kqvw_h, projw_h, w1_h, w2_h, n0, n1, n2, n3);
    }
    {
        int n4 = BB * TT * 3 * 64 * 64 / 4;
        f2h_kernel<<<(n4 + 255) / 256, 256>>>((const float4*)x, xh, n4);
    }
    // implicit-GEMM conv tokenizer (no im2col)
    conv_gemm_kernel<<<dim3(DHID / 128, MCONV / 128), 256>>>(xh, wT_h, conv_b, tok);
    gemm_kernel<<<dim3(1024 / 64, BT / 64), 256>>>(z, film_w, film_b, film, BT, 1024, 32);
    tok_reduce_kernel<<<BT, 256>>>(tok, tok_g, tok_b, film, h);

    // transformer
    for (int i = 0; i < LAYERS; i++) {
        kqvattn_kernel<<<BB * NHEAD, 256, SMEMF>>>(
            h, ln1_g + i * DHID, ln1_b + i * DHID, kqvw_h + (long)i * DHID * 1536,
            kqv_b + i * 1536, ropeS, ropeC, attn_h);
        hgemm_kernel<32, 64, 2, 2, 1><<<dim3(DHID / 64, BT / 32), 128>>>(
            attn_h, projw_h + (long)i * DHID * DHID, proj_b + i * DHID, h, nullptr,
            BT, DHID, DHID, 2, h, rs_attn + i);
        ln_h_kernel<<<BT, 256>>>(h, ln2_g + i * DHID, ln2_b + i * DHID, xln_h);
        hgemm_kernel<32, 64, 2, 2, 1><<<dim3(2048 / 64, BT / 32), 128>>>(
            xln_h, w1_h + (long)i * DHID * 2048, mlp_b1 + i * 2048, nullptr, mlp_h,
            BT, 2048, DHID, 1, nullptr, nullptr);
        hgemm_kernel<32, 64, 2, 2, 1><<<dim3(DHID / 64, BT / 32), 128>>>(
            mlp_h, w2_h + (long)i * 2048 * DHID, mlp_b2 + i * DHID, h, nullptr,
            BT, DHID, 2048, 2, h, rs_mlp + i);
    }
    head_kernel<<<BT, 256>>>(h, head_g, head_b, head_w, head_bi, out);
}

// round 10
// speedup vs baseline: 1.5728x; 1.0126x over previous
#include <cuda_runtime.h>
#include <cuda_fp16.h>
#include <cstdint>
#include <math.h>

// ---------------- problem constants ----------------
#define DHID   512
#define NHEAD  8
#define LAYERS 6
#define BB     16
#define TT     32
#define NTOK   64
#define KCONV  576
#define BT     512
#define MCONV  32768

// ---------------- device scratch ----------------
__device__ __half g_wT_h[KCONV * DHID];
__device__ __half g_xh[BB * TT * 3 * 64 * 64];      // x in fp16
__device__ __half g_kqvw_h[LAYERS * DHID * 3 * DHID];
__device__ __half g_projw_h[LAYERS * DHID * DHID];
__device__ __half g_w1_h[LAYERS * DHID * 4 * DHID];
__device__ __half g_w2_h[LAYERS * 4 * DHID * DHID];
__device__ __half g_attn_h[BT * DHID];
__device__ __half g_mlp_h[BT * 4 * DHID];
__device__ float  g_tok[(size_t)MCONV * DHID];
__device__ float  g_film[BT * 2 * DHID];
__device__ float  g_h[BT * DHID];
__device__ float  g_ropeS[TT * 32];
__device__ float  g_ropeC[TT * 32];

// ---------------- helpers ----------------
__device__ __forceinline__ float warp_sum(float v) {
#pragma unroll
    for (int o = 16; o; o >>= 1) v += __shfl_xor_sync(0xffffffffu, v, o);
    return v;
}
__device__ __forceinline__ float warp_max(float v) {
#pragma unroll
    for (int o = 16; o; o >>= 1) v = fmaxf(v, __shfl_xor_sync(0xffffffffu, v, o));
    return v;
}
__device__ __forceinline__ float block_sum_256(float v, float* sbuf) {
    int lane = threadIdx.x & 31, wid = threadIdx.x >> 5;
    v = warp_sum(v);
    if (lane == 0) sbuf[wid] = v;
    __syncthreads();
    float r = sbuf[0];
#pragma unroll
    for (int w = 1; w < 8; w++) r += sbuf[w];
    __syncthreads();
    return r;
}
__device__ __forceinline__ unsigned smem_u32(const void* p) {
    return (unsigned)__cvta_generic_to_shared(p);
}
__device__ __forceinline__ void cp_async16(unsigned dst, const void* src) {
    asm volatile("cp.async.cg.shared.global [%0], [%1], 16;" :: "r"(dst), "l"(src));
}
__device__ __forceinline__ void cp_async16z(unsigned dst, const void* src, int srcsize) {
    asm volatile("cp.async.cg.shared.global [%0], [%1], 16, %2;" :: "r"(dst), "l"(src), "r"(srcsize));
}
__device__ __forceinline__ void cp_commit() {
    asm volatile("cp.async.commit_group;");
}
template<int N>
__device__ __forceinline__ void cp_wait() {
    asm volatile("cp.async.wait_group %0;" :: "n"(N));
}

// ---------------- rope table ----------------
__global__ void rope_kernel(float* rs, float* rc) {
    int i = threadIdx.x;      // 1024
    int t = i >> 5, j = i & 31;
    float ang = (float)t * powf(10000.f, -(float)j * (1.f / 32.f));
    float sn, cs; sincosf(ang, &sn, &cs);
    rs[i] = sn; rc[i] = cs;
}

// ---------------- conversions ----------------
__global__ void f2h_kernel(const float4* __restrict__ s, __half* __restrict__ d, int n4) {
    int i = blockIdx.x * 256 + threadIdx.x;
    if (i >= n4) return;
    float4 v = s[i];
    __half2* o = (__half2*)(d + (size_t)i * 4);
    o[0] = __floats2half2_rn(v.x, v.y);
    o[1] = __floats2half2_rn(v.z, v.w);
}
__global__ void f2h4_kernel(const float4* __restrict__ s0, const float4* __restrict__ s1,
                            const float4* __restrict__ s2, const float4* __restrict__ s3,
                            __half* __restrict__ d0, __half* __restrict__ d1,
                            __half* __restrict__ d2, __half* __restrict__ d3,
                            int n0, int n1, int n2, int n3) {
    int i = blockIdx.x * 256 + threadIdx.x;
    const float4* s; __half* d; int j = i;
    if (j < n0) { s = s0; d = d0; }
    else { j -= n0;
        if (j < n1) { s = s1; d = d1; }
        else { j -= n1;
            if (j < n2) { s = s2; d = d2; }
            else { j -= n2; if (j >= n3) return; s = s3; d = d3; }
        }
    }
    float4 v = s[j];
    __half2* o = (__half2*)(d + (size_t)j * 4);
    o[0] = __floats2half2_rn(v.x, v.y);
    o[1] = __floats2half2_rn(v.z, v.w);
}
__global__ void transpose_wh_kernel(const float* __restrict__ w, __half* __restrict__ wT) {
    int idx = blockIdx.x * 256 + threadIdx.x;
    if (idx >= DHID * KCONV) return;
    int d = idx / KCONV, k = idx % KCONV;
    wT[k * DHID + d] = __float2half_rn(w[idx]);
}

// ---------------- implicit-GEMM conv ----------------
#define APAD 8
#define BPAD 8
#define STG  3

__device__ __forceinline__ const __half* conv_srcaddr(const __half* xh, int R, int kcol, int& sz) {
    int b = R >> 11;
    int t = (R >> 6) & 31;
    int n = R & 63;
    int c = kcol / 192;
    int rem = kcol - c * 192;
    int kt = rem >> 6;
    int ph = (rem & 63) >> 3;
    int tt = t + kt - 2;
    sz = (tt >= 0) ? 16 : 0;
    if (tt < 0) tt = 0;
    return xh + (((long)(b * 32 + tt) * 3 + c) << 12) + ((n >> 3) * 8 + ph) * 64 + (n & 7) * 8;
}

__global__ void conv_gemm_kernel(const __half* __restrict__ xh, const __half* __restrict__ B,
                                 const float* __restrict__ bias, float* __restrict__ Cf) {
    constexpr int BM = 128, BN = 128, WN = 2, MI = 2;
    constexpr int NT = 256;
    constexpr int A_IT = 2, B_IT = 2;
    constexpr int WTN = BN / WN;
    constexpr int NJ = 8, NJ2 = 4;
    constexpr int KT = KCONV / 32;
    __shared__ __half As[STG][BM][32 + APAD];
    __shared__ __half Bs[STG][32][BN + BPAD];

    int tid = threadIdx.x, lane = tid & 31, warp = tid >> 5;
    int wm = warp / WN, wn = warp % WN;
    int bm = blockIdx.y * BM, bn = blockIdx.x * BN;

    int ar[A_IT], aq[A_IT], br[B_IT], bq[B_IT];
#pragma unroll
    for (int i = 0; i < A_IT; i++) { int u = tid + i * NT; ar[i] = u >> 2; aq[i] = u & 3; }
#pragma unroll
    for (int i = 0; i < B_IT; i++) { int v = tid + i * NT; br[i] = v / (BN / 8); bq[i] = v % (BN / 8); }

#pragma unroll
    for (int s = 0; s < STG - 1; s++) {
        int k0 = s * 32;
#pragma unroll
        for (int i = 0; i < A_IT; i++) {
            int sz; const __half* src = conv_srcaddr(xh, bm + ar[i], k0 + aq[i] * 8, sz);
            cp_async16z(smem_u32(&As[s][ar[i]][aq[i] * 8]), src, sz);
        }
#pragma unroll
        for (int i = 0; i < B_IT; i++)
            cp_async16(smem_u32(&Bs[s][br[i]][bq[i] * 8]),
                       B + (long)(k0 + br[i]) * DHID + bn + bq[i] * 8);
        cp_commit();
    }

    float c[MI][NJ][4];
#pragma unroll
    for (int i = 0; i < MI; i++)
#pragma unroll
        for (int j = 0; j < NJ; j++)
#pragma unroll
            for (int e = 0; e < 4; e++) c[i][j][e] = 0.f;

    for (int kt = 0; kt < KT; kt++) {
        cp_wait<STG - 2>();
        __syncthreads();
        int buf = kt % STG;
#pragma unroll
        for (int ks = 0; ks < 32; ks += 16) {
            unsigned a[MI][4], bf[NJ2][4];
#pragma unroll
            for (int i = 0; i < MI; i++) {
                unsigned addr = smem_u32(&As[buf][wm * MI * 16 + i * 16 + (lane & 15)][ks + (lane >> 4) * 8]);
                asm volatile("ldmatrix.sync.aligned.m8n8.x4.shared.b16 {%0,%1,%2,%3}, [%4];"
                             : "=r"(a[i][0]), "=r"(a[i][1]), "=r"(a[i][2]), "=r"(a[i][3]) : "r"(addr));
            }
#pragma unroll
            for (int j2 = 0; j2 < NJ2; j2++) {
                unsigned addr = smem_u32(&Bs[buf][ks + (lane & 7) + ((lane >> 3) & 1) * 8]
                                             [wn * WTN + j2 * 16 + (lane >> 4) * 8]);
                asm volatile("ldmatrix.sync.aligned.m8n8.x4.trans.shared.b16 {%0,%1,%2,%3}, [%4];"
                             : "=r"(bf[j2][0]), "=r"(bf[j2][1]), "=r"(bf[j2][2]), "=r"(bf[j2][3]) : "r"(addr));
            }
#pragma unroll
            for (int i = 0; i < MI; i++)
#pragma unroll
                for (int j = 0; j < NJ; j++) {
                    unsigned b0 = bf[j >> 1][(j & 1) * 2], b1 = bf[j >> 1][(j & 1) * 2 + 1];
                    asm volatile(
                        "mma.sync.aligned.m16n8k16.row.col.f32.f16.f16.f32 "
                        "{%0,%1,%2,%3}, {%4,%5,%6,%7}, {%8,%9}, {%0,%1,%2,%3};"
                        : "+f"(c[i][j][0]), "+f"(c[i][j][1]), "+f"(c[i][j][2]), "+f"(c[i][j][3])
                        : "r"(a[i][0]), "r"(a[i][1]), "r"(a[i][2]), "r"(a[i][3]), "r"(b0), "r"(b1));
                }
        }
        int kn = kt + STG - 1;
        if (kn < KT) {
            int nb = kn % STG;
            int k0 = kn * 32;
#pragma unroll
            for (int i = 0; i < A_IT; i++) {
                int sz; const __half* src = conv_srcaddr(xh, bm + ar[i], k0 + aq[i] * 8, sz);
                cp_async16z(smem_u32(&As[nb][ar[i]][aq[i] * 8]), src, sz);
            }
#pragma unroll
            for (int i = 0; i < B_IT; i++)
                cp_async16(smem_u32(&Bs[nb][br[i]][bq[i] * 8]),
                           B + (long)(k0 + br[i]) * DHID + bn + bq[i] * 8);
        }
        cp_commit();
    }

#pragma unroll
    for (int i = 0; i < MI; i++)
#pragma unroll
        for (int j = 0; j < NJ; j++) {
            int r0 = bm + wm * MI * 16 + i * 16 + (lane >> 2);
            int c0 = bn + wn * WTN + j * 8 + (lane & 3) * 2;
#pragma unroll
            for (int half_ = 0; half_ < 2; half_++) {
                int rr = r0 + half_ * 8;
                float v0 = c[i][j][half_ * 2 + 0] + bias[c0];
                float v1 = c[i][j][half_ * 2 + 1] + bias[c0 + 1];
                *(float2*)&Cf[(long)rr * DHID + c0] = make_float2(v0, v1);
            }
        }
}

// ---------------- tensor-core GEMM, 3-stage cp.async pipeline ----------------
template<int BM, int BN, int WM, int WN, int MI>
__global__ void hgemm_kernel(const __half* __restrict__ A, const __half* __restrict__ B,
                             const float* __restrict__ bias,
                             float* __restrict__ Cf, __half* __restrict__ Ch,
                             int M, int N, int K, int epi,
                             const float* __restrict__ res, const float* __restrict__ scale) {
    constexpr int NT = WM * WN * 32;
    constexpr int A_IT = BM * 4 / NT;
    constexpr int B_IT = 4 * BN / NT;
    constexpr int WTN = BN / WN;
    constexpr int NJ = WTN / 8;
    constexpr int NJ2 = WTN / 16;
    __shared__ __half As[STG][BM][32 + APAD];
    __shared__ __half Bs[STG][32][BN + BPAD];

    int tid = threadIdx.x;
    int lane = tid & 31;
    int warp = tid >> 5;
    int wm = warp / WN, wn = warp % WN;
    int bm = blockIdx.y * BM, bn = blockIdx.x * BN;
    int KT = K >> 5;

    int ar[A_IT], aq[A_IT], br[B_IT], bq[B_IT];
#pragma unroll
    for (int i = 0; i < A_IT; i++) { int u = tid + i * NT; ar[i] = u >> 2; aq[i] = u & 3; }
#pragma unroll
    for (int i = 0; i < B_IT; i++) { int v = tid + i * NT; br[i] = v / (BN / 8); bq[i] = v % (BN / 8); }

#pragma unroll
    for (int s = 0; s < STG - 1; s++) {
        int k0 = s * 32;
        if (s < KT) {
#pragma unroll
            for (int i = 0; i < A_IT; i++)
                cp_async16(smem_u32(&As[s][ar[i]][aq[i] * 8]),
                           A + (long)(bm + ar[i]) * K + k0 + aq[i] * 8);
#pragma unroll
            for (int i = 0; i < B_IT; i++)
                cp_async16(smem_u32(&Bs[s][br[i]][bq[i] * 8]),
                           B + (long)(k0 + br[i]) * N + bn + bq[i] * 8);
        }
        cp_commit();
    }

    float c[MI][NJ][4];
#pragma unroll
    for (int i = 0; i < MI; i++)
#pragma unroll
        for (int j = 0; j < NJ; j++)
#pragma unroll
            for (int e = 0; e < 4; e++) c[i][j][e] = 0.f;

    for (int kt = 0; kt < KT; kt++) {
        cp_wait<STG - 2>();
        __syncthreads();
        int buf = kt % STG;
#pragma unroll
        for (int ks = 0; ks < 32; ks += 16) {
            unsigned a[MI][4], bf[NJ2][4];
#pragma unroll
            for (int i = 0; i < MI; i++) {
                unsigned addr = smem_u32(&As[buf][wm * MI * 16 + i * 16 + (lane & 15)][ks + (lane >> 4) * 8]);
                asm volatile("ldmatrix.sync.aligned.m8n8.x4.shared.b16 {%0,%1,%2,%3}, [%4];"
                             : "=r"(a[i][0]), "=r"(a[i][1]), "=r"(a[i][2]), "=r"(a[i][3]) : "r"(addr));
            }
#pragma unroll
            for (int j2 = 0; j2 < NJ2; j2++) {
                unsigned addr = smem_u32(&Bs[buf][ks + (lane & 7) + ((lane >> 3) & 1) * 8]
                                             [wn * WTN + j2 * 16 + (lane >> 4) * 8]);
                asm volatile("ldmatrix.sync.aligned.m8n8.x4.trans.shared.b16 {%0,%1,%2,%3}, [%4];"
                             : "=r"(bf[j2][0]), "=r"(bf[j2][1]), "=r"(bf[j2][2]), "=r"(bf[j2][3]) : "r"(addr));
            }
#pragma unroll
            for (int i = 0; i < MI; i++)
#pragma unroll
                for (int j = 0; j < NJ; j++) {
                    unsigned b0 = bf[j >> 1][(j & 1) * 2], b1 = bf[j >> 1][(j & 1) * 2 + 1];
                    asm volatile(
                        "mma.sync.aligned.m16n8k16.row.col.f32.f16.f16.f32 "
                        "{%0,%1,%2,%3}, {%4,%5,%6,%7}, {%8,%9}, {%0,%1,%2,%3};"
                        : "+f"(c[i][j][0]), "+f"(c[i][j][1]), "+f"(c[i][j][2]), "+f"(c[i][j][3])
                        : "r"(a[i][0]), "r"(a[i][1]), "r"(a[i][2]), "r"(a[i][3]), "r"(b0), "r"(b1));
                }
        }
        int kn = kt + STG - 1;
        if (kn < KT) {
            int nb = kn % STG;
            int k0 = kn * 32;
#pragma unroll
            for (int i = 0; i < A_IT; i++)
                cp_async16(smem_u32(&As[nb][ar[i]][aq[i] * 8]),
                           A + (long)(bm + ar[i]) * K + k0 + aq[i] * 8);
#pragma unroll
            for (int i = 0; i < B_IT; i++)
                cp_async16(smem_u32(&Bs[nb][br[i]][bq[i] * 8]),
                           B + (long)(k0 + br[i]) * N + bn + bq[i] * 8);
        }
        cp_commit();
    }

    float sc = (epi == 2) ? scale[0] : 0.f;
#pragma unroll
    for (int i = 0; i < MI; i++)
#pragma unroll
        for (int j = 0; j < NJ; j++) {
            int r0 = bm + wm * MI * 16 + i * 16 + (lane >> 2);
            int c0 = bn + wn * WTN + j * 8 + (lane & 3) * 2;
#pragma unroll
            for (int half_ = 0; half_ < 2; half_++) {
                int rr = r0 + half_ * 8;
                float v0 = c[i][j][half_ * 2 + 0] + bias[c0];
                float v1 = c[i][j][half_ * 2 + 1] + bias[c0 + 1];
                long off = (long)rr * N + c0;
                if (epi == 0) {
                    *(float2*)&Cf[off] = make_float2(v0, v1);
                } else if (epi == 1) {
                    float g0 = 0.5f * v0 * (1.f + erff(v0 * 0.70710678118654752f));
                    float g1 = 0.5f * v1 * (1.f + erff(v1 * 0.70710678118654752f));
                    *(__half2*)&Ch[off] = __floats2half2_rn(g0, g1);
                } else {
                    float2 rv = *(const float2*)&res[off];
                    *(float2*)&Cf[off] = make_float2(rv.x + sc * v0, rv.y + sc * v1);
                }
            }
        }
}

// ---------------- fused LN2 + mlp1 GEMM (+GELU) ----------------
// BM=32, BN=128, 256 thr (8 warps: wm 0..1 x wn 0..3). K=512, N=2048.
// Each block LN-normalizes its 32 rows into resident smem A, then pipelined B.
#define XSTR 520
#define M1BSTR 136
#define SMEM_M1 (32 * XSTR * 2 + 3 * 32 * M1BSTR * 2)   // 59392

__global__ void mlp1_ln_kernel(const float* __restrict__ H, const float* __restrict__ g,
                               const float* __restrict__ bvec, const __half* __restrict__ B,
                               const float* __restrict__ bias, __half* __restrict__ out) {
    extern __shared__ __half sm1[];
    __half* xs = sm1;                      // [32][520]
    __half* Bs = sm1 + 32 * XSTR;          // [3][32][136]
    int tid = threadIdx.x, lane = tid & 31, warp = tid >> 5;
    int wm = warp >> 2, wn = warp & 3;
    int bm = blockIdx.y * 32, bn = blockIdx.x * 128;

    int br[2], bq[2];
#pragma unroll
    for (int i = 0; i < 2; i++) { int v = tid + i * 256; br[i] = v >> 4; bq[i] = v & 15; }
#pragma unroll
    for (int s = 0; s < 2; s++) {
        int k0 = s * 32;
#pragma unroll
        for (int i = 0; i < 2; i++)
            cp_async16(smem_u32(&Bs[(s * 32 + br[i]) * M1BSTR + bq[i] * 8]),
                       B + (long)(k0 + br[i]) * 2048 + bn + bq[i] * 8);
        cp_commit();
    }

    // LN: each warp 4 rows
    for (int ri = 0; ri < 4; ri++) {
        int r = warp * 4 + ri;
        const float* row = H + (long)(bm + r) * DHID;
        float v[16]; float s = 0.f;
#pragma unroll
        for (int i = 0; i < 16; i++) { v[i] = row[lane + 32 * i]; s += v[i]; }
        s = warp_sum(s);
        float mu = s * (1.f / 512.f);
        float vs = 0.f;
#pragma unroll
        for (int i = 0; i < 16; i++) { float d = v[i] - mu; vs += d * d; }
        vs = warp_sum(vs);
        float rstd = rsqrtf(vs * (1.f / 512.f) + 1e-5f);
#pragma unroll
        for (int i = 0; i < 16; i++) {
            int d = lane + 32 * i;
            xs[r * XSTR + d] = __float2half_rn((v[i] - mu) * rstd * g[d] + bvec[d]);
        }
    }

    float c[4][4];
#pragma unroll
    for (int j = 0; j < 4; j++)
#pragma unroll
        for (int e = 0; e < 4; e++) c[j][e] = 0.f;

    for (int kt = 0; kt < 16; kt++) {
        cp_wait<1>();
        __syncthreads();
        int buf = kt % 3;
#pragma unroll
        for (int ks = 0; ks < 32; ks += 16) {
            unsigned a[4], bf[2][4];
            unsigned addr = smem_u32(&xs[(wm * 16 + (lane & 15)) * XSTR + kt * 32 + ks + (lane >> 4) * 8]);
            asm volatile("ldmatrix.sync.aligned.m8n8.x4.shared.b16 {%0,%1,%2,%3}, [%4];"
                         : "=r"(a[0]), "=r"(a[1]), "=r"(a[2]), "=r"(a[3]) : "r"(addr));
#pragma unroll
            for (int j2 = 0; j2 < 2; j2++) {
                unsigned baddr = smem_u32(&Bs[(buf * 32 + ks + (lane & 7) + ((lane >> 3) & 1) * 8) * M1BSTR
                                              + wn * 32 + j2 * 16 + (lane >> 4) * 8]);
                asm volatile("ldmatrix.sync.aligned.m8n8.x4.trans.shared.b16 {%0,%1,%2,%3}, [%4];"
                             : "=r"(bf[j2][0]), "=r"(bf[j2][1]), "=r"(bf[j2][2]), "=r"(bf[j2][3]) : "r"(baddr));
            }
#pragma unroll
            for (int j = 0; j < 4; j++) {
                unsigned b0 = bf[j >> 1][(j & 1) * 2], b1 = bf[j >> 1][(j & 1) * 2 + 1];
                asm volatile(
                    "mma.sync.aligned.m16n8k16.row.col.f32.f16.f16.f32 "
                    "{%0,%1,%2,%3}, {%4,%5,%6,%7}, {%8,%9}, {%0,%1,%2,%3};"
                    : "+f"(c[j][0]), "+f"(c[j][1]), "+f"(c[j][2]), "+f"(c[j][3])
                    : "r"(a[0]), "r"(a[1]), "r"(a[2]), "r"(a[3]), "r"(b0), "r"(b1));
            }
        }
        int kn = kt + 2;
        if (kn < 16) {
            int nb = kn % 3;
            int k0 = kn * 32;
#pragma unroll
            for (int i = 0; i < 2; i++)
                cp_async16(smem_u32(&Bs[(nb * 32 + br[i]) * M1BSTR + bq[i] * 8]),
                           B + (long)(k0 + br[i]) * 2048 + bn + bq[i] * 8);
        }
        cp_commit();
    }

#pragma unroll
    for (int j = 0; j < 4; j++) {
        int r0 = bm + wm * 16 + (lane >> 2);
        int c0 = bn + wn * 32 + j * 8 + (lane & 3) * 2;
        float b0 = bias[c0], b1 = bias[c0 + 1];
#pragma unroll
        for (int half_ = 0; half_ < 2; half_++) {
            int rr = r0 + half_ * 8;
            float v0 = c[j][half_ * 2 + 0] + b0;
            float v1 = c[j][half_ * 2 + 1] + b1;
            float g0 = 0.5f * v0 * (1.f + erff(v0 * 0.70710678118654752f));
            float g1 = 0.5f * v1 * (1.f + erff(v1 * 0.70710678118654752f));
            *(__half2*)&out[(long)rr * 2048 + c0] = __floats2half2_rn(g0, g1);
        }
    }
}

// ---------------- fused LN1 + kqv GEMM + RoPE + attention ----------------
#define BSTRF 200
#define SMEMF 79872

__global__ void kqvattn_kernel(const float* __restrict__ H, const float* __restrict__ g,
                               const float* __restrict__ bvec, const __half* __restrict__ W,
                               const float* __restrict__ bias,
                               const float* __restrict__ ropeS, const float* __restrict__ ropeC,
                               __half* __restrict__ out) {
    extern __shared__ char smf[];
    __half* xs = (__half*)smf;
    __half* Bsm = (__half*)(smf + 33280);
    float* kk = (float*)(smf + 33280);
    float* qq = kk + 32 * 65;
    float* vv = qq + 32 * 64;
    float* ss = vv + 32 * 64;
    float* rs = (float*)(smf + 71680);
    float* rc = rs + 32 * 32;

    int tid = threadIdx.x, lane = tid & 31, warp = tid >> 5;
    int bh = blockIdx.x, b = bh >> 3, h = bh & 7;
    int wm = warp >> 2, wn = warp & 3;

    for (int i = tid; i < 1024; i += 256) { rs[i] = ropeS[i]; rc[i] = ropeC[i]; }

    int brr[3], bqq[3];
#pragma unroll
    for (int i = 0; i < 3; i++) { int v = tid + i * 256; brr[i] = v / 24; bqq[i] = v % 24; }
    const __half* Wbase = W + h * 64;
#pragma unroll
    for (int s = 0; s < 2; s++) {
        int k0 = s * 32;
#pragma unroll
        for (int i = 0; i < 3; i++) {
            cp_async16(smem_u32(&Bsm[(s * 32 + brr[i]) * BSTRF + bqq[i] * 8]),
                       Wbase + (long)(k0 + brr[i]) * 1536 + (bqq[i] >> 3) * 512 + (bqq[i] & 7) * 8);
        }
        cp_commit();
    }

    for (int ri = 0; ri < 4; ri++) {
        int r = warp * 4 + ri;
        const float* row = H + (long)(b * 32 + r) * DHID;
        float v[16]; float s = 0.f;
#pragma unroll
        for (int i = 0; i < 16; i++) { v[i] = row[lane + 32 * i]; s += v[i]; }
        s = warp_sum(s);
        float mu = s * (1.f / 512.f);
        float vs = 0.f;
#pragma unroll
        for (int i = 0; i < 16; i++) { float d = v[i] - mu; vs += d * d; }
        vs = warp_sum(vs);
        float rstd = rsqrtf(vs * (1.f / 512.f) + 1e-5f);
#pragma unroll
        for (int i = 0; i < 16; i++) {
            int d = lane + 32 * i;
            xs[r * XSTR + d] = __float2half_rn((v[i] - mu) * rstd * g[d] + bvec[d]);
        }
    }

    float c[6][4];
#pragma unroll
    for (int j = 0; j < 6; j++)
#pragma unroll
        for (int e = 0; e < 4; e++) c[j][e] = 0.f;

    for (int kt = 0; kt < 16; kt++) {
        cp_wait<1>();
        __syncthreads();
        int buf = kt % 3;
#pragma unroll
        for (int ks = 0; ks < 32; ks += 16) {
            unsigned a[4], bf[3][4];
            unsigned addr = smem_u32(&xs[(wm * 16 + (lane & 15)) * XSTR + kt * 32 + ks + (lane >> 4) * 8]);
            asm volatile("ldmatrix.sync.aligned.m8n8.x4.shared.b16 {%0,%1,%2,%3}, [%4];"
                         : "=r"(a[0]), "=r"(a[1]), "=r"(a[2]), "=r"(a[3]) : "r"(addr));
#pragma unroll
            for (int j2 = 0; j2 < 3; j2++) {
                unsigned baddr = smem_u32(&Bsm[(buf * 32 + ks + (lane & 7) + ((lane >> 3) & 1) * 8) * BSTRF
                                               + wn * 48 + j2 * 16 + (lane >> 4) * 8]);
                asm volatile("ldmatrix.sync.aligned.m8n8.x4.trans.shared.b16 {%0,%1,%2,%3}, [%4];"
                             : "=r"(bf[j2][0]), "=r"(bf[j2][1]), "=r"(bf[j2][2]), "=r"(bf[j2][3]) : "r"(baddr));
            }
#pragma unroll
            for (int j = 0; j < 6; j++) {
                unsigned b0 = bf[j >> 1][(j & 1) * 2], b1 = bf[j >> 1][(j & 1) * 2 + 1];
                asm volatile(
                    "mma.sync.aligned.m16n8k16.row.col.f32.f16.f16.f32 "
                    "{%0,%1,%2,%3}, {%4,%5,%6,%7}, {%8,%9}, {%0,%1,%2,%3};"
                    : "+f"(c[j][0]), "+f"(c[j][1]), "+f"(c[j][2]), "+f"(c[j][3])
                    : "r"(a[0]), "r"(a[1]), "r"(a[2]), "r"(a[3]), "r"(b0), "r"(b1));
            }
        }
        int kn = kt + 2;
        if (kn < 16) {
            int nb = kn % 3;
            int k0 = kn * 32;
#pragma unroll
            for (int i = 0; i < 3; i++) {
                cp_async16(smem_u32(&Bsm[(nb * 32 + brr[i]) * BSTRF + bqq[i] * 8]),
                           Wbase + (long)(k0 + brr[i]) * 1536 + (bqq[i] >> 3) * 512 + (bqq[i] & 7) * 8);
            }
        }
        cp_commit();
    }
    __syncthreads();

#pragma unroll
    for (int j = 0; j < 6; j++) {
        int c0 = wn * 48 + j * 8 + (lane & 3) * 2;
        int seg = c0 >> 6, d = c0 & 63;
        float b0 = bias[seg * 512 + h * 64 + d];
        float b1 = bias[seg * 512 + h * 64 + d + 1];
#pragma unroll
        for (int half_ = 0; half_ < 2; half_++) {
            int r = wm * 16 + (lane >> 2) + half_ * 8;
            float v0 = c[j][half_ * 2 + 0] + b0;
            float v1 = c[j][half_ * 2 + 1] + b1;
            if (seg == 0)      { kk[r * 65 + d] = v0; kk[r * 65 + d + 1] = v1; }
            else if (seg == 1) { qq[r * 64 + d] = v0; qq[r * 64 + d + 1] = v1; }
            else               { vv[r * 64 + d] = v0; vv[r * 64 + d + 1] = v1; }
        }
    }
    __syncthreads();

#pragma unroll
    for (int i = 0; i < 4; i++) {
        int e = tid + i * 256;
        int t = e >> 5, j = e & 31;
        float sn = rs[t * 32 + j], cs = rc[t * 32 + j];
        float q1 = qq[t * 64 + j], q2 = qq[t * 64 + j + 32];
        qq[t * 64 + j]      = q1 * cs - q2 * sn;
        qq[t * 64 + j + 32] = q2 * cs + q1 * sn;
        float k1 = kk[t * 65 + j], k2 = kk[t * 65 + j + 32];
        kk[t * 65 + j]      = k1 * cs - k2 * sn;
        kk[t * 65 + j + 32] = k2 * cs + k1 * sn;
    }
    __syncthreads();

#pragma unroll
    for (int i = 0; i < 4; i++) {
        int e = tid + i * 256;
        int tq = e >> 5, tk = e & 31;
        if (tk <= tq) {
            float acc = 0.f;
#pragma unroll
            for (int dd = 0; dd < 64; dd++) acc += qq[tq * 64 + dd] * kk[tk * 65 + dd];
            ss[tq * 33 + tk] = acc * 0.125f;
        }
    }
    __syncthreads();
    for (int r = warp; r < 32; r += 8) {
        float val = (lane <= r) ? ss[r * 33 + lane] : -3.4e38f;
        float m = warp_max(val);
        float e = (lane <= r) ? expf(val - m) : 0.f;
        float sum = warp_sum(e);
        ss[r * 33 + lane] = e / sum;
    }
    __syncthreads();
#pragma unroll
    for (int i = 0; i < 8; i++) {
        int e = tid + i * 256;
        int t = e >> 6, d = e & 63;
        float acc = 0.f;
#pragma unroll
        for (int kk2 = 0; kk2 < 32; kk2++) acc += ss[t * 33 + kk2] * vv[kk2 * 64 + d];
        out[(long)(b * 32 + t) * DHID + h * 64 + d] = __float2half_rn(acc);
    }
}

// ---------------- small fp32 GEMM (film only) ----------------
__global__ void gemm_kernel(const float* __restrict__ A, const float* __restrict__ Bm,
                            const float* __restrict__ bias, float* C,
                            int M, int N, int K) {
    __shared__ float As[16][65];
    __shared__ float Bs[16][64];
    int bm = blockIdx.y * 64, bn = blockIdx.x * 64;
    int tid = threadIdx.x;
    int tx = tid & 15, ty = tid >> 4;
    float acc[4][4];
#pragma unroll
    for (int i = 0; i < 4; i++)
#pragma unroll
        for (int j = 0; j < 4; j++) acc[i][j] = 0.f;
    const float* Ab = A + (long)bm * K;
    for (int k0 = 0; k0 < K; k0 += 16) {
        {
            int col = tid & 15, row = tid >> 4;
#pragma unroll
            for (int r = 0; r < 4; r++)
                As[col][row + r * 16] = Ab[(long)(row + r * 16) * K + k0 + col];
        }
        {
            int col = tid & 63, row = tid >> 6;
#pragma unroll
            for (int r = 0; r < 4; r++)
                Bs[row + r * 4][col] = Bm[(long)(k0 + row + r * 4) * N + bn + col];
        }
        __syncthreads();
#pragma unroll
        for (int kk = 0; kk < 16; kk++) {
            float a0 = As[kk][ty * 4 + 0], a1 = As[kk][ty * 4 + 1];
            float a2 = As[kk][ty * 4 + 2], a3 = As[kk][ty * 4 + 3];
            float4 b4 = *(const float4*)&Bs[kk][tx * 4];
            acc[0][0] += a0 * b4.x; acc[0][1] += a0 * b4.y; acc[0][2] += a0 * b4.z; acc[0][3] += a0 * b4.w;
            acc[1][0] += a1 * b4.x; acc[1][1] += a1 * b4.y; acc[1][2] += a1 * b4.z; acc[1][3] += a1 * b4.w;
            acc[2][0] += a2 * b4.x; acc[2][1] += a2 * b4.y; acc[2][2] += a2 * b4.z; acc[2][3] += a2 * b4.w;
            acc[3][0] += a3 * b4.x; acc[3][1] += a3 * b4.y; acc[3][2] += a3 * b4.z; acc[3][3] += a3 * b4.w;
        }
        __syncthreads();
    }
#pragma unroll
    for (int i = 0; i < 4; i++) {
        int row = bm + ty * 4 + i;
#pragma unroll
        for (int j = 0; j < 4; j++) {
            int col = bn + tx * 4 + j;
            C[(long)row * N + col] = acc[i][j] + bias[col];
        }
    }
}

// ---------------- fused token LN + FiLM + spatial mean ----------------
__global__ void tok_reduce_kernel(const float* __restrict__ tok, const float* __restrict__ tg,
                                  const float* __restrict__ tb, const float* __restrict__ film,
                                  float* __restrict__ h) {
    __shared__ float accs[8][DHID];
    int bt = blockIdx.x;
    int wid = threadIdx.x >> 5, lane = threadIdx.x & 31;
    float acc[16];
#pragma unroll
    for (int i = 0; i < 16; i++) acc[i] = 0.f;
    const float* gb = film + bt * (2 * DHID);
    for (int n = wid; n < NTOK; n += 8) {
        const float* row = tok + (long)(bt * NTOK + n) * DHID;
        float v[16]; float s = 0.f;
#pragma unroll
        for (int i = 0; i < 16; i++) { v[i] = row[i * 32 + lane]; s += v[i]; }
        s = warp_sum(s);
        float mu = s * (1.f / 512.f);
        float vs = 0.f;
#pragma unroll
        for (int i = 0; i < 16; i++) { float d = v[i] - mu; vs += d * d; }
        vs = warp_sum(vs);
        float rstd = rsqrtf(vs * (1.f / 512.f) + 1e-5f);
#pragma unroll
        for (int i = 0; i < 16; i++) {
            int d = i * 32 + lane;
            float ln = (v[i] - mu) * rstd * tg[d] + tb[d];
            acc[i] += (1.f + 0.5f * gb[d]) * ln + 0.5f * gb[DHID + d];
        }
    }
#pragma unroll
    for (int i = 0; i < 16; i++) accs[wid][i * 32 + lane] = acc[i];
    __syncthreads();
    for (int d = threadIdx.x; d < DHID; d += 256) {
        float s = 0.f;
#pragma unroll
        for (int w = 0; w < 8; w++) s += accs[w][d];
        h[bt * DHID + d] = s * (1.f / 64.f);
    }
}

// ---------------- head ----------------
__global__ void head_kernel(const float* __restrict__ hin, const float* __restrict__ g,
                            const float* __restrict__ b, const float* __restrict__ w,
                            const float* __restrict__ bias0, float* __restrict__ out) {
    __shared__ float sbuf[8];
    int tok = blockIdx.x, tid = threadIdx.x;
    const float* row = hin + tok * DHID;
    float v0 = row[tid], v1 = row[tid + 256];
    float sum = block_sum_256(v0 + v1, sbuf);
    float mu = sum * (1.f / 512.f);
    float d0 = v0 - mu, d1 = v1 - mu;
    float vs = block_sum_256(d0 * d0 + d1 * d1, sbuf);
    float rstd = rsqrtf(vs * (1.f / 512.f) + 1e-5f);
    float c = (d0 * rstd * g[tid] + b[tid]) * w[tid] +
              (d1 * rstd * g[tid + 256] + b[tid + 256]) * w[tid + 256];
    float tot = block_sum_256(c, sbuf);
    if (tid == 0) out[tok] = tot + bias0[0];
}

// ---------------- launch ----------------
extern "C" void kernel_launch(void* const* d_in, const int* in_sizes, int n_in,
                              void* d_out, int out_size) {
    const float* x       = (const float*)d_in[0];
    const float* z       = (const float*)d_in[1];
    const float* conv_w  = (const float*)d_in[2];
    const float* conv_b  = (const float*)d_in[3];
    const float* tok_g   = (const float*)d_in[4];
    const float* tok_b   = (const float*)d_in[5];
    const float* film_w  = (const float*)d_in[6];
    const float* film_b  = (const float*)d_in[7];
    const float* ln1_g   = (const float*)d_in[8];
    const float* ln1_b   = (const float*)d_in[9];
    const float* kqv_w   = (const float*)d_in[10];
    const float* kqv_b   = (const float*)d_in[11];
    const float* proj_w  = (const float*)d_in[12];
    const float* proj_b  = (const float*)d_in[13];
    const float* ln2_g   = (const float*)d_in[14];
    const float* ln2_b   = (const float*)d_in[15];
    const float* mlp_w1  = (const float*)d_in[16];
    const float* mlp_b1  = (const float*)d_in[17];
    const float* mlp_w2  = (const float*)d_in[18];
    const float* mlp_b2  = (const float*)d_in[19];
    const float* rs_attn = (const float*)d_in[20];
    const float* rs_mlp  = (const float*)d_in[21];
    const float* head_g  = (const float*)d_in[22];
    const float* head_b  = (const float*)d_in[23];
    const float* head_w  = (const float*)d_in[24];
    const float* head_bi = (const float*)d_in[25];
    float* out = (float*)d_out;

    __half *wT_h, *xh, *kqvw_h, *projw_h, *w1_h, *w2_h, *attn_h, *mlp_h;
    float *tok, *film, *h, *ropeS, *ropeC;
    cudaGetSymbolAddress((void**)&wT_h, g_wT_h);
    cudaGetSymbolAddress((void**)&xh, g_xh);
    cudaGetSymbolAddress((void**)&kqvw_h, g_kqvw_h);
    cudaGetSymbolAddress((void**)&projw_h, g_projw_h);
    cudaGetSymbolAddress((void**)&w1_h, g_w1_h);
    cudaGetSymbolAddress((void**)&w2_h, g_w2_h);
    cudaGetSymbolAddress((void**)&attn_h, g_attn_h);
    cudaGetSymbolAddress((void**)&mlp_h, g_mlp_h);
    cudaGetSymbolAddress((void**)&tok, g_tok);
    cudaGetSymbolAddress((void**)&film, g_film);
    cudaGetSymbolAddress((void**)&h, g_h);
    cudaGetSymbolAddress((void**)&ropeS, g_ropeS);
    cudaGetSymbolAddress((void**)&ropeC, g_ropeC);

    cudaFuncSetAttribute(kqvattn_kernel, cudaFuncAttributeMaxDynamicSharedMemorySize, SMEMF);
    cudaFuncSetAttribute(mlp1_ln_kernel, cudaFuncAttributeMaxDynamicSharedMemorySize, SMEM_M1);

    // setup: weights, rope, x -> fp16
    transpose_wh_kernel<<<(DHID * KCONV + 255) / 256, 256>>>(conv_w, wT_h);
    rope_kernel<<<1, 1024>>>(ropeS, ropeC);
    {
        int n0 = LAYERS * DHID * 3 * DHID / 4;
        int n1 = LAYERS * DHID * DHID / 4;
        int n2 = LAYERS * DHID * 4 * DHID / 4;
        int n3 = n2;
        int tot = n0 + n1 + n2 + n3;
        f2h4_kernel<<<(tot + 255) / 256, 256>>>(
            (const float4*)kqv_w, (const float4*)proj_w, (const float4*)mlp_w1, (const float4*)mlp_w2,
            kqvw_h, projw_h, w1_h, w2_h, n0, n1, n2, n3);
    }
    {
        int n4 = BB * TT * 3 * 64 * 64 / 4;
        f2h_kernel<<<(n4 + 255) / 256, 256>>>((const float4*)x, xh, n4);
    }
    // implicit-GEMM conv tokenizer
    conv_gemm_kernel<<<dim3(DHID / 128, MCONV / 128), 256>>>(xh, wT_h, conv_b, tok);
    gemm_kernel<<<dim3(1024 / 64, BT / 64), 256>>>(z, film_w, film_b, film, BT, 1024, 32);
    tok_reduce_kernel<<<BT, 256>>>(tok, tok_g, tok_b, film, h);

    // transformer (4 launches/layer)
    for (int i = 0; i < LAYERS; i++) {
        kqvattn_kernel<<<BB * NHEAD, 256, SMEMF>>>(
            h, ln1_g + i * DHID, ln1_b + i * DHID, kqvw_h + (long)i * DHID * 1536,
            kqv_b + i * 1536, ropeS, ropeC, attn_h);
        hgemm_kernel<32, 64, 2, 2, 1><<<dim3(DHID / 64, BT / 32), 128>>>(
            attn_h, projw_h + (long)i * DHID * DHID, proj_b + i * DHID, h, nullptr,
            BT, DHID, DHID, 2, h, rs_attn + i);
        mlp1_ln_kernel<<<dim3(2048 / 128, BT / 32), 256, SMEM_M1>>>(
            h, ln2_g + i * DHID, ln2_b + i * DHID, w1_h + (long)i * DHID * 2048,
            mlp_b1 + i * 2048, mlp_h);
        hgemm_kernel<32, 64, 2, 2, 1><<<dim3(DHID / 64, BT / 32), 128>>>(
            mlp_h, w2_h + (long)i * 2048 * DHID, mlp_b2 + i * DHID, h, nullptr,
            BT, DHID, 2048, 2, h, rs_mlp + i);
    }
    head_kernel<<<BT, 256>>>(h, head_g, head_b, head_w, head_bi, out);
}

// round 11
// speedup vs baseline: 1.8103x; 1.1509x over previous
#include <cuda_runtime.h>
#include <cuda_fp16.h>
#include <cstdint>
#include <math.h>

// ---------------- problem constants ----------------
#define DHID   512
#define NHEAD  8
#define LAYERS 6
#define BB     16
#define TT     32
#define NTOK   64
#define KCONV  576
#define BT     512
#define MCONV  32768

// ---------------- device scratch ----------------
__device__ __half g_wT_h[KCONV * DHID];
__device__ __half g_xh[BB * TT * 3 * 64 * 64];
__device__ __half g_kqvw_h[LAYERS * DHID * 3 * DHID];
__device__ __half g_projw_h[LAYERS * DHID * DHID];
__device__ __half g_w1_h[LAYERS * DHID * 4 * DHID];
__device__ __half g_w2_h[LAYERS * 4 * DHID * DHID];
__device__ __half g_attn_h[BT * DHID];
__device__ __half g_mlp_h[BT * 4 * DHID];
__device__ float  g_tok[(size_t)MCONV * DHID];
__device__ float  g_film[BT * 2 * DHID];
__device__ float  g_h[BT * DHID];
__device__ float  g_ropeS[TT * 32];
__device__ float  g_ropeC[TT * 32];

// ---------------- helpers ----------------
__device__ __forceinline__ float warp_sum(float v) {
#pragma unroll
    for (int o = 16; o; o >>= 1) v += __shfl_xor_sync(0xffffffffu, v, o);
    return v;
}
__device__ __forceinline__ float warp_max(float v) {
#pragma unroll
    for (int o = 16; o; o >>= 1) v = fmaxf(v, __shfl_xor_sync(0xffffffffu, v, o));
    return v;
}
__device__ __forceinline__ float block_sum_256(float v, float* sbuf) {
    int lane = threadIdx.x & 31, wid = threadIdx.x >> 5;
    v = warp_sum(v);
    if (lane == 0) sbuf[wid] = v;
    __syncthreads();
    float r = sbuf[0];
#pragma unroll
    for (int w = 1; w < 8; w++) r += sbuf[w];
    __syncthreads();
    return r;
}
__device__ __forceinline__ unsigned smem_u32(const void* p) {
    return (unsigned)__cvta_generic_to_shared(p);
}
__device__ __forceinline__ void cp_async16(unsigned dst, const void* src) {
    asm volatile("cp.async.cg.shared.global [%0], [%1], 16;" :: "r"(dst), "l"(src));
}
__device__ __forceinline__ void cp_async16z(unsigned dst, const void* src, int srcsize) {
    asm volatile("cp.async.cg.shared.global [%0], [%1], 16, %2;" :: "r"(dst), "l"(src), "r"(srcsize));
}
__device__ __forceinline__ void cp_commit() {
    asm volatile("cp.async.commit_group;");
}
template<int N>
__device__ __forceinline__ void cp_wait() {
    asm volatile("cp.async.wait_group %0;" :: "n"(N));
}

// ---------------- merged setup: transpose + rope + weight f2h + x f2h ----------
// blocks [0, NB_T): transpose conv_w       (294912 elems, 1 per thread)
// blocks [NB_T, +4): rope                  (1024 threads total)
// blocks [.., +NB_W): weight f2h segments  (float4 each)
// blocks [.., +NB_X): x f2h
#define NB_T 1152
#define NB_R 4
__global__ void setup_kernel(const float* __restrict__ conv_w, __half* __restrict__ wT,
                             float* __restrict__ rs, float* __restrict__ rc,
                             const float4* __restrict__ s0, const float4* __restrict__ s1,
                             const float4* __restrict__ s2, const float4* __restrict__ s3,
                             __half* __restrict__ d0, __half* __restrict__ d1,
                             __half* __restrict__ d2, __half* __restrict__ d3,
                             int n0, int n1, int n2, int n3,
                             const float4* __restrict__ xs, __half* __restrict__ xd, int nx) {
    int blk = blockIdx.x;
    if (blk < NB_T) {
        int idx = blk * 256 + threadIdx.x;
        if (idx < DHID * KCONV) {
            int d = idx / KCONV, k = idx % KCONV;
            wT[k * DHID + d] = __float2half_rn(conv_w[idx]);
        }
        return;
    }
    blk -= NB_T;
    if (blk < NB_R) {
        int i = blk * 256 + threadIdx.x;
        if (i < 1024) {
            int t = i >> 5, j = i & 31;
            float ang = (float)t * powf(10000.f, -(float)j * (1.f / 32.f));
            float sn, cs; sincosf(ang, &sn, &cs);
            rs[i] = sn; rc[i] = cs;
        }
        return;
    }
    blk -= NB_R;
    int i = blk * 256 + threadIdx.x;
    const float4* s; __half* d; int j = i;
    if (j < n0) { s = s0; d = d0; }
    else { j -= n0;
        if (j < n1) { s = s1; d = d1; }
        else { j -= n1;
            if (j < n2) { s = s2; d = d2; }
            else { j -= n2;
                if (j < n3) { s = s3; d = d3; }
                else { j -= n3; if (j >= nx) return; s = xs; d = xd; }
            }
        }
    }
    float4 v = s[j];
    __half2* o = (__half2*)(d + (size_t)j * 4);
    o[0] = __floats2half2_rn(v.x, v.y);
    o[1] = __floats2half2_rn(v.z, v.w);
}

// ---------------- implicit-GEMM conv (BK=32, proven) ----------------
#define APAD 8
#define BPAD 8
#define STG  3

__device__ __forceinline__ const __half* conv_srcaddr(const __half* xh, int R, int kcol, int& sz) {
    int b = R >> 11;
    int t = (R >> 6) & 31;
    int n = R & 63;
    int c = kcol / 192;
    int rem = kcol - c * 192;
    int kt = rem >> 6;
    int ph = (rem & 63) >> 3;
    int tt = t + kt - 2;
    sz = (tt >= 0) ? 16 : 0;
    if (tt < 0) tt = 0;
    return xh + (((long)(b * 32 + tt) * 3 + c) << 12) + ((n >> 3) * 8 + ph) * 64 + (n & 7) * 8;
}

__global__ void conv_gemm_kernel(const __half* __restrict__ xh, const __half* __restrict__ B,
                                 const float* __restrict__ bias, float* __restrict__ Cf) {
    constexpr int BM = 128, BN = 128, WN = 2, MI = 2;
    constexpr int NT = 256;
    constexpr int A_IT = 2, B_IT = 2;
    constexpr int WTN = BN / WN;
    constexpr int NJ = 8, NJ2 = 4;
    constexpr int KT = KCONV / 32;
    __shared__ __half As[STG][BM][32 + APAD];
    __shared__ __half Bs[STG][32][BN + BPAD];

    int tid = threadIdx.x, lane = tid & 31, warp = tid >> 5;
    int wm = warp / WN, wn = warp % WN;
    int bm = blockIdx.y * BM, bn = blockIdx.x * BN;

    int ar[A_IT], aq[A_IT], br[B_IT], bq[B_IT];
#pragma unroll
    for (int i = 0; i < A_IT; i++) { int u = tid + i * NT; ar[i] = u >> 2; aq[i] = u & 3; }
#pragma unroll
    for (int i = 0; i < B_IT; i++) { int v = tid + i * NT; br[i] = v / (BN / 8); bq[i] = v % (BN / 8); }

#pragma unroll
    for (int s = 0; s < STG - 1; s++) {
        int k0 = s * 32;
#pragma unroll
        for (int i = 0; i < A_IT; i++) {
            int sz; const __half* src = conv_srcaddr(xh, bm + ar[i], k0 + aq[i] * 8, sz);
            cp_async16z(smem_u32(&As[s][ar[i]][aq[i] * 8]), src, sz);
        }
#pragma unroll
        for (int i = 0; i < B_IT; i++)
            cp_async16(smem_u32(&Bs[s][br[i]][bq[i] * 8]),
                       B + (long)(k0 + br[i]) * DHID + bn + bq[i] * 8);
        cp_commit();
    }

    float c[MI][NJ][4];
#pragma unroll
    for (int i = 0; i < MI; i++)
#pragma unroll
        for (int j = 0; j < NJ; j++)
#pragma unroll
            for (int e = 0; e < 4; e++) c[i][j][e] = 0.f;

    for (int kt = 0; kt < KT; kt++) {
        cp_wait<STG - 2>();
        __syncthreads();
        int buf = kt % STG;
#pragma unroll
        for (int ks = 0; ks < 32; ks += 16) {
            unsigned a[MI][4], bf[NJ2][4];
#pragma unroll
            for (int i = 0; i < MI; i++) {
                unsigned addr = smem_u32(&As[buf][wm * MI * 16 + i * 16 + (lane & 15)][ks + (lane >> 4) * 8]);
                asm volatile("ldmatrix.sync.aligned.m8n8.x4.shared.b16 {%0,%1,%2,%3}, [%4];"
                             : "=r"(a[i][0]), "=r"(a[i][1]), "=r"(a[i][2]), "=r"(a[i][3]) : "r"(addr));
            }
#pragma unroll
            for (int j2 = 0; j2 < NJ2; j2++) {
                unsigned addr = smem_u32(&Bs[buf][ks + (lane & 7) + ((lane >> 3) & 1) * 8]
                                             [wn * WTN + j2 * 16 + (lane >> 4) * 8]);
                asm volatile("ldmatrix.sync.aligned.m8n8.x4.trans.shared.b16 {%0,%1,%2,%3}, [%4];"
                             : "=r"(bf[j2][0]), "=r"(bf[j2][1]), "=r"(bf[j2][2]), "=r"(bf[j2][3]) : "r"(addr));
            }
#pragma unroll
            for (int i = 0; i < MI; i++)
#pragma unroll
                for (int j = 0; j < NJ; j++) {
                    unsigned b0 = bf[j >> 1][(j & 1) * 2], b1 = bf[j >> 1][(j & 1) * 2 + 1];
                    asm volatile(
                        "mma.sync.aligned.m16n8k16.row.col.f32.f16.f16.f32 "
                        "{%0,%1,%2,%3}, {%4,%5,%6,%7}, {%8,%9}, {%0,%1,%2,%3};"
                        : "+f"(c[i][j][0]), "+f"(c[i][j][1]), "+f"(c[i][j][2]), "+f"(c[i][j][3])
                        : "r"(a[i][0]), "r"(a[i][1]), "r"(a[i][2]), "r"(a[i][3]), "r"(b0), "r"(b1));
                }
        }
        int kn = kt + STG - 1;
        if (kn < KT) {
            int nb = kn % STG;
            int k0 = kn * 32;
#pragma unroll
            for (int i = 0; i < A_IT; i++) {
                int sz; const __half* src = conv_srcaddr(xh, bm + ar[i], k0 + aq[i] * 8, sz);
                cp_async16z(smem_u32(&As[nb][ar[i]][aq[i] * 8]), src, sz);
            }
#pragma unroll
            for (int i = 0; i < B_IT; i++)
                cp_async16(smem_u32(&Bs[nb][br[i]][bq[i] * 8]),
                           B + (long)(k0 + br[i]) * DHID + bn + bq[i] * 8);
        }
        cp_commit();
    }

#pragma unroll
    for (int i = 0; i < MI; i++)
#pragma unroll
        for (int j = 0; j < NJ; j++) {
            int r0 = bm + wm * MI * 16 + i * 16 + (lane >> 2);
            int c0 = bn + wn * WTN + j * 8 + (lane & 3) * 2;
#pragma unroll
            for (int half_ = 0; half_ < 2; half_++) {
                int rr = r0 + half_ * 8;
                float v0 = c[i][j][half_ * 2 + 0] + bias[c0];
                float v1 = c[i][j][half_ * 2 + 1] + bias[c0 + 1];
                *(float2*)&Cf[(long)rr * DHID + c0] = make_float2(v0, v1);
            }
        }
}

// ---------------- tensor-core GEMM, BK=64, 3-stage cp.async ----------------
// BM=32, BN=64, 128 threads (4 warps: wm 0..1 x wn 0..1).
// epi 0: Cf=acc+bias   1: Ch=half(gelu)   2: Cf=res+scale[0]*(acc+bias)
__global__ void hgemm64_kernel(const __half* __restrict__ A, const __half* __restrict__ B,
                               const float* __restrict__ bias,
                               float* __restrict__ Cf, __half* __restrict__ Ch,
                               int M, int N, int K, int epi,
                               const float* __restrict__ res, const float* __restrict__ scale) {
    constexpr int BM = 32, BN = 64;
    __shared__ __half As[STG][BM][64 + APAD];
    __shared__ __half Bs[STG][64][BN + BPAD];

    int tid = threadIdx.x, lane = tid & 31, warp = tid >> 5;
    int wm = warp >> 1, wn = warp & 1;
    int bm = blockIdx.y * BM, bn = blockIdx.x * BN;
    int KT = K >> 6;

    // A: 32*8=256 cp per stage / 128 thr = 2;  B: 64*8=512 / 128 = 4
    int ar[2], aq[2], br[4], bq[4];
#pragma unroll
    for (int i = 0; i < 2; i++) { int u = tid + i * 128; ar[i] = u >> 3; aq[i] = u & 7; }
#pragma unroll
    for (int i = 0; i < 4; i++) { int v = tid + i * 128; br[i] = v >> 3; bq[i] = v & 7; }

#pragma unroll
    for (int s = 0; s < STG - 1; s++) {
        int k0 = s * 64;
        if (s < KT) {
#pragma unroll
            for (int i = 0; i < 2; i++)
                cp_async16(smem_u32(&As[s][ar[i]][aq[i] * 8]),
                           A + (long)(bm + ar[i]) * K + k0 + aq[i] * 8);
#pragma unroll
            for (int i = 0; i < 4; i++)
                cp_async16(smem_u32(&Bs[s][br[i]][bq[i] * 8]),
                           B + (long)(k0 + br[i]) * N + bn + bq[i] * 8);
        }
        cp_commit();
    }

    float c[4][4];
#pragma unroll
    for (int j = 0; j < 4; j++)
#pragma unroll
        for (int e = 0; e < 4; e++) c[j][e] = 0.f;

    for (int kt = 0; kt < KT; kt++) {
        cp_wait<STG - 2>();
        __syncthreads();
        int buf = kt % STG;
#pragma unroll
        for (int ks = 0; ks < 64; ks += 16) {
            unsigned a[4], bf[2][4];
            unsigned addr = smem_u32(&As[buf][wm * 16 + (lane & 15)][ks + (lane >> 4) * 8]);
            asm volatile("ldmatrix.sync.aligned.m8n8.x4.shared.b16 {%0,%1,%2,%3}, [%4];"
                         : "=r"(a[0]), "=r"(a[1]), "=r"(a[2]), "=r"(a[3]) : "r"(addr));
#pragma unroll
            for (int j2 = 0; j2 < 2; j2++) {
                unsigned baddr = smem_u32(&Bs[buf][ks + (lane & 7) + ((lane >> 3) & 1) * 8]
                                              [wn * 32 + j2 * 16 + (lane >> 4) * 8]);
                asm volatile("ldmatrix.sync.aligned.m8n8.x4.trans.shared.b16 {%0,%1,%2,%3}, [%4];"
                             : "=r"(bf[j2][0]), "=r"(bf[j2][1]), "=r"(bf[j2][2]), "=r"(bf[j2][3]) : "r"(baddr));
            }
#pragma unroll
            for (int j = 0; j < 4; j++) {
                unsigned b0 = bf[j >> 1][(j & 1) * 2], b1 = bf[j >> 1][(j & 1) * 2 + 1];
                asm volatile(
                    "mma.sync.aligned.m16n8k16.row.col.f32.f16.f16.f32 "
                    "{%0,%1,%2,%3}, {%4,%5,%6,%7}, {%8,%9}, {%0,%1,%2,%3};"
                    : "+f"(c[j][0]), "+f"(c[j][1]), "+f"(c[j][2]), "+f"(c[j][3])
                    : "r"(a[0]), "r"(a[1]), "r"(a[2]), "r"(a[3]), "r"(b0), "r"(b1));
            }
        }
        int kn = kt + STG - 1;
        if (kn < KT) {
            int nb = kn % STG;
            int k0 = kn * 64;
#pragma unroll
            for (int i = 0; i < 2; i++)
                cp_async16(smem_u32(&As[nb][ar[i]][aq[i] * 8]),
                           A + (long)(bm + ar[i]) * K + k0 + aq[i] * 8);
#pragma unroll
            for (int i = 0; i < 4; i++)
                cp_async16(smem_u32(&Bs[nb][br[i]][bq[i] * 8]),
                           B + (long)(k0 + br[i]) * N + bn + bq[i] * 8);
        }
        cp_commit();
    }

    float sc = (epi == 2) ? scale[0] : 0.f;
#pragma unroll
    for (int j = 0; j < 4; j++) {
        int r0 = bm + wm * 16 + (lane >> 2);
        int c0 = bn + wn * 32 + j * 8 + (lane & 3) * 2;
#pragma unroll
        for (int half_ = 0; half_ < 2; half_++) {
            int rr = r0 + half_ * 8;
            float v0 = c[j][half_ * 2 + 0] + bias[c0];
            float v1 = c[j][half_ * 2 + 1] + bias[c0 + 1];
            long off = (long)rr * N + c0;
            if (epi == 0) {
                *(float2*)&Cf[off] = make_float2(v0, v1);
            } else if (epi == 1) {
                float g0 = 0.5f * v0 * (1.f + erff(v0 * 0.70710678118654752f));
                float g1 = 0.5f * v1 * (1.f + erff(v1 * 0.70710678118654752f));
                *(__half2*)&Ch[off] = __floats2half2_rn(g0, g1);
            } else {
                float2 rv = *(const float2*)&res[off];
                *(float2*)&Cf[off] = make_float2(rv.x + sc * v0, rv.y + sc * v1);
            }
        }
    }
}

// ---------------- fused LN2 + mlp1 GEMM (+GELU), BK=64 ----------------
// BM=32, BN=128, 256 thr (8 warps: wm 0..1 x wn 0..3). K=512 (8 iters), N=2048.
#define XSTR 520
#define M1BSTR 136
#define SMEM_M1 (32 * XSTR * 2 + 3 * 64 * M1BSTR * 2)   // 33280 + 52224 = 85504

__global__ void mlp1_ln_kernel(const float* __restrict__ H, const float* __restrict__ g,
                               const float* __restrict__ bvec, const __half* __restrict__ B,
                               const float* __restrict__ bias, __half* __restrict__ out) {
    extern __shared__ __half sm1[];
    __half* xs = sm1;                      // [32][520]
    __half* Bs = sm1 + 32 * XSTR;          // [3][64][136]
    int tid = threadIdx.x, lane = tid & 31, warp = tid >> 5;
    int wm = warp >> 2, wn = warp & 3;
    int bm = blockIdx.y * 32, bn = blockIdx.x * 128;

    // B: 64*16 = 1024 cp per stage / 256 thr = 4
    int br[4], bq[4];
#pragma unroll
    for (int i = 0; i < 4; i++) { int v = tid + i * 256; br[i] = v >> 4; bq[i] = v & 15; }
#pragma unroll
    for (int s = 0; s < 2; s++) {
        int k0 = s * 64;
#pragma unroll
        for (int i = 0; i < 4; i++)
            cp_async16(smem_u32(&Bs[(s * 64 + br[i]) * M1BSTR + bq[i] * 8]),
                       B + (long)(k0 + br[i]) * 2048 + bn + bq[i] * 8);
        cp_commit();
    }

    for (int ri = 0; ri < 4; ri++) {
        int r = warp * 4 + ri;
        const float* row = H + (long)(bm + r) * DHID;
        float v[16]; float s = 0.f;
#pragma unroll
        for (int i = 0; i < 16; i++) { v[i] = row[lane + 32 * i]; s += v[i]; }
        s = warp_sum(s);
        float mu = s * (1.f / 512.f);
        float vs = 0.f;
#pragma unroll
        for (int i = 0; i < 16; i++) { float d = v[i] - mu; vs += d * d; }
        vs = warp_sum(vs);
        float rstd = rsqrtf(vs * (1.f / 512.f) + 1e-5f);
#pragma unroll
        for (int i = 0; i < 16; i++) {
            int d = lane + 32 * i;
            xs[r * XSTR + d] = __float2half_rn((v[i] - mu) * rstd * g[d] + bvec[d]);
        }
    }

    float c[4][4];
#pragma unroll
    for (int j = 0; j < 4; j++)
#pragma unroll
        for (int e = 0; e < 4; e++) c[j][e] = 0.f;

    for (int kt = 0; kt < 8; kt++) {
        cp_wait<1>();
        __syncthreads();
        int buf = kt % 3;
#pragma unroll
        for (int ks = 0; ks < 64; ks += 16) {
            unsigned a[4], bf[2][4];
            unsigned addr = smem_u32(&xs[(wm * 16 + (lane & 15)) * XSTR + kt * 64 + ks + (lane >> 4) * 8]);
            asm volatile("ldmatrix.sync.aligned.m8n8.x4.shared.b16 {%0,%1,%2,%3}, [%4];"
                         : "=r"(a[0]), "=r"(a[1]), "=r"(a[2]), "=r"(a[3]) : "r"(addr));
#pragma unroll
            for (int j2 = 0; j2 < 2; j2++) {
                unsigned baddr = smem_u32(&Bs[(buf * 64 + ks + (lane & 7) + ((lane >> 3) & 1) * 8) * M1BSTR
                                              + wn * 32 + j2 * 16 + (lane >> 4) * 8]);
                asm volatile("ldmatrix.sync.aligned.m8n8.x4.trans.shared.b16 {%0,%1,%2,%3}, [%4];"
                             : "=r"(bf[j2][0]), "=r"(bf[j2][1]), "=r"(bf[j2][2]), "=r"(bf[j2][3]) : "r"(baddr));
            }
#pragma unroll
            for (int j = 0; j < 4; j++) {
                unsigned b0 = bf[j >> 1][(j & 1) * 2], b1 = bf[j >> 1][(j & 1) * 2 + 1];
                asm volatile(
                    "mma.sync.aligned.m16n8k16.row.col.f32.f16.f16.f32 "
                    "{%0,%1,%2,%3}, {%4,%5,%6,%7}, {%8,%9}, {%0,%1,%2,%3};"
                    : "+f"(c[j][0]), "+f"(c[j][1]), "+f"(c[j][2]), "+f"(c[j][3])
                    : "r"(a[0]), "r"(a[1]), "r"(a[2]), "r"(a[3]), "r"(b0), "r"(b1));
            }
        }
        int kn = kt + 2;
        if (kn < 8) {
            int nb = kn % 3;
            int k0 = kn * 64;
#pragma unroll
            for (int i = 0; i < 4; i++)
                cp_async16(smem_u32(&Bs[(nb * 64 + br[i]) * M1BSTR + bq[i] * 8]),
                           B + (long)(k0 + br[i]) * 2048 + bn + bq[i] * 8);
        }
        cp_commit();
    }

#pragma unroll
    for (int j = 0; j < 4; j++) {
        int r0 = bm + wm * 16 + (lane >> 2);
        int c0 = bn + wn * 32 + j * 8 + (lane & 3) * 2;
        float b0 = bias[c0], b1 = bias[c0 + 1];
#pragma unroll
        for (int half_ = 0; half_ < 2; half_++) {
            int rr = r0 + half_ * 8;
            float v0 = c[j][half_ * 2 + 0] + b0;
            float v1 = c[j][half_ * 2 + 1] + b1;
            float g0 = 0.5f * v0 * (1.f + erff(v0 * 0.70710678118654752f));
            float g1 = 0.5f * v1 * (1.f + erff(v1 * 0.70710678118654752f));
            *(__half2*)&out[(long)rr * 2048 + c0] = __floats2half2_rn(g0, g1);
        }
    }
}

// ---------------- fused LN1 + kqv GEMM + RoPE + attention (BK=32) ----------------
#define BSTRF 200
#define SMEMF 79872

__global__ void kqvattn_kernel(const float* __restrict__ H, const float* __restrict__ g,
                               const float* __restrict__ bvec, const __half* __restrict__ W,
                               const float* __restrict__ bias,
                               const float* __restrict__ ropeS, const float* __restrict__ ropeC,
                               __half* __restrict__ out) {
    extern __shared__ char smf[];
    __half* xs = (__half*)smf;
    __half* Bsm = (__half*)(smf + 33280);
    float* kk = (float*)(smf + 33280);
    float* qq = kk + 32 * 65;
    float* vv = qq + 32 * 64;
    float* ss = vv + 32 * 64;
    float* rs = (float*)(smf + 71680);
    float* rc = rs + 32 * 32;

    int tid = threadIdx.x, lane = tid & 31, warp = tid >> 5;
    int bh = blockIdx.x, b = bh >> 3, h = bh & 7;
    int wm = warp >> 2, wn = warp & 3;

    for (int i = tid; i < 1024; i += 256) { rs[i] = ropeS[i]; rc[i] = ropeC[i]; }

    int brr[3], bqq[3];
#pragma unroll
    for (int i = 0; i < 3; i++) { int v = tid + i * 256; brr[i] = v / 24; bqq[i] = v % 24; }
    const __half* Wbase = W + h * 64;
#pragma unroll
    for (int s = 0; s < 2; s++) {
        int k0 = s * 32;
#pragma unroll
        for (int i = 0; i < 3; i++) {
            cp_async16(smem_u32(&Bsm[(s * 32 + brr[i]) * BSTRF + bqq[i] * 8]),
                       Wbase + (long)(k0 + brr[i]) * 1536 + (bqq[i] >> 3) * 512 + (bqq[i] & 7) * 8);
        }
        cp_commit();
    }

    for (int ri = 0; ri < 4; ri++) {
        int r = warp * 4 + ri;
        const float* row = H + (long)(b * 32 + r) * DHID;
        float v[16]; float s = 0.f;
#pragma unroll
        for (int i = 0; i < 16; i++) { v[i] = row[lane + 32 * i]; s += v[i]; }
        s = warp_sum(s);
        float mu = s * (1.f / 512.f);
        float vs = 0.f;
#pragma unroll
        for (int i = 0; i < 16; i++) { float d = v[i] - mu; vs += d * d; }
        vs = warp_sum(vs);
        float rstd = rsqrtf(vs * (1.f / 512.f) + 1e-5f);
#pragma unroll
        for (int i = 0; i < 16; i++) {
            int d = lane + 32 * i;
            xs[r * XSTR + d] = __float2half_rn((v[i] - mu) * rstd * g[d] + bvec[d]);
        }
    }

    float c[6][4];
#pragma unroll
    for (int j = 0; j < 6; j++)
#pragma unroll
        for (int e = 0; e < 4; e++) c[j][e] = 0.f;

    for (int kt = 0; kt < 16; kt++) {
        cp_wait<1>();
        __syncthreads();
        int buf = kt % 3;
#pragma unroll
        for (int ks = 0; ks < 32; ks += 16) {
            unsigned a[4], bf[3][4];
            unsigned addr = smem_u32(&xs[(wm * 16 + (lane & 15)) * XSTR + kt * 32 + ks + (lane >> 4) * 8]);
            asm volatile("ldmatrix.sync.aligned.m8n8.x4.shared.b16 {%0,%1,%2,%3}, [%4];"
                         : "=r"(a[0]), "=r"(a[1]), "=r"(a[2]), "=r"(a[3]) : "r"(addr));
#pragma unroll
            for (int j2 = 0; j2 < 3; j2++) {
                unsigned baddr = smem_u32(&Bsm[(buf * 32 + ks + (lane & 7) + ((lane >> 3) & 1) * 8) * BSTRF
                                               + wn * 48 + j2 * 16 + (lane >> 4) * 8]);
                asm volatile("ldmatrix.sync.aligned.m8n8.x4.trans.shared.b16 {%0,%1,%2,%3}, [%4];"
                             : "=r"(bf[j2][0]), "=r"(bf[j2][1]), "=r"(bf[j2][2]), "=r"(bf[j2][3]) : "r"(baddr));
            }
#pragma unroll
            for (int j = 0; j < 6; j++) {
                unsigned b0 = bf[j >> 1][(j & 1) * 2], b1 = bf[j >> 1][(j & 1) * 2 + 1];
                asm volatile(
                    "mma.sync.aligned.m16n8k16.row.col.f32.f16.f16.f32 "
                    "{%0,%1,%2,%3}, {%4,%5,%6,%7}, {%8,%9}, {%0,%1,%2,%3};"
                    : "+f"(c[j][0]), "+f"(c[j][1]), "+f"(c[j][2]), "+f"(c[j][3])
                    : "r"(a[0]), "r"(a[1]), "r"(a[2]), "r"(a[3]), "r"(b0), "r"(b1));
            }
        }
        int kn = kt + 2;
        if (kn < 16) {
            int nb = kn % 3;
            int k0 = kn * 32;
#pragma unroll
            for (int i = 0; i < 3; i++) {
                cp_async16(smem_u32(&Bsm[(nb * 32 + brr[i]) * BSTRF + bqq[i] * 8]),
                           Wbase + (long)(k0 + brr[i]) * 1536 + (bqq[i] >> 3) * 512 + (bqq[i] & 7) * 8);
            }
        }
        cp_commit();
    }
    __syncthreads();

#pragma unroll
    for (int j = 0; j < 6; j++) {
        int c0 = wn * 48 + j * 8 + (lane & 3) * 2;
        int seg = c0 >> 6, d = c0 & 63;
        float b0 = bias[seg * 512 + h * 64 + d];
        float b1 = bias[seg * 512 + h * 64 + d + 1];
#pragma unroll
        for (int half_ = 0; half_ < 2; half_++) {
            int r = wm * 16 + (lane >> 2) + half_ * 8;
            float v0 = c[j][half_ * 2 + 0] + b0;
            float v1 = c[j][half_ * 2 + 1] + b1;
            if (seg == 0)      { kk[r * 65 + d] = v0; kk[r * 65 + d + 1] = v1; }
            else if (seg == 1) { qq[r * 64 + d] = v0; qq[r * 64 + d + 1] = v1; }
            else               { vv[r * 64 + d] = v0; vv[r * 64 + d + 1] = v1; }
        }
    }
    __syncthreads();

#pragma unroll
    for (int i = 0; i < 4; i++) {
        int e = tid + i * 256;
        int t = e >> 5, j = e & 31;
        float sn = rs[t * 32 + j], cs = rc[t * 32 + j];
        float q1 = qq[t * 64 + j], q2 = qq[t * 64 + j + 32];
        qq[t * 64 + j]      = q1 * cs - q2 * sn;
        qq[t * 64 + j + 32] = q2 * cs + q1 * sn;
        float k1 = kk[t * 65 + j], k2 = kk[t * 65 + j + 32];
        kk[t * 65 + j]      = k1 * cs - k2 * sn;
        kk[t * 65 + j + 32] = k2 * cs + k1 * sn;
    }
    __syncthreads();

#pragma unroll
    for (int i = 0; i < 4; i++) {
        int e = tid + i * 256;
        int tq = e >> 5, tk = e & 31;
        if (tk <= tq) {
            float acc = 0.f;
#pragma unroll
            for (int dd = 0; dd < 64; dd++) acc += qq[tq * 64 + dd] * kk[tk * 65 + dd];
            ss[tq * 33 + tk] = acc * 0.125f;
        }
    }
    __syncthreads();
    for (int r = warp; r < 32; r += 8) {
        float val = (lane <= r) ? ss[r * 33 + lane] : -3.4e38f;
        float m = warp_max(val);
        float e = (lane <= r) ? expf(val - m) : 0.f;
        float sum = warp_sum(e);
        ss[r * 33 + lane] = e / sum;
    }
    __syncthreads();
#pragma unroll
    for (int i = 0; i < 8; i++) {
        int e = tid + i * 256;
        int t = e >> 6, d = e & 63;
        float acc = 0.f;
#pragma unroll
        for (int kk2 = 0; kk2 < 32; kk2++) acc += ss[t * 33 + kk2] * vv[kk2 * 64 + d];
        out[(long)(b * 32 + t) * DHID + h * 64 + d] = __float2half_rn(acc);
    }
}

// ---------------- small fp32 GEMM (film only) ----------------
__global__ void gemm_kernel(const float* __restrict__ A, const float* __restrict__ Bm,
                            const float* __restrict__ bias, float* C,
                            int M, int N, int K) {
    __shared__ float As[16][65];
    __shared__ float Bs[16][64];
    int bm = blockIdx.y * 64, bn = blockIdx.x * 64;
    int tid = threadIdx.x;
    int tx = tid & 15, ty = tid >> 4;
    float acc[4][4];
#pragma unroll
    for (int i = 0; i < 4; i++)
#pragma unroll
        for (int j = 0; j < 4; j++) acc[i][j] = 0.f;
    const float* Ab = A + (long)bm * K;
    for (int k0 = 0; k0 < K; k0 += 16) {
        {
            int col = tid & 15, row = tid >> 4;
#pragma unroll
            for (int r = 0; r < 4; r++)
                As[col][row + r * 16] = Ab[(long)(row + r * 16) * K + k0 + col];
        }
        {
            int col = tid & 63, row = tid >> 6;
#pragma unroll
            for (int r = 0; r < 4; r++)
                Bs[row + r * 4][col] = Bm[(long)(k0 + row + r * 4) * N + bn + col];
        }
        __syncthreads();
#pragma unroll
        for (int kk = 0; kk < 16; kk++) {
            float a0 = As[kk][ty * 4 + 0], a1 = As[kk][ty * 4 + 1];
            float a2 = As[kk][ty * 4 + 2], a3 = As[kk][ty * 4 + 3];
            float4 b4 = *(const float4*)&Bs[kk][tx * 4];
            acc[0][0] += a0 * b4.x; acc[0][1] += a0 * b4.y; acc[0][2] += a0 * b4.z; acc[0][3] += a0 * b4.w;
            acc[1][0] += a1 * b4.x; acc[1][1] += a1 * b4.y; acc[1][2] += a1 * b4.z; acc[1][3] += a1 * b4.w;
            acc[2][0] += a2 * b4.x; acc[2][1] += a2 * b4.y; acc[2][2] += a2 * b4.z; acc[2][3] += a2 * b4.w;
            acc[3][0] += a3 * b4.x; acc[3][1] += a3 * b4.y; acc[3][2] += a3 * b4.z; acc[3][3] += a3 * b4.w;
        }
        __syncthreads();
    }
#pragma unroll
    for (int i = 0; i < 4; i++) {
        int row = bm + ty * 4 + i;
#pragma unroll
        for (int j = 0; j < 4; j++) {
            int col = bn + tx * 4 + j;
            C[(long)row * N + col] = acc[i][j] + bias[col];
        }
    }
}

// ---------------- fused token LN + FiLM + spatial mean ----------------
__global__ void tok_reduce_kernel(const float* __restrict__ tok, const float* __restrict__ tg,
                                  const float* __restrict__ tb, const float* __restrict__ film,
                                  float* __restrict__ h) {
    __shared__ float accs[8][DHID];
    int bt = blockIdx.x;
    int wid = threadIdx.x >> 5, lane = threadIdx.x & 31;
    float acc[16];
#pragma unroll
    for (int i = 0; i < 16; i++) acc[i] = 0.f;
    const float* gb = film + bt * (2 * DHID);
    for (int n = wid; n < NTOK; n += 8) {
        const float* row = tok + (long)(bt * NTOK + n) * DHID;
        float v[16]; float s = 0.f;
#pragma unroll
        for (int i = 0; i < 16; i++) { v[i] = row[i * 32 + lane]; s += v[i]; }
        s = warp_sum(s);
        float mu = s * (1.f / 512.f);
        float vs = 0.f;
#pragma unroll
        for (int i = 0; i < 16; i++) { float d = v[i] - mu; vs += d * d; }
        vs = warp_sum(vs);
        float rstd = rsqrtf(vs * (1.f / 512.f) + 1e-5f);
#pragma unroll
        for (int i = 0; i < 16; i++) {
            int d = i * 32 + lane;
            float ln = (v[i] - mu) * rstd * tg[d] + tb[d];
            acc[i] += (1.f + 0.5f * gb[d]) * ln + 0.5f * gb[DHID + d];
        }
    }
#pragma unroll
    for (int i = 0; i < 16; i++) accs[wid][i * 32 + lane] = acc[i];
    __syncthreads();
    for (int d = threadIdx.x; d < DHID; d += 256) {
        float s = 0.f;
#pragma unroll
        for (int w = 0; w < 8; w++) s += accs[w][d];
        h[bt * DHID + d] = s * (1.f / 64.f);
    }
}

// ---------------- head ----------------
__global__ void head_kernel(const float* __restrict__ hin, const float* __restrict__ g,
                            const float* __restrict__ b, const float* __restrict__ w,
                            const float* __restrict__ bias0, float* __restrict__ out) {
    __shared__ float sbuf[8];
    int tok = blockIdx.x, tid = threadIdx.x;
    const float* row = hin + tok * DHID;
    float v0 = row[tid], v1 = row[tid + 256];
    float sum = block_sum_256(v0 + v1, sbuf);
    float mu = sum * (1.f / 512.f);
    float d0 = v0 - mu, d1 = v1 - mu;
    float vs = block_sum_256(d0 * d0 + d1 * d1, sbuf);
    float rstd = rsqrtf(vs * (1.f / 512.f) + 1e-5f);
    float c = (d0 * rstd * g[tid] + b[tid]) * w[tid] +
              (d1 * rstd * g[tid + 256] + b[tid + 256]) * w[tid + 256];
    float tot = block_sum_256(c, sbuf);
    if (tid == 0) out[tok] = tot + bias0[0];
}

// ---------------- launch ----------------
extern "C" void kernel_launch(void* const* d_in, const int* in_sizes, int n_in,
                              void* d_out, int out_size) {
    const float* x       = (const float*)d_in[0];
    const float* z       = (const float*)d_in[1];
    const float* conv_w  = (const float*)d_in[2];
    const float* conv_b  = (const float*)d_in[3];
    const float* tok_g   = (const float*)d_in[4];
    const float* tok_b   = (const float*)d_in[5];
    const float* film_w  = (const float*)d_in[6];
    const float* film_b  = (const float*)d_in[7];
    const float* ln1_g   = (const float*)d_in[8];
    const float* ln1_b   = (const float*)d_in[9];
    const float* kqv_w   = (const float*)d_in[10];
    const float* kqv_b   = (const float*)d_in[11];
    const float* proj_w  = (const float*)d_in[12];
    const float* proj_b  = (const float*)d_in[13];
    const float* ln2_g   = (const float*)d_in[14];
    const float* ln2_b   = (const float*)d_in[15];
    const float* mlp_w1  = (const float*)d_in[16];
    const float* mlp_b1  = (const float*)d_in[17];
    const float* mlp_w2  = (const float*)d_in[18];
    const float* mlp_b2  = (const float*)d_in[19];
    const float* rs_attn = (const float*)d_in[20];
    const float* rs_mlp  = (const float*)d_in[21];
    const float* head_g  = (const float*)d_in[22];
    const float* head_b  = (const float*)d_in[23];
    const float* head_w  = (const float*)d_in[24];
    const float* head_bi = (const float*)d_in[25];
    float* out = (float*)d_out;

    __half *wT_h, *xh, *kqvw_h, *projw_h, *w1_h, *w2_h, *attn_h, *mlp_h;
    float *tok, *film, *h, *ropeS, *ropeC;
    cudaGetSymbolAddress((void**)&wT_h, g_wT_h);
    cudaGetSymbolAddress((void**)&xh, g_xh);
    cudaGetSymbolAddress((void**)&kqvw_h, g_kqvw_h);
    cudaGetSymbolAddress((void**)&projw_h, g_projw_h);
    cudaGetSymbolAddress((void**)&w1_h, g_w1_h);
    cudaGetSymbolAddress((void**)&w2_h, g_w2_h);
    cudaGetSymbolAddress((void**)&attn_h, g_attn_h);
    cudaGetSymbolAddress((void**)&mlp_h, g_mlp_h);
    cudaGetSymbolAddress((void**)&tok, g_tok);
    cudaGetSymbolAddress((void**)&film, g_film);
    cudaGetSymbolAddress((void**)&h, g_h);
    cudaGetSymbolAddress((void**)&ropeS, g_ropeS);
    cudaGetSymbolAddress((void**)&ropeC, g_ropeC);

    cudaFuncSetAttribute(kqvattn_kernel, cudaFuncAttributeMaxDynamicSharedMemorySize, SMEMF);
    cudaFuncSetAttribute(mlp1_ln_kernel, cudaFuncAttributeMaxDynamicSharedMemorySize, SMEM_M1);

    // merged setup: transpose + rope + weight f2h + x f2h (one launch)
    {
        int n0 = LAYERS * DHID * 3 * DHID / 4;
        int n1 = LAYERS * DHID * DHID / 4;
        int n2 = LAYERS * DHID * 4 * DHID / 4;
        int n3 = n2;
        int nx = BB * TT * 3 * 64 * 64 / 4;
        int nconv = (n0 + n1 + n2 + n3 + nx + 255) / 256;
        setup_kernel<<<NB_T + NB_R + nconv, 256>>>(
            conv_w, wT_h, ropeS, ropeC,
            (const float4*)kqv_w, (const float4*)proj_w, (const float4*)mlp_w1, (const float4*)mlp_w2,
            kqvw_h, projw_h, w1_h, w2_h, n0, n1, n2, n3,
            (const float4*)x, xh, nx);
    }
    // implicit-GEMM conv tokenizer
    conv_gemm_kernel<<<dim3(DHID / 128, MCONV / 128), 256>>>(xh, wT_h, conv_b, tok);
    gemm_kernel<<<dim3(1024 / 64, BT / 64), 256>>>(z, film_w, film_b, film, BT, 1024, 32);
    tok_reduce_kernel<<<BT, 256>>>(tok, tok_g, tok_b, film, h);

    // transformer (4 launches/layer)
    for (int i = 0; i < LAYERS; i++) {
        kqvattn_kernel<<<BB * NHEAD, 256, SMEMF>>>(
            h, ln1_g + i * DHID, ln1_b + i * DHID, kqvw_h + (long)i * DHID * 1536,
            kqv_b + i * 1536, ropeS, ropeC, attn_h);
        hgemm64_kernel<<<dim3(DHID / 64, BT / 32), 128>>>(
            attn_h, projw_h + (long)i * DHID * DHID, proj_b + i * DHID, h, nullptr,
            BT, DHID, DHID, 2, h, rs_attn + i);
        mlp1_ln_kernel<<<dim3(2048 / 128, BT / 32), 256, SMEM_M1>>>(
            h, ln2_g + i * DHID, ln2_b + i * DHID, w1_h + (long)i * DHID * 2048,
            mlp_b1 + i * 2048, mlp_h);
        hgemm64_kernel<<<dim3(DHID / 64, BT / 32), 128>>>(
            mlp_h, w2_h + (long)i * 2048 * DHID, mlp_b2 + i * DHID, h, nullptr,
            BT, DHID, 2048, 2, h, rs_mlp + i);
    }
    head_kernel<<<BT, 256>>>(h, head_g, head_b, head_w, head_bi, out);
}